// round 1
// baseline (speedup 1.0000x reference)
#include <cuda_runtime.h>
#include <math.h>

// ---------------------------------------------------------------------------
// TransformerBlock: B=8192 windows, N=9 tokens, DIM=512, HEADS=8, HEAD_DIM=64
// Pipeline: LN1 -> QKV gemm -> window attn -> proj gemm (+x) -> LN2 ->
//           FC1 gemm (+gelu) -> FC2 gemm (+x1) -> depthwise 3x3 merge conv
// ---------------------------------------------------------------------------

#define MROWS (8192 * 9)   // 73728 token rows

// Scratch (allocation-free: static device globals)
__device__ float g_h   [(size_t)MROWS * 512];   // LN output (reused for LN1 and LN2)
__device__ float g_qkv [(size_t)MROWS * 1536];  // QKV
__device__ float g_attn[(size_t)MROWS * 512];   // attn out, later reused as x2
__device__ float g_x1  [(size_t)MROWS * 512];   // residual after attention
__device__ float g_mlp [(size_t)MROWS * 2048];  // GELU(FC1)

// ---------------------------------------------------------------------------
// LayerNorm over last dim (512). One warp per row, block = (32, 8).
// ---------------------------------------------------------------------------
__global__ __launch_bounds__(256) void ln_kernel(
    const float* __restrict__ x, const float* __restrict__ gam,
    const float* __restrict__ bet, float* __restrict__ out)
{
    int row  = blockIdx.x * 8 + threadIdx.y;
    int lane = threadIdx.x;
    const float4* xr = reinterpret_cast<const float4*>(x) + (size_t)row * 128;
    float4 v[4];
    float s = 0.f, s2 = 0.f;
#pragma unroll
    for (int i = 0; i < 4; i++) {
        v[i] = xr[lane + 32 * i];
        s  += v[i].x + v[i].y + v[i].z + v[i].w;
        s2 += v[i].x * v[i].x + v[i].y * v[i].y + v[i].z * v[i].z + v[i].w * v[i].w;
    }
#pragma unroll
    for (int o = 16; o; o >>= 1) {
        s  += __shfl_xor_sync(0xffffffffu, s,  o);
        s2 += __shfl_xor_sync(0xffffffffu, s2, o);
    }
    float mu   = s * (1.f / 512.f);
    float var  = s2 * (1.f / 512.f) - mu * mu;
    float rstd = rsqrtf(var + 1e-5f);
    float4* orow = reinterpret_cast<float4*>(out) + (size_t)row * 128;
    const float4* g4 = reinterpret_cast<const float4*>(gam);
    const float4* b4 = reinterpret_cast<const float4*>(bet);
#pragma unroll
    for (int i = 0; i < 4; i++) {
        int c = lane + 32 * i;
        float4 g = g4[c], b = b4[c], o;
        o.x = (v[i].x - mu) * rstd * g.x + b.x;
        o.y = (v[i].y - mu) * rstd * g.y + b.y;
        o.z = (v[i].z - mu) * rstd * g.z + b.z;
        o.w = (v[i].w - mu) * rstd * g.w + b.w;
        orow[c] = o;
    }
}

// ---------------------------------------------------------------------------
// SGEMM: C[M,N] = A[M,K] @ Bw[N,K]^T + bias[N]  (+ epilogue)
//   ep = 0: none;  ep = 1: exact GELU;  ep = 2: add Res[M,N]
// 128x128 block tile, BK=8, 8x8 per thread, 256 threads. M,N multiples of 128,
// K multiple of 8. A and Bw are both K-contiguous (TN layout).
// ---------------------------------------------------------------------------
__global__ __launch_bounds__(256) void gemm_kernel(
    const float* __restrict__ A, const float* __restrict__ Bw,
    const float* __restrict__ bias, const float* __restrict__ Res,
    float* __restrict__ C, int N, int K, int ep)
{
    __shared__ float As[8][128];
    __shared__ float Bs[8][128];
    int tid = threadIdx.x;
    int tx = tid & 15, ty = tid >> 4;
    int bm = blockIdx.y * 128, bn = blockIdx.x * 128;
    int lr = tid >> 1;           // load row within tile (0..127)
    int lc = (tid & 1) * 4;      // k offset within BK (0 or 4)
    const float* Aload = A  + (size_t)(bm + lr) * K + lc;
    const float* Bload = Bw + (size_t)(bn + lr) * K + lc;

    float acc[8][8];
#pragma unroll
    for (int i = 0; i < 8; i++)
#pragma unroll
        for (int j = 0; j < 8; j++) acc[i][j] = 0.f;

    for (int kt = 0; kt < K; kt += 8) {
        float4 av = *reinterpret_cast<const float4*>(Aload + kt);
        float4 bv = *reinterpret_cast<const float4*>(Bload + kt);
        As[lc + 0][lr] = av.x; As[lc + 1][lr] = av.y;
        As[lc + 2][lr] = av.z; As[lc + 3][lr] = av.w;
        Bs[lc + 0][lr] = bv.x; Bs[lc + 1][lr] = bv.y;
        Bs[lc + 2][lr] = bv.z; Bs[lc + 3][lr] = bv.w;
        __syncthreads();
#pragma unroll
        for (int kk = 0; kk < 8; kk++) {
            float a[8], b[8];
#pragma unroll
            for (int i = 0; i < 8; i++) a[i] = As[kk][ty * 8 + i];
#pragma unroll
            for (int j = 0; j < 8; j++) b[j] = Bs[kk][tx * 8 + j];
#pragma unroll
            for (int i = 0; i < 8; i++)
#pragma unroll
                for (int j = 0; j < 8; j++)
                    acc[i][j] = fmaf(a[i], b[j], acc[i][j]);
        }
        __syncthreads();
    }

#pragma unroll
    for (int i = 0; i < 8; i++) {
        int row = bm + ty * 8 + i;
#pragma unroll
        for (int j = 0; j < 8; j++) {
            int col = bn + tx * 8 + j;
            float v = acc[i][j] + bias[col];
            if (ep == 1) {
                v = 0.5f * v * (1.f + erff(v * 0.70710678118654752f));
            } else if (ep == 2) {
                v += Res[(size_t)row * N + col];
            }
            C[(size_t)row * N + col] = v;
        }
    }
}

// ---------------------------------------------------------------------------
// Window attention. One CTA per window (b), 8 warps = 8 heads.
// qkv row layout per token: [q(512) | k(512) | v(512)], head h slice = h*64..
// out row (b*9+n), col h*64+d.
// ---------------------------------------------------------------------------
__global__ __launch_bounds__(256) void attn_kernel(
    const float* __restrict__ qkv, const float* __restrict__ bias_table,
    float* __restrict__ out)
{
    __shared__ float sq[9][520];    // padded rows to dodge bank conflicts
    __shared__ float sk[9][520];
    __shared__ float sp[8][81];
    int b   = blockIdx.x;
    int tid = threadIdx.x;
    size_t base = (size_t)b * 9 * 1536;

    for (int idx = tid; idx < 9 * 512; idx += 256) {
        int n = idx >> 9, c = idx & 511;
        sq[n][c] = qkv[base + (size_t)n * 1536 + c] * 0.125f;   // SCALE = 64^-0.5
        sk[n][c] = qkv[base + (size_t)n * 1536 + 512 + c];
    }
    __syncthreads();

    int h = tid >> 5, lane = tid & 31;

    // scores + relative position bias
#pragma unroll
    for (int r = 0; r < 3; r++) {
        int idx = r * 32 + lane;
        if (idx < 81) {
            int n = idx / 9, m = idx - n * 9;
            const float* qp = &sq[n][h * 64];
            const float* kp = &sk[m][h * 64];
            float s = 0.f;
#pragma unroll
            for (int d = 0; d < 64; d++) s = fmaf(qp[d], kp[d], s);
            int di = n / 3 - m / 3 + 2;
            int dj = n % 3 - m % 3 + 2;
            s += bias_table[(di * 5 + dj) * 8 + h];
            sp[h][idx] = s;
        }
    }
    __syncwarp();

    // softmax: lanes 0..8 each own one query row
    if (lane < 9) {
        float mx = -1e30f;
#pragma unroll
        for (int m = 0; m < 9; m++) mx = fmaxf(mx, sp[h][lane * 9 + m]);
        float e[9], sum = 0.f;
#pragma unroll
        for (int m = 0; m < 9; m++) { e[m] = __expf(sp[h][lane * 9 + m] - mx); sum += e[m]; }
        float inv = 1.f / sum;
#pragma unroll
        for (int m = 0; m < 9; m++) sp[h][lane * 9 + m] = e[m] * inv;
    }
    __syncwarp();

    // out = P @ V; lane owns d = lane and d = lane+32
    float a0[9], a1[9];
#pragma unroll
    for (int n = 0; n < 9; n++) { a0[n] = 0.f; a1[n] = 0.f; }
#pragma unroll
    for (int m = 0; m < 9; m++) {
        size_t vb = base + (size_t)m * 1536 + 1024 + h * 64;
        float v0 = qkv[vb + lane];
        float v1 = qkv[vb + 32 + lane];
#pragma unroll
        for (int n = 0; n < 9; n++) {
            float p = sp[h][n * 9 + m];
            a0[n] = fmaf(p, v0, a0[n]);
            a1[n] = fmaf(p, v1, a1[n]);
        }
    }
#pragma unroll
    for (int n = 0; n < 9; n++) {
        size_t o = ((size_t)b * 9 + n) * 512 + h * 64;
        out[o + lane]      = a0[n];
        out[o + 32 + lane] = a1[n];
    }
}

// ---------------------------------------------------------------------------
// Depthwise 3x3 merge conv: y[b,c] = sum_n x2[b,n,c]*w[c,n] + bc[c]
// ---------------------------------------------------------------------------
__global__ __launch_bounds__(256) void conv_kernel(
    const float* __restrict__ x, const float* __restrict__ w,
    const float* __restrict__ bc, float* __restrict__ out)
{
    int i = blockIdx.x * 256 + threadIdx.x;   // over B*512
    int c = i & 511;
    int b = i >> 9;
    float acc = bc[c];
    size_t base = (size_t)b * 9 * 512 + c;
#pragma unroll
    for (int n = 0; n < 9; n++)
        acc = fmaf(x[base + (size_t)n * 512], w[c * 9 + n], acc);
    out[i] = acc;
}

// ---------------------------------------------------------------------------
extern "C" void kernel_launch(void* const* d_in, const int* in_sizes, int n_in,
                              void* d_out, int out_size)
{
    const float* x          = (const float*)d_in[0];
    const float* gamma1     = (const float*)d_in[1];
    const float* beta1      = (const float*)d_in[2];
    const float* w_qkv      = (const float*)d_in[3];
    const float* b_qkv      = (const float*)d_in[4];
    const float* bias_table = (const float*)d_in[5];
    const float* w_proj     = (const float*)d_in[6];
    const float* b_proj     = (const float*)d_in[7];
    const float* gamma2     = (const float*)d_in[8];
    const float* beta2      = (const float*)d_in[9];
    const float* w_fc1      = (const float*)d_in[10];
    const float* b_fc1      = (const float*)d_in[11];
    const float* w_fc2      = (const float*)d_in[12];
    const float* b_fc2      = (const float*)d_in[13];
    const float* w_conv     = (const float*)d_in[14];
    const float* b_conv     = (const float*)d_in[15];
    float* out = (float*)d_out;

    float *h, *qkv, *attn, *x1, *mlp;
    cudaGetSymbolAddress((void**)&h,    g_h);
    cudaGetSymbolAddress((void**)&qkv,  g_qkv);
    cudaGetSymbolAddress((void**)&attn, g_attn);
    cudaGetSymbolAddress((void**)&x1,   g_x1);
    cudaGetSymbolAddress((void**)&mlp,  g_mlp);

    const int MB = MROWS / 128;   // 576 row tiles

    // LN1: x -> h
    ln_kernel<<<MROWS / 8, dim3(32, 8)>>>(x, gamma1, beta1, h);
    // QKV: h @ w_qkv^T + b_qkv -> qkv
    gemm_kernel<<<dim3(1536 / 128, MB), 256>>>(h, w_qkv, b_qkv, nullptr, qkv, 1536, 512, 0);
    // window attention -> attn
    attn_kernel<<<8192, 256>>>(qkv, bias_table, attn);
    // proj + shortcut: attn @ w_proj^T + b_proj + x -> x1
    gemm_kernel<<<dim3(512 / 128, MB), 256>>>(attn, w_proj, b_proj, x, x1, 512, 512, 2);
    // LN2: x1 -> h
    ln_kernel<<<MROWS / 8, dim3(32, 8)>>>(x1, gamma2, beta2, h);
    // FC1 + GELU: h @ w_fc1^T + b_fc1 -> mlp
    gemm_kernel<<<dim3(2048 / 128, MB), 256>>>(h, w_fc1, b_fc1, nullptr, mlp, 2048, 512, 1);
    // FC2 + residual: mlp @ w_fc2^T + b_fc2 + x1 -> x2 (reuse attn buffer)
    gemm_kernel<<<dim3(512 / 128, MB), 256>>>(mlp, w_fc2, b_fc2, x1, attn, 512, 2048, 2);
    // merge conv -> out
    conv_kernel<<<(8192 * 512) / 256, 256>>>(attn, w_conv, b_conv, out);
}

// round 2
// speedup vs baseline: 6.9538x; 6.9538x over previous
#include <cuda_runtime.h>
#include <math.h>
#include <stdint.h>

// ---------------------------------------------------------------------------
// TransformerBlock: B=8192 windows, N=9 tokens, DIM=512, HEADS=8, HEAD_DIM=64
// Round 2: all GEMMs on tensor cores (mma.sync m16n8k8 tf32, cp.async 2-stage)
// ---------------------------------------------------------------------------

#define MROWS (8192 * 9)   // 73728 token rows

// Scratch (allocation-free: static device globals)
__device__ float g_h   [(size_t)MROWS * 512];   // LN output (tf32-rounded)
__device__ float g_qkv [(size_t)MROWS * 1536];  // QKV (fp32)
__device__ float g_attn[(size_t)MROWS * 512];   // attn out (tf32) / later x2 (fp32)
__device__ float g_x1  [(size_t)MROWS * 512];   // residual after attention (fp32)
__device__ float g_mlp [(size_t)MROWS * 2048];  // GELU(FC1) (tf32-rounded)
__device__ float g_w   [3145728];               // tf32-rounded weights

__device__ __forceinline__ float tf32r(float x) {
    uint32_t u;
    asm("cvt.rna.tf32.f32 %0, %1;" : "=r"(u) : "f"(x));
    return __uint_as_float(u);
}

__device__ __forceinline__ void cp16(float* dst, const float* src) {
    uint32_t s = (uint32_t)__cvta_generic_to_shared(dst);
    asm volatile("cp.async.cg.shared.global [%0], [%1], 16;\n" :: "r"(s), "l"(src));
}
__device__ __forceinline__ void cp_commit() { asm volatile("cp.async.commit_group;\n"); }
template <int N> __device__ __forceinline__ void cp_wait() {
    asm volatile("cp.async.wait_group %0;\n" :: "n"(N));
}

__device__ __forceinline__ void mma_tf32(float4& d, const uint32_t a[4], const uint32_t b[2]) {
    asm volatile(
        "mma.sync.aligned.m16n8k8.row.col.f32.tf32.tf32.f32 "
        "{%0,%1,%2,%3}, {%4,%5,%6,%7}, {%8,%9}, {%0,%1,%2,%3};\n"
        : "+f"(d.x), "+f"(d.y), "+f"(d.z), "+f"(d.w)
        : "r"(a[0]), "r"(a[1]), "r"(a[2]), "r"(a[3]), "r"(b[0]), "r"(b[1]));
}

// ---------------------------------------------------------------------------
// Round a weight matrix to tf32 (grid-stride)
// ---------------------------------------------------------------------------
__global__ __launch_bounds__(256) void roundw_kernel(
    const float* __restrict__ in, float* __restrict__ out, int n)
{
    for (int i = blockIdx.x * 256 + threadIdx.x; i < n; i += gridDim.x * 256)
        out[i] = tf32r(in[i]);
}

// ---------------------------------------------------------------------------
// LayerNorm over last dim (512). One warp per row. Output rounded to tf32
// (it only ever feeds an MMA).
// ---------------------------------------------------------------------------
__global__ __launch_bounds__(256) void ln_kernel(
    const float* __restrict__ x, const float* __restrict__ gam,
    const float* __restrict__ bet, float* __restrict__ out)
{
    int row  = blockIdx.x * 8 + threadIdx.y;
    int lane = threadIdx.x;
    const float4* xr = reinterpret_cast<const float4*>(x) + (size_t)row * 128;
    float4 v[4];
    float s = 0.f, s2 = 0.f;
#pragma unroll
    for (int i = 0; i < 4; i++) {
        v[i] = xr[lane + 32 * i];
        s  += v[i].x + v[i].y + v[i].z + v[i].w;
        s2 += v[i].x * v[i].x + v[i].y * v[i].y + v[i].z * v[i].z + v[i].w * v[i].w;
    }
#pragma unroll
    for (int o = 16; o; o >>= 1) {
        s  += __shfl_xor_sync(0xffffffffu, s,  o);
        s2 += __shfl_xor_sync(0xffffffffu, s2, o);
    }
    float mu   = s * (1.f / 512.f);
    float var  = s2 * (1.f / 512.f) - mu * mu;
    float rstd = rsqrtf(var + 1e-5f);
    float4* orow = reinterpret_cast<float4*>(out) + (size_t)row * 128;
    const float4* g4 = reinterpret_cast<const float4*>(gam);
    const float4* b4 = reinterpret_cast<const float4*>(bet);
#pragma unroll
    for (int i = 0; i < 4; i++) {
        int c = lane + 32 * i;
        float4 g = g4[c], b = b4[c], o;
        o.x = tf32r((v[i].x - mu) * rstd * g.x + b.x);
        o.y = tf32r((v[i].y - mu) * rstd * g.y + b.y);
        o.z = tf32r((v[i].z - mu) * rstd * g.z + b.z);
        o.w = tf32r((v[i].w - mu) * rstd * g.w + b.w);
        orow[c] = o;
    }
}

// ---------------------------------------------------------------------------
// tf32 tensor-core GEMM: C[M,N] = A[M,K] @ Bw[N,K]^T + bias[N]  (+ epilogue)
//   ep=0 none, ep=1 exact GELU (output tf32-rounded), ep=2 add Res (fp32)
// 128x128x32 CTA tile, 8 warps (4x2), each warp 32x64 via m16n8k8 tiles.
// 2-stage cp.async pipeline. A and Bw K-contiguous; inputs pre-rounded tf32.
// ---------------------------------------------------------------------------
#define BK   32
#define LDS_ (BK + 4)   // 36 floats: conflict-free fragment loads
#define ATILE (128 * LDS_)

__global__ __launch_bounds__(256, 2) void gemm_tf32_kernel(
    const float* __restrict__ A, const float* __restrict__ Bw,
    const float* __restrict__ bias, const float* __restrict__ Res,
    float* __restrict__ C, int N, int K, int ep)
{
    extern __shared__ float smem[];   // [As0|As1|Bs0|Bs1], each 128*36 floats

    int tid  = threadIdx.x;
    int bm   = blockIdx.y * 128, bn = blockIdx.x * 128;
    int warp = tid >> 5, lane = tid & 31;
    int warpM = warp >> 1, warpN = warp & 1;
    int lg = lane >> 2, lt = lane & 3;   // group / thread-in-group

    // global loaders: 16B per thread, 32 rows per pass, 4 passes
    int lrow = tid >> 3;          // 0..31
    int lcol = (tid & 7) * 4;     // 0..28
    const float* Ag = A  + (size_t)(bm + lrow) * K + lcol;
    const float* Bg = Bw + (size_t)(bn + lrow) * K + lcol;

    float4 acc[2][8];
#pragma unroll
    for (int mt = 0; mt < 2; mt++)
#pragma unroll
        for (int nt = 0; nt < 8; nt++) acc[mt][nt] = make_float4(0.f, 0.f, 0.f, 0.f);

    auto loadTile = [&](int stage, int kt) {
        float* as = smem + stage * ATILE;
        float* bs = smem + 2 * ATILE + stage * ATILE;
#pragma unroll
        for (int p = 0; p < 4; p++) {
            int r = p * 32 + lrow;
            cp16(as + r * LDS_ + lcol, Ag + (size_t)p * 32 * K + kt);
            cp16(bs + r * LDS_ + lcol, Bg + (size_t)p * 32 * K + kt);
        }
        cp_commit();
    };

    loadTile(0, 0);

    int stage = 0;
    for (int kt = 0; kt < K; kt += BK) {
        if (kt + BK < K) {
            loadTile(stage ^ 1, kt + BK);
            cp_wait<1>();
        } else {
            cp_wait<0>();
        }
        __syncthreads();

        const float* as = smem + stage * ATILE;
        const float* bs = smem + 2 * ATILE + stage * ATILE;
#pragma unroll
        for (int ks = 0; ks < 4; ks++) {
            int k0 = ks * 8;
            uint32_t a[2][4], b[8][2];
#pragma unroll
            for (int mt = 0; mt < 2; mt++) {
                const float* p = as + (warpM * 32 + mt * 16 + lg) * LDS_ + k0 + lt;
                a[mt][0] = __float_as_uint(p[0]);
                a[mt][1] = __float_as_uint(p[8 * LDS_]);
                a[mt][2] = __float_as_uint(p[4]);
                a[mt][3] = __float_as_uint(p[8 * LDS_ + 4]);
            }
#pragma unroll
            for (int nt = 0; nt < 8; nt++) {
                const float* p = bs + (warpN * 64 + nt * 8 + lg) * LDS_ + k0 + lt;
                b[nt][0] = __float_as_uint(p[0]);
                b[nt][1] = __float_as_uint(p[4]);
            }
#pragma unroll
            for (int mt = 0; mt < 2; mt++)
#pragma unroll
                for (int nt = 0; nt < 8; nt++)
                    mma_tf32(acc[mt][nt], a[mt], b[nt]);
        }
        __syncthreads();
        stage ^= 1;
    }

    // epilogue: c0,c1 at (row, col..col+1); c2,c3 at (row+8, ...)
#pragma unroll
    for (int mt = 0; mt < 2; mt++) {
        int row = bm + warpM * 32 + mt * 16 + lg;
#pragma unroll
        for (int nt = 0; nt < 8; nt++) {
            int col = bn + warpN * 64 + nt * 8 + lt * 2;
            float b0 = bias[col], b1 = bias[col + 1];
            float4 v = acc[mt][nt];
            float o00 = v.x + b0, o01 = v.y + b1;   // row
            float o10 = v.z + b0, o11 = v.w + b1;   // row+8
            if (ep == 1) {
                o00 = tf32r(0.5f * o00 * (1.f + erff(o00 * 0.70710678f)));
                o01 = tf32r(0.5f * o01 * (1.f + erff(o01 * 0.70710678f)));
                o10 = tf32r(0.5f * o10 * (1.f + erff(o10 * 0.70710678f)));
                o11 = tf32r(0.5f * o11 * (1.f + erff(o11 * 0.70710678f)));
            } else if (ep == 2) {
                const float2 r0 = *reinterpret_cast<const float2*>(Res + (size_t)row * N + col);
                const float2 r1 = *reinterpret_cast<const float2*>(Res + (size_t)(row + 8) * N + col);
                o00 += r0.x; o01 += r0.y; o10 += r1.x; o11 += r1.y;
            }
            *reinterpret_cast<float2*>(C + (size_t)row * N + col)       = make_float2(o00, o01);
            *reinterpret_cast<float2*>(C + (size_t)(row + 8) * N + col) = make_float2(o10, o11);
        }
    }
}

// ---------------------------------------------------------------------------
// Window attention (fp32). One CTA per window, 8 warps = 8 heads.
// Output rounded to tf32 (only feeds the proj MMA).
// ---------------------------------------------------------------------------
__global__ __launch_bounds__(256) void attn_kernel(
    const float* __restrict__ qkv, const float* __restrict__ bias_table,
    float* __restrict__ out)
{
    __shared__ float sq[9][520];
    __shared__ float sk[9][520];
    __shared__ float sp[8][81];
    int b   = blockIdx.x;
    int tid = threadIdx.x;
    size_t base = (size_t)b * 9 * 1536;

    for (int idx = tid; idx < 9 * 512; idx += 256) {
        int n = idx >> 9, c = idx & 511;
        sq[n][c] = qkv[base + (size_t)n * 1536 + c] * 0.125f;
        sk[n][c] = qkv[base + (size_t)n * 1536 + 512 + c];
    }
    __syncthreads();

    int h = tid >> 5, lane = tid & 31;

#pragma unroll
    for (int r = 0; r < 3; r++) {
        int idx = r * 32 + lane;
        if (idx < 81) {
            int n = idx / 9, m = idx - n * 9;
            const float* qp = &sq[n][h * 64];
            const float* kp = &sk[m][h * 64];
            float s = 0.f;
#pragma unroll
            for (int d = 0; d < 64; d++) s = fmaf(qp[d], kp[d], s);
            int di = n / 3 - m / 3 + 2;
            int dj = n % 3 - m % 3 + 2;
            s += bias_table[(di * 5 + dj) * 8 + h];
            sp[h][idx] = s;
        }
    }
    __syncwarp();

    if (lane < 9) {
        float mx = -1e30f;
#pragma unroll
        for (int m = 0; m < 9; m++) mx = fmaxf(mx, sp[h][lane * 9 + m]);
        float e[9], sum = 0.f;
#pragma unroll
        for (int m = 0; m < 9; m++) { e[m] = __expf(sp[h][lane * 9 + m] - mx); sum += e[m]; }
        float inv = 1.f / sum;
#pragma unroll
        for (int m = 0; m < 9; m++) sp[h][lane * 9 + m] = e[m] * inv;
    }
    __syncwarp();

    float a0[9], a1[9];
#pragma unroll
    for (int n = 0; n < 9; n++) { a0[n] = 0.f; a1[n] = 0.f; }
#pragma unroll
    for (int m = 0; m < 9; m++) {
        size_t vb = base + (size_t)m * 1536 + 1024 + h * 64;
        float v0 = qkv[vb + lane];
        float v1 = qkv[vb + 32 + lane];
#pragma unroll
        for (int n = 0; n < 9; n++) {
            float p = sp[h][n * 9 + m];
            a0[n] = fmaf(p, v0, a0[n]);
            a1[n] = fmaf(p, v1, a1[n]);
        }
    }
#pragma unroll
    for (int n = 0; n < 9; n++) {
        size_t o = ((size_t)b * 9 + n) * 512 + h * 64;
        out[o + lane]      = tf32r(a0[n]);
        out[o + 32 + lane] = tf32r(a1[n]);
    }
}

// ---------------------------------------------------------------------------
// Depthwise 3x3 merge conv (fp32)
// ---------------------------------------------------------------------------
__global__ __launch_bounds__(256) void conv_kernel(
    const float* __restrict__ x, const float* __restrict__ w,
    const float* __restrict__ bc, float* __restrict__ out)
{
    int i = blockIdx.x * 256 + threadIdx.x;
    int c = i & 511;
    int b = i >> 9;
    float acc = bc[c];
    size_t base = (size_t)b * 9 * 512 + c;
#pragma unroll
    for (int n = 0; n < 9; n++)
        acc = fmaf(x[base + (size_t)n * 512], w[c * 9 + n], acc);
    out[i] = acc;
}

// ---------------------------------------------------------------------------
extern "C" void kernel_launch(void* const* d_in, const int* in_sizes, int n_in,
                              void* d_out, int out_size)
{
    const float* x          = (const float*)d_in[0];
    const float* gamma1     = (const float*)d_in[1];
    const float* beta1      = (const float*)d_in[2];
    const float* w_qkv      = (const float*)d_in[3];
    const float* b_qkv      = (const float*)d_in[4];
    const float* bias_table = (const float*)d_in[5];
    const float* w_proj     = (const float*)d_in[6];
    const float* b_proj     = (const float*)d_in[7];
    const float* gamma2     = (const float*)d_in[8];
    const float* beta2      = (const float*)d_in[9];
    const float* w_fc1      = (const float*)d_in[10];
    const float* b_fc1      = (const float*)d_in[11];
    const float* w_fc2      = (const float*)d_in[12];
    const float* b_fc2      = (const float*)d_in[13];
    const float* w_conv     = (const float*)d_in[14];
    const float* b_conv     = (const float*)d_in[15];
    float* out = (float*)d_out;

    float *h, *qkv, *attn, *x1, *mlp, *w;
    cudaGetSymbolAddress((void**)&h,    g_h);
    cudaGetSymbolAddress((void**)&qkv,  g_qkv);
    cudaGetSymbolAddress((void**)&attn, g_attn);
    cudaGetSymbolAddress((void**)&x1,   g_x1);
    cudaGetSymbolAddress((void**)&mlp,  g_mlp);
    cudaGetSymbolAddress((void**)&w,    g_w);

    const int SMEM = 4 * ATILE * sizeof(float);   // 73728 B
    cudaFuncSetAttribute(gemm_tf32_kernel,
                         cudaFuncAttributeMaxDynamicSharedMemorySize, SMEM);

    float* wq = w;
    float* wp = w + 786432;
    float* w1 = w + 1048576;
    float* w2 = w + 2097152;

    // pre-round weights to tf32
    roundw_kernel<<<3072, 256>>>(w_qkv, wq, 786432);
    roundw_kernel<<<1024, 256>>>(w_proj, wp, 262144);
    roundw_kernel<<<4096, 256>>>(w_fc1, w1, 1048576);
    roundw_kernel<<<4096, 256>>>(w_fc2, w2, 1048576);

    const int MB = MROWS / 128;   // 576 row tiles

    // LN1: x -> h (tf32)
    ln_kernel<<<MROWS / 8, dim3(32, 8)>>>(x, gamma1, beta1, h);
    // QKV: h @ wq^T + b_qkv -> qkv (fp32)
    gemm_tf32_kernel<<<dim3(12, MB), 256, SMEM>>>(h, wq, b_qkv, nullptr, qkv, 1536, 512, 0);
    // window attention -> attn (tf32)
    attn_kernel<<<8192, 256>>>(qkv, bias_table, attn);
    // proj + shortcut: attn @ wp^T + b_proj + x -> x1 (fp32)
    gemm_tf32_kernel<<<dim3(4, MB), 256, SMEM>>>(attn, wp, b_proj, x, x1, 512, 512, 2);
    // LN2: x1 -> h (tf32)
    ln_kernel<<<MROWS / 8, dim3(32, 8)>>>(x1, gamma2, beta2, h);
    // FC1 + GELU: h @ w1^T + b_fc1 -> mlp (tf32)
    gemm_tf32_kernel<<<dim3(16, MB), 256, SMEM>>>(h, w1, b_fc1, nullptr, mlp, 2048, 512, 1);
    // FC2 + residual: mlp @ w2^T + b_fc2 + x1 -> x2 (reuse attn buffer, fp32)
    gemm_tf32_kernel<<<dim3(4, MB), 256, SMEM>>>(mlp, w2, b_fc2, x1, attn, 512, 2048, 2);
    // merge conv -> out
    conv_kernel<<<(8192 * 512) / 256, 256>>>(attn, w_conv, b_conv, out);
}

// round 4
// speedup vs baseline: 10.2649x; 1.4761x over previous
#include <cuda_runtime.h>
#include <cuda_bf16.h>
#include <math.h>
#include <stdint.h>

// ---------------------------------------------------------------------------
// TransformerBlock: B=8192, N=9, DIM=512, HEADS=8, HEAD_DIM=64
// Round 3: bf16 tensor-core GEMMs (m16n8k16), bf16 intermediate storage,
// 3-stage cp.async pipeline. Residual stream stays fp32.
// ---------------------------------------------------------------------------

#define MROWS (8192 * 9)   // 73728 token rows

typedef __nv_bfloat16  bf16;
typedef __nv_bfloat162 bf162;

// Scratch (allocation-free: static device globals)
__device__ __align__(16) bf16  g_h   [(size_t)MROWS * 512];   // LN out (bf16)
__device__ __align__(16) bf16  g_qkv [(size_t)MROWS * 1536];  // QKV (bf16); later reused as fp32 x2
__device__ __align__(16) bf16  g_attn[(size_t)MROWS * 512];   // attn out (bf16)
__device__ __align__(16) float g_x1  [(size_t)MROWS * 512];   // residual after attn (fp32)
__device__ __align__(16) bf16  g_mlp [(size_t)MROWS * 2048];  // GELU(FC1) (bf16)
__device__ __align__(16) bf16  g_wb  [3145728];               // bf16 weights

__device__ __forceinline__ void cp16(void* dst, const void* src) {
    uint32_t s = (uint32_t)__cvta_generic_to_shared(dst);
    asm volatile("cp.async.cg.shared.global [%0], [%1], 16;\n" :: "r"(s), "l"(src));
}
__device__ __forceinline__ void cp_commit() { asm volatile("cp.async.commit_group;\n"); }
template <int N> __device__ __forceinline__ void cp_wait() {
    asm volatile("cp.async.wait_group %0;\n" :: "n"(N));
}

__device__ __forceinline__ void mma_bf16(float4& d, const uint32_t a[4], const uint32_t b[2]) {
    asm volatile(
        "mma.sync.aligned.m16n8k16.row.col.f32.bf16.bf16.f32 "
        "{%0,%1,%2,%3}, {%4,%5,%6,%7}, {%8,%9}, {%0,%1,%2,%3};\n"
        : "+f"(d.x), "+f"(d.y), "+f"(d.z), "+f"(d.w)
        : "r"(a[0]), "r"(a[1]), "r"(a[2]), "r"(a[3]), "r"(b[0]), "r"(b[1]));
}

// ---------------------------------------------------------------------------
// Convert fp32 weights -> bf16 (vectorized)
// ---------------------------------------------------------------------------
__global__ __launch_bounds__(256) void convw_kernel(
    const float* __restrict__ in, bf16* __restrict__ out, int n4)
{
    int i = blockIdx.x * 256 + threadIdx.x;
    if (i < n4) {
        float4 v = reinterpret_cast<const float4*>(in)[i];
        bf162* o = reinterpret_cast<bf162*>(out) + i * 2;
        o[0] = __floats2bfloat162_rn(v.x, v.y);
        o[1] = __floats2bfloat162_rn(v.z, v.w);
    }
}

// ---------------------------------------------------------------------------
// LayerNorm over last dim (512). One warp per row. fp32 in -> bf16 out.
// ---------------------------------------------------------------------------
__global__ __launch_bounds__(256) void ln_kernel(
    const float* __restrict__ x, const float* __restrict__ gam,
    const float* __restrict__ bet, bf16* __restrict__ out)
{
    int row  = blockIdx.x * 8 + threadIdx.y;
    int lane = threadIdx.x;
    const float4* xr = reinterpret_cast<const float4*>(x) + (size_t)row * 128;
    float4 v[4];
    float s = 0.f, s2 = 0.f;
#pragma unroll
    for (int i = 0; i < 4; i++) {
        v[i] = xr[lane + 32 * i];
        s  += v[i].x + v[i].y + v[i].z + v[i].w;
        s2 += v[i].x * v[i].x + v[i].y * v[i].y + v[i].z * v[i].z + v[i].w * v[i].w;
    }
#pragma unroll
    for (int o = 16; o; o >>= 1) {
        s  += __shfl_xor_sync(0xffffffffu, s,  o);
        s2 += __shfl_xor_sync(0xffffffffu, s2, o);
    }
    float mu   = s * (1.f / 512.f);
    float var  = s2 * (1.f / 512.f) - mu * mu;
    float rstd = rsqrtf(var + 1e-5f);
    bf162* orow = reinterpret_cast<bf162*>(out) + (size_t)row * 256;
    const float4* g4 = reinterpret_cast<const float4*>(gam);
    const float4* b4 = reinterpret_cast<const float4*>(bet);
#pragma unroll
    for (int i = 0; i < 4; i++) {
        int c = lane + 32 * i;
        float4 g = g4[c], b = b4[c];
        float o0 = (v[i].x - mu) * rstd * g.x + b.x;
        float o1 = (v[i].y - mu) * rstd * g.y + b.y;
        float o2 = (v[i].z - mu) * rstd * g.z + b.z;
        float o3 = (v[i].w - mu) * rstd * g.w + b.w;
        orow[2 * c]     = __floats2bfloat162_rn(o0, o1);
        orow[2 * c + 1] = __floats2bfloat162_rn(o2, o3);
    }
}

// ---------------------------------------------------------------------------
// bf16 tensor-core GEMM: C[M,N] = A[M,K] @ Bw[N,K]^T + bias[N] (+ epilogue)
//   EP=0: none (bf16 out);  EP=1: exact GELU (bf16 out);  EP=2: +Res (fp32 out)
// 128x128x32 CTA tile, 8 warps (4Mx2N), warp = 32x64 via m16n8k16.
// 3-stage cp.async pipeline. Smem pitch 40 bf16 (80B): conflict-free frags.
// ---------------------------------------------------------------------------
#define BK     32
#define PITCH  40                  // bf16 elements per smem row
#define TILE   (128 * PITCH)       // bf16 elements per stage per matrix
#define STAGES 3
#define GSMEM  (STAGES * 2 * TILE * 2)   // bytes = 61440

__device__ __forceinline__ void store2(bf16* C, size_t off, float a, float b) {
    *reinterpret_cast<bf162*>(C + off) = __floats2bfloat162_rn(a, b);
}
__device__ __forceinline__ void store2(float* C, size_t off, float a, float b) {
    *reinterpret_cast<float2*>(C + off) = make_float2(a, b);
}

template <int EP, typename OutT>
__global__ __launch_bounds__(256, 2) void gemm_bf16_kernel(
    const bf16* __restrict__ A, const bf16* __restrict__ Bw,
    const float* __restrict__ bias, const float* __restrict__ Res,
    OutT* __restrict__ C, int N, int K)
{
    extern __shared__ bf16 smem[];   // [A stages][B stages]

    int tid  = threadIdx.x;
    int bm   = blockIdx.y * 128, bn = blockIdx.x * 128;
    int warp = tid >> 5, lane = tid & 31;
    int warpM = warp >> 1, warpN = warp & 1;
    int lg = lane >> 2, lt = lane & 3;

    // loaders: 16B = 8 bf16 per cp; 128 rows x 32 cols per matrix per stage
    int lrow = tid >> 2;           // 0..63
    int lcol = (tid & 3) * 8;      // 0,8,16,24
    const bf16* Ag = A  + (size_t)(bm + lrow) * K + lcol;
    const bf16* Bg = Bw + (size_t)(bn + lrow) * K + lcol;

    float4 acc[2][8];
#pragma unroll
    for (int mt = 0; mt < 2; mt++)
#pragma unroll
        for (int nt = 0; nt < 8; nt++) acc[mt][nt] = make_float4(0.f, 0.f, 0.f, 0.f);

    auto loadTile = [&](int stage, int kt) {
        bf16* as = smem + stage * TILE;
        bf16* bs = smem + STAGES * TILE + stage * TILE;
#pragma unroll
        for (int p = 0; p < 2; p++) {
            int r = p * 64 + lrow;
            cp16(as + r * PITCH + lcol, Ag + (size_t)p * 64 * K + kt);
            cp16(bs + r * PITCH + lcol, Bg + (size_t)p * 64 * K + kt);
        }
    };

    loadTile(0, 0);  cp_commit();
    loadTile(1, BK); cp_commit();

    int stage = 0;
    for (int kt = 0; kt < K; kt += BK) {
        int pre = stage + 2; if (pre >= STAGES) pre -= STAGES;
        if (kt + 2 * BK < K) loadTile(pre, kt + 2 * BK);
        cp_commit();
        cp_wait<2>();
        __syncthreads();

        const bf16* as = smem + stage * TILE;
        const bf16* bs = smem + STAGES * TILE + stage * TILE;
#pragma unroll
        for (int ks = 0; ks < 2; ks++) {
            int k0 = ks * 16;
            uint32_t a[2][4], b[8][2];
#pragma unroll
            for (int mt = 0; mt < 2; mt++) {
                const bf16* p = as + (warpM * 32 + mt * 16 + lg) * PITCH + k0 + lt * 2;
                a[mt][0] = *reinterpret_cast<const uint32_t*>(p);
                a[mt][1] = *reinterpret_cast<const uint32_t*>(p + 8 * PITCH);
                a[mt][2] = *reinterpret_cast<const uint32_t*>(p + 8);
                a[mt][3] = *reinterpret_cast<const uint32_t*>(p + 8 * PITCH + 8);
            }
#pragma unroll
            for (int nt = 0; nt < 8; nt++) {
                const bf16* p = bs + (warpN * 64 + nt * 8 + lg) * PITCH + k0 + lt * 2;
                b[nt][0] = *reinterpret_cast<const uint32_t*>(p);
                b[nt][1] = *reinterpret_cast<const uint32_t*>(p + 8);
            }
#pragma unroll
            for (int mt = 0; mt < 2; mt++)
#pragma unroll
                for (int nt = 0; nt < 8; nt++)
                    mma_bf16(acc[mt][nt], a[mt], b[nt]);
        }
        __syncthreads();
        stage++; if (stage >= STAGES) stage = 0;
    }

    // epilogue
#pragma unroll
    for (int mt = 0; mt < 2; mt++) {
        int row = bm + warpM * 32 + mt * 16 + lg;
#pragma unroll
        for (int nt = 0; nt < 8; nt++) {
            int col = bn + warpN * 64 + nt * 8 + lt * 2;
            float b0 = bias[col], b1 = bias[col + 1];
            float4 v = acc[mt][nt];
            float o00 = v.x + b0, o01 = v.y + b1;   // row
            float o10 = v.z + b0, o11 = v.w + b1;   // row+8
            if (EP == 1) {
                o00 = 0.5f * o00 * (1.f + erff(o00 * 0.70710678f));
                o01 = 0.5f * o01 * (1.f + erff(o01 * 0.70710678f));
                o10 = 0.5f * o10 * (1.f + erff(o10 * 0.70710678f));
                o11 = 0.5f * o11 * (1.f + erff(o11 * 0.70710678f));
            } else if (EP == 2) {
                const float2 r0 = *reinterpret_cast<const float2*>(Res + (size_t)row * N + col);
                const float2 r1 = *reinterpret_cast<const float2*>(Res + (size_t)(row + 8) * N + col);
                o00 += r0.x; o01 += r0.y; o10 += r1.x; o11 += r1.y;
            }
            store2(C, (size_t)row * N + col,       o00, o01);
            store2(C, (size_t)(row + 8) * N + col, o10, o11);
        }
    }
}

// ---------------------------------------------------------------------------
// Window attention (fp32 math). One CTA per window, 8 warps = 8 heads.
// bf16 qkv in -> bf16 attn out.
// ---------------------------------------------------------------------------
__global__ __launch_bounds__(256) void attn_kernel(
    const bf16* __restrict__ qkv, const float* __restrict__ bias_table,
    bf16* __restrict__ out)
{
    __shared__ float sq[9][520];
    __shared__ float sk[9][520];
    __shared__ float sp[8][81];
    int b   = blockIdx.x;
    int tid = threadIdx.x;
    size_t base = (size_t)b * 9 * 1536;

    for (int idx = tid; idx < 9 * 256; idx += 256) {
        int n = idx >> 8, c2 = idx & 255;
        float2 q = __bfloat1622float2(
            *reinterpret_cast<const bf162*>(qkv + base + (size_t)n * 1536 + c2 * 2));
        float2 k = __bfloat1622float2(
            *reinterpret_cast<const bf162*>(qkv + base + (size_t)n * 1536 + 512 + c2 * 2));
        sq[n][c2 * 2]     = q.x * 0.125f;
        sq[n][c2 * 2 + 1] = q.y * 0.125f;
        sk[n][c2 * 2]     = k.x;
        sk[n][c2 * 2 + 1] = k.y;
    }
    __syncthreads();

    int h = tid >> 5, lane = tid & 31;

#pragma unroll
    for (int r = 0; r < 3; r++) {
        int idx = r * 32 + lane;
        if (idx < 81) {
            int n = idx / 9, m = idx - n * 9;
            const float* qp = &sq[n][h * 64];
            const float* kp = &sk[m][h * 64];
            float s = 0.f;
#pragma unroll
            for (int d = 0; d < 64; d++) s = fmaf(qp[d], kp[d], s);
            int di = n / 3 - m / 3 + 2;
            int dj = n % 3 - m % 3 + 2;
            s += bias_table[(di * 5 + dj) * 8 + h];
            sp[h][idx] = s;
        }
    }
    __syncwarp();

    if (lane < 9) {
        float mx = -1e30f;
#pragma unroll
        for (int m = 0; m < 9; m++) mx = fmaxf(mx, sp[h][lane * 9 + m]);
        float e[9], sum = 0.f;
#pragma unroll
        for (int m = 0; m < 9; m++) { e[m] = __expf(sp[h][lane * 9 + m] - mx); sum += e[m]; }
        float inv = 1.f / sum;
#pragma unroll
        for (int m = 0; m < 9; m++) sp[h][lane * 9 + m] = e[m] * inv;
    }
    __syncwarp();

    float a0[9], a1[9];
#pragma unroll
    for (int n = 0; n < 9; n++) { a0[n] = 0.f; a1[n] = 0.f; }
#pragma unroll
    for (int m = 0; m < 9; m++) {
        size_t vb = base + (size_t)m * 1536 + 1024 + h * 64;
        float v0 = __bfloat162float(qkv[vb + lane]);
        float v1 = __bfloat162float(qkv[vb + 32 + lane]);
#pragma unroll
        for (int n = 0; n < 9; n++) {
            float p = sp[h][n * 9 + m];
            a0[n] = fmaf(p, v0, a0[n]);
            a1[n] = fmaf(p, v1, a1[n]);
        }
    }
#pragma unroll
    for (int n = 0; n < 9; n++) {
        size_t o = ((size_t)b * 9 + n) * 512 + h * 64;
        out[o + lane]      = __float2bfloat16_rn(a0[n]);
        out[o + 32 + lane] = __float2bfloat16_rn(a1[n]);
    }
}

// ---------------------------------------------------------------------------
// Depthwise 3x3 merge conv (fp32)
// ---------------------------------------------------------------------------
__global__ __launch_bounds__(256) void conv_kernel(
    const float* __restrict__ x, const float* __restrict__ w,
    const float* __restrict__ bc, float* __restrict__ out)
{
    int i = blockIdx.x * 256 + threadIdx.x;
    int c = i & 511;
    int b = i >> 9;
    float acc = bc[c];
    size_t base = (size_t)b * 9 * 512 + c;
#pragma unroll
    for (int n = 0; n < 9; n++)
        acc = fmaf(x[base + (size_t)n * 512], w[c * 9 + n], acc);
    out[i] = acc;
}

// ---------------------------------------------------------------------------
extern "C" void kernel_launch(void* const* d_in, const int* in_sizes, int n_in,
                              void* d_out, int out_size)
{
    const float* x          = (const float*)d_in[0];
    const float* gamma1     = (const float*)d_in[1];
    const float* beta1      = (const float*)d_in[2];
    const float* w_qkv      = (const float*)d_in[3];
    const float* b_qkv      = (const float*)d_in[4];
    const float* bias_table = (const float*)d_in[5];
    const float* w_proj     = (const float*)d_in[6];
    const float* b_proj     = (const float*)d_in[7];
    const float* gamma2     = (const float*)d_in[8];
    const float* beta2      = (const float*)d_in[9];
    const float* w_fc1      = (const float*)d_in[10];
    const float* b_fc1      = (const float*)d_in[11];
    const float* w_fc2      = (const float*)d_in[12];
    const float* b_fc2      = (const float*)d_in[13];
    const float* w_conv     = (const float*)d_in[14];
    const float* b_conv     = (const float*)d_in[15];
    float* out = (float*)d_out;

    bf16 *h, *qkv, *attn, *mlp, *wb;
    float *x1;
    cudaGetSymbolAddress((void**)&h,    g_h);
    cudaGetSymbolAddress((void**)&qkv,  g_qkv);
    cudaGetSymbolAddress((void**)&attn, g_attn);
    cudaGetSymbolAddress((void**)&x1,   g_x1);
    cudaGetSymbolAddress((void**)&mlp,  g_mlp);
    cudaGetSymbolAddress((void**)&wb,   g_wb);
    float* x2 = reinterpret_cast<float*>(qkv);   // reuse qkv buffer after FC2 input read? no — after attn consumed qkv; FC2 writes here

    cudaFuncSetAttribute(gemm_bf16_kernel<0, bf16>,
                         cudaFuncAttributeMaxDynamicSharedMemorySize, GSMEM);
    cudaFuncSetAttribute(gemm_bf16_kernel<1, bf16>,
                         cudaFuncAttributeMaxDynamicSharedMemorySize, GSMEM);
    cudaFuncSetAttribute(gemm_bf16_kernel<2, float>,
                         cudaFuncAttributeMaxDynamicSharedMemorySize, GSMEM);

    bf16* wq = wb;
    bf16* wp = wb + 786432;
    bf16* w1 = wb + 1048576;
    bf16* w2 = wb + 2097152;

    convw_kernel<<<768,  256>>>(w_qkv,  wq, 196608);
    convw_kernel<<<256,  256>>>(w_proj, wp, 65536);
    convw_kernel<<<1024, 256>>>(w_fc1,  w1, 262144);
    convw_kernel<<<1024, 256>>>(w_fc2,  w2, 262144);

    const int MB = MROWS / 128;   // 576 row tiles

    // LN1: x -> h (bf16)
    ln_kernel<<<MROWS / 8, dim3(32, 8)>>>(x, gamma1, beta1, h);
    // QKV: h @ wq^T + b_qkv -> qkv (bf16)
    gemm_bf16_kernel<0, bf16><<<dim3(12, MB), 256, GSMEM>>>(h, wq, b_qkv, nullptr, qkv, 1536, 512);
    // window attention -> attn (bf16)
    attn_kernel<<<8192, 256>>>(qkv, bias_table, attn);
    // proj + shortcut: attn @ wp^T + b_proj + x -> x1 (fp32)
    gemm_bf16_kernel<2, float><<<dim3(4, MB), 256, GSMEM>>>(attn, wp, b_proj, x, x1, 512, 512);
    // LN2: x1 -> h (bf16)
    ln_kernel<<<MROWS / 8, dim3(32, 8)>>>(x1, gamma2, beta2, h);
    // FC1 + GELU: h @ w1^T + b_fc1 -> mlp (bf16)
    gemm_bf16_kernel<1, bf16><<<dim3(16, MB), 256, GSMEM>>>(h, w1, b_fc1, nullptr, mlp, 2048, 512);
    // FC2 + residual: mlp @ w2^T + b_fc2 + x1 -> x2 (fp32, reuses qkv buffer)
    gemm_bf16_kernel<2, float><<<dim3(4, MB), 256, GSMEM>>>(mlp, w2, b_fc2, x1, x2, 512, 2048);
    // merge conv -> out
    conv_kernel<<<(8192 * 512) / 256, 256>>>(x2, w_conv, b_conv, out);
}

// round 7
// speedup vs baseline: 10.6138x; 1.0340x over previous
#include <cuda_runtime.h>
#include <cuda_bf16.h>
#include <math.h>
#include <stdint.h>

// ---------------------------------------------------------------------------
// TransformerBlock: B=8192, N=9, DIM=512, HEADS=8, HEAD_DIM=64
// Round 5: bf16 HMMA GEMMs with ldmatrix fragment loads (tcgen05 rejected by
// the harness's compute_103 PTX pass). 3-stage cp.async, bf16 intermediates,
// fp32 residual stream.
// ---------------------------------------------------------------------------

#define MROWS (8192 * 9)   // 73728 token rows

typedef __nv_bfloat16  bf16;
typedef __nv_bfloat162 bf162;

// Scratch (allocation-free: static device globals)
__device__ __align__(16) bf16  g_h   [(size_t)MROWS * 512];   // LN out (bf16)
__device__ __align__(16) bf16  g_qkv [(size_t)MROWS * 1536];  // QKV (bf16); later fp32 x2
__device__ __align__(16) bf16  g_attn[(size_t)MROWS * 512];   // attn out (bf16)
__device__ __align__(16) float g_x1  [(size_t)MROWS * 512];   // residual after attn (fp32)
__device__ __align__(16) bf16  g_mlp [(size_t)MROWS * 2048];  // GELU(FC1) (bf16)
__device__ __align__(16) bf16  g_wb  [3145728];               // bf16 weights

__device__ __forceinline__ void cp16(void* dst, const void* src) {
    uint32_t s = (uint32_t)__cvta_generic_to_shared(dst);
    asm volatile("cp.async.cg.shared.global [%0], [%1], 16;\n" :: "r"(s), "l"(src));
}
__device__ __forceinline__ void cp_commit() { asm volatile("cp.async.commit_group;\n"); }
template <int N> __device__ __forceinline__ void cp_wait() {
    asm volatile("cp.async.wait_group %0;\n" :: "n"(N));
}

__device__ __forceinline__ void mma_bf16(float4& d, const uint32_t a[4], const uint32_t b[2]) {
    asm volatile(
        "mma.sync.aligned.m16n8k16.row.col.f32.bf16.bf16.f32 "
        "{%0,%1,%2,%3}, {%4,%5,%6,%7}, {%8,%9}, {%0,%1,%2,%3};\n"
        : "+f"(d.x), "+f"(d.y), "+f"(d.z), "+f"(d.w)
        : "r"(a[0]), "r"(a[1]), "r"(a[2]), "r"(a[3]), "r"(b[0]), "r"(b[1]));
}
__device__ __forceinline__ void ldsm4(uint32_t& r0, uint32_t& r1, uint32_t& r2,
                                      uint32_t& r3, uint32_t addr) {
    asm volatile("ldmatrix.sync.aligned.m8n8.x4.shared.b16 {%0,%1,%2,%3}, [%4];"
                 : "=r"(r0), "=r"(r1), "=r"(r2), "=r"(r3) : "r"(addr));
}

// ---------------------------------------------------------------------------
// Convert fp32 weights -> bf16 (vectorized)
// ---------------------------------------------------------------------------
__global__ __launch_bounds__(256) void convw_kernel(
    const float* __restrict__ in, bf16* __restrict__ out, int n4)
{
    int i = blockIdx.x * 256 + threadIdx.x;
    if (i < n4) {
        float4 v = reinterpret_cast<const float4*>(in)[i];
        bf162* o = reinterpret_cast<bf162*>(out) + i * 2;
        o[0] = __floats2bfloat162_rn(v.x, v.y);
        o[1] = __floats2bfloat162_rn(v.z, v.w);
    }
}

// ---------------------------------------------------------------------------
// LayerNorm over last dim (512). One warp per row. fp32 in -> bf16 out.
// ---------------------------------------------------------------------------
__global__ __launch_bounds__(256) void ln_kernel(
    const float* __restrict__ x, const float* __restrict__ gam,
    const float* __restrict__ bet, bf16* __restrict__ out)
{
    int row  = blockIdx.x * 8 + threadIdx.y;
    int lane = threadIdx.x;
    const float4* xr = reinterpret_cast<const float4*>(x) + (size_t)row * 128;
    float4 v[4];
    float s = 0.f, s2 = 0.f;
#pragma unroll
    for (int i = 0; i < 4; i++) {
        v[i] = xr[lane + 32 * i];
        s  += v[i].x + v[i].y + v[i].z + v[i].w;
        s2 += v[i].x * v[i].x + v[i].y * v[i].y + v[i].z * v[i].z + v[i].w * v[i].w;
    }
#pragma unroll
    for (int o = 16; o; o >>= 1) {
        s  += __shfl_xor_sync(0xffffffffu, s,  o);
        s2 += __shfl_xor_sync(0xffffffffu, s2, o);
    }
    float mu   = s * (1.f / 512.f);
    float var  = s2 * (1.f / 512.f) - mu * mu;
    float rstd = rsqrtf(var + 1e-5f);
    bf162* orow = reinterpret_cast<bf162*>(out) + (size_t)row * 256;
    const float4* g4 = reinterpret_cast<const float4*>(gam);
    const float4* b4 = reinterpret_cast<const float4*>(bet);
#pragma unroll
    for (int i = 0; i < 4; i++) {
        int c = lane + 32 * i;
        float4 g = g4[c], b = b4[c];
        float o0 = (v[i].x - mu) * rstd * g.x + b.x;
        float o1 = (v[i].y - mu) * rstd * g.y + b.y;
        float o2 = (v[i].z - mu) * rstd * g.z + b.z;
        float o3 = (v[i].w - mu) * rstd * g.w + b.w;
        orow[2 * c]     = __floats2bfloat162_rn(o0, o1);
        orow[2 * c + 1] = __floats2bfloat162_rn(o2, o3);
    }
}

// ---------------------------------------------------------------------------
// bf16 HMMA GEMM: C[M,N] = A[M,K] @ Bw[N,K]^T + bias[N] (+ epilogue)
//   EP=0: none (bf16 out);  EP=1: exact GELU (bf16 out);  EP=2: +Res (fp32 out)
// 128x128x32 CTA tile, 8 warps (4Mx2N), warp = 32x64 via m16n8k16.
// ldmatrix.x4 fragment loads; 3-stage cp.async. PITCH=40 bf16 (80B rows):
// per-matrix row offsets mod 128B all distinct -> conflict-free LDSM.
// ---------------------------------------------------------------------------
#define BK     32
#define PITCH  40                  // bf16 elements per smem row
#define TILE   (128 * PITCH)       // bf16 elements per stage per matrix
#define STAGES 3
#define GSMEM  (STAGES * 2 * TILE * 2)   // bytes = 61440

__device__ __forceinline__ void store2(bf16* C, size_t off, float a, float b) {
    *reinterpret_cast<bf162*>(C + off) = __floats2bfloat162_rn(a, b);
}
__device__ __forceinline__ void store2(float* C, size_t off, float a, float b) {
    *reinterpret_cast<float2*>(C + off) = make_float2(a, b);
}

template <int EP, typename OutT>
__global__ __launch_bounds__(256, 2) void gemm_bf16_kernel(
    const bf16* __restrict__ A, const bf16* __restrict__ Bw,
    const float* __restrict__ bias, const float* __restrict__ Res,
    OutT* __restrict__ C, int N, int K)
{
    extern __shared__ bf16 smem[];   // [A stages][B stages]
    uint32_t sbase = (uint32_t)__cvta_generic_to_shared(smem);

    int tid  = threadIdx.x;
    int bm   = blockIdx.y * 128, bn = blockIdx.x * 128;
    int warp = tid >> 5, lane = tid & 31;
    int warpM = warp >> 1, warpN = warp & 1;
    int lg = lane >> 2, lt = lane & 3;

    // ldmatrix lane->row/k mapping (see header comment)
    int aRow = warpM * 32 + ((lane >> 3) & 1) * 8 + (lane & 7);
    int aK   = (lane >> 4) * 8;
    int bRow = warpN * 64 + (lane >> 4) * 8 + (lane & 7);
    int bK   = ((lane >> 3) & 1) * 8;

    // loaders: 16B = 8 bf16 per cp; 128 rows x 32 cols per matrix per stage
    int lrow = tid >> 2;           // 0..63
    int lcol = (tid & 3) * 8;      // 0,8,16,24
    const bf16* Ag = A  + (size_t)(bm + lrow) * K + lcol;
    const bf16* Bg = Bw + (size_t)(bn + lrow) * K + lcol;

    float4 acc[2][8];
#pragma unroll
    for (int mt = 0; mt < 2; mt++)
#pragma unroll
        for (int nt = 0; nt < 8; nt++) acc[mt][nt] = make_float4(0.f, 0.f, 0.f, 0.f);

    auto loadTile = [&](int stage, int kt) {
        bf16* as = smem + stage * TILE;
        bf16* bs = smem + STAGES * TILE + stage * TILE;
#pragma unroll
        for (int p = 0; p < 2; p++) {
            int r = p * 64 + lrow;
            cp16(as + r * PITCH + lcol, Ag + (size_t)p * 64 * K + kt);
            cp16(bs + r * PITCH + lcol, Bg + (size_t)p * 64 * K + kt);
        }
    };

    loadTile(0, 0);  cp_commit();
    loadTile(1, BK); cp_commit();

    int stage = 0;
    for (int kt = 0; kt < K; kt += BK) {
        int pre = stage + 2; if (pre >= STAGES) pre -= STAGES;
        if (kt + 2 * BK < K) loadTile(pre, kt + 2 * BK);
        cp_commit();
        cp_wait<2>();
        __syncthreads();

        uint32_t aBase = sbase + (stage * TILE) * 2;
        uint32_t bBase = sbase + (STAGES * TILE + stage * TILE) * 2;
#pragma unroll
        for (int ks = 0; ks < 2; ks++) {
            int k0 = ks * 16;
            uint32_t a[2][4], b[8][2];
#pragma unroll
            for (int mt = 0; mt < 2; mt++) {
                uint32_t addr = aBase + (uint32_t)(((aRow + mt * 16) * PITCH + k0 + aK) * 2);
                ldsm4(a[mt][0], a[mt][1], a[mt][2], a[mt][3], addr);
            }
#pragma unroll
            for (int np = 0; np < 4; np++) {
                uint32_t addr = bBase + (uint32_t)(((bRow + np * 16) * PITCH + k0 + bK) * 2);
                ldsm4(b[2 * np][0], b[2 * np][1], b[2 * np + 1][0], b[2 * np + 1][1], addr);
            }
#pragma unroll
            for (int mt = 0; mt < 2; mt++)
#pragma unroll
                for (int nt = 0; nt < 8; nt++)
                    mma_bf16(acc[mt][nt], a[mt], b[nt]);
        }
        __syncthreads();
        stage++; if (stage >= STAGES) stage = 0;
    }

    // epilogue
#pragma unroll
    for (int mt = 0; mt < 2; mt++) {
        int row = bm + warpM * 32 + mt * 16 + lg;
#pragma unroll
        for (int nt = 0; nt < 8; nt++) {
            int col = bn + warpN * 64 + nt * 8 + lt * 2;
            float b0 = bias[col], b1 = bias[col + 1];
            float4 v = acc[mt][nt];
            float o00 = v.x + b0, o01 = v.y + b1;   // row
            float o10 = v.z + b0, o11 = v.w + b1;   // row+8
            if (EP == 1) {
                o00 = 0.5f * o00 * (1.f + erff(o00 * 0.70710678f));
                o01 = 0.5f * o01 * (1.f + erff(o01 * 0.70710678f));
                o10 = 0.5f * o10 * (1.f + erff(o10 * 0.70710678f));
                o11 = 0.5f * o11 * (1.f + erff(o11 * 0.70710678f));
            } else if (EP == 2) {
                const float2 r0 = *reinterpret_cast<const float2*>(Res + (size_t)row * N + col);
                const float2 r1 = *reinterpret_cast<const float2*>(Res + (size_t)(row + 8) * N + col);
                o00 += r0.x; o01 += r0.y; o10 += r1.x; o11 += r1.y;
            }
            store2(C, (size_t)row * N + col,       o00, o01);
            store2(C, (size_t)(row + 8) * N + col, o10, o11);
        }
    }
}

// ---------------------------------------------------------------------------
// Window attention (fp32 math). One CTA per window, 8 warps = 8 heads.
// ---------------------------------------------------------------------------
__global__ __launch_bounds__(256) void attn_kernel(
    const bf16* __restrict__ qkv, const float* __restrict__ bias_table,
    bf16* __restrict__ out)
{
    __shared__ float sq[9][520];
    __shared__ float sk[9][520];
    __shared__ float sp[8][81];
    int b   = blockIdx.x;
    int tid = threadIdx.x;
    size_t base = (size_t)b * 9 * 1536;

    for (int idx = tid; idx < 9 * 256; idx += 256) {
        int n = idx >> 8, c2 = idx & 255;
        float2 q = __bfloat1622float2(
            *reinterpret_cast<const bf162*>(qkv + base + (size_t)n * 1536 + c2 * 2));
        float2 k = __bfloat1622float2(
            *reinterpret_cast<const bf162*>(qkv + base + (size_t)n * 1536 + 512 + c2 * 2));
        sq[n][c2 * 2]     = q.x * 0.125f;
        sq[n][c2 * 2 + 1] = q.y * 0.125f;
        sk[n][c2 * 2]     = k.x;
        sk[n][c2 * 2 + 1] = k.y;
    }
    __syncthreads();

    int h = tid >> 5, lane = tid & 31;

#pragma unroll
    for (int r = 0; r < 3; r++) {
        int idx = r * 32 + lane;
        if (idx < 81) {
            int n = idx / 9, m = idx - n * 9;
            const float* qp = &sq[n][h * 64];
            const float* kp = &sk[m][h * 64];
            float s = 0.f;
#pragma unroll
            for (int d = 0; d < 64; d++) s = fmaf(qp[d], kp[d], s);
            int di = n / 3 - m / 3 + 2;
            int dj = n % 3 - m % 3 + 2;
            s += bias_table[(di * 5 + dj) * 8 + h];
            sp[h][idx] = s;
        }
    }
    __syncwarp();

    if (lane < 9) {
        float mx = -1e30f;
#pragma unroll
        for (int m = 0; m < 9; m++) mx = fmaxf(mx, sp[h][lane * 9 + m]);
        float e[9], sum = 0.f;
#pragma unroll
        for (int m = 0; m < 9; m++) { e[m] = __expf(sp[h][lane * 9 + m] - mx); sum += e[m]; }
        float inv = 1.f / sum;
#pragma unroll
        for (int m = 0; m < 9; m++) sp[h][lane * 9 + m] = e[m] * inv;
    }
    __syncwarp();

    float a0[9], a1[9];
#pragma unroll
    for (int n = 0; n < 9; n++) { a0[n] = 0.f; a1[n] = 0.f; }
#pragma unroll
    for (int m = 0; m < 9; m++) {
        size_t vb = base + (size_t)m * 1536 + 1024 + h * 64;
        float v0 = __bfloat162float(qkv[vb + lane]);
        float v1 = __bfloat162float(qkv[vb + 32 + lane]);
#pragma unroll
        for (int n = 0; n < 9; n++) {
            float p = sp[h][n * 9 + m];
            a0[n] = fmaf(p, v0, a0[n]);
            a1[n] = fmaf(p, v1, a1[n]);
        }
    }
#pragma unroll
    for (int n = 0; n < 9; n++) {
        size_t o = ((size_t)b * 9 + n) * 512 + h * 64;
        out[o + lane]      = __float2bfloat16_rn(a0[n]);
        out[o + 32 + lane] = __float2bfloat16_rn(a1[n]);
    }
}

// ---------------------------------------------------------------------------
// Depthwise 3x3 merge conv (fp32)
// ---------------------------------------------------------------------------
__global__ __launch_bounds__(256) void conv_kernel(
    const float* __restrict__ x, const float* __restrict__ w,
    const float* __restrict__ bc, float* __restrict__ out)
{
    int i = blockIdx.x * 256 + threadIdx.x;
    int c = i & 511;
    int b = i >> 9;
    float acc = bc[c];
    size_t base = (size_t)b * 9 * 512 + c;
#pragma unroll
    for (int n = 0; n < 9; n++)
        acc = fmaf(x[base + (size_t)n * 512], w[c * 9 + n], acc);
    out[i] = acc;
}

// ---------------------------------------------------------------------------
extern "C" void kernel_launch(void* const* d_in, const int* in_sizes, int n_in,
                              void* d_out, int out_size)
{
    const float* x          = (const float*)d_in[0];
    const float* gamma1     = (const float*)d_in[1];
    const float* beta1      = (const float*)d_in[2];
    const float* w_qkv      = (const float*)d_in[3];
    const float* b_qkv      = (const float*)d_in[4];
    const float* bias_table = (const float*)d_in[5];
    const float* w_proj     = (const float*)d_in[6];
    const float* b_proj     = (const float*)d_in[7];
    const float* gamma2     = (const float*)d_in[8];
    const float* beta2      = (const float*)d_in[9];
    const float* w_fc1      = (const float*)d_in[10];
    const float* b_fc1      = (const float*)d_in[11];
    const float* w_fc2      = (const float*)d_in[12];
    const float* b_fc2      = (const float*)d_in[13];
    const float* w_conv     = (const float*)d_in[14];
    const float* b_conv     = (const float*)d_in[15];
    float* out = (float*)d_out;

    bf16 *h, *qkv, *attn, *mlp, *wb;
    float *x1;
    cudaGetSymbolAddress((void**)&h,    g_h);
    cudaGetSymbolAddress((void**)&qkv,  g_qkv);
    cudaGetSymbolAddress((void**)&attn, g_attn);
    cudaGetSymbolAddress((void**)&x1,   g_x1);
    cudaGetSymbolAddress((void**)&mlp,  g_mlp);
    cudaGetSymbolAddress((void**)&wb,   g_wb);
    float* x2 = reinterpret_cast<float*>(qkv);   // reuse qkv buffer for x2 (fp32)

    cudaFuncSetAttribute(gemm_bf16_kernel<0, bf16>,
                         cudaFuncAttributeMaxDynamicSharedMemorySize, GSMEM);
    cudaFuncSetAttribute(gemm_bf16_kernel<1, bf16>,
                         cudaFuncAttributeMaxDynamicSharedMemorySize, GSMEM);
    cudaFuncSetAttribute(gemm_bf16_kernel<2, float>,
                         cudaFuncAttributeMaxDynamicSharedMemorySize, GSMEM);

    bf16* wq = wb;
    bf16* wp = wb + 786432;
    bf16* w1 = wb + 1048576;
    bf16* w2 = wb + 2097152;

    convw_kernel<<<768,  256>>>(w_qkv,  wq, 196608);
    convw_kernel<<<256,  256>>>(w_proj, wp, 65536);
    convw_kernel<<<1024, 256>>>(w_fc1,  w1, 262144);
    convw_kernel<<<1024, 256>>>(w_fc2,  w2, 262144);

    const int MB = MROWS / 128;   // 576 row tiles

    // LN1: x -> h (bf16)
    ln_kernel<<<MROWS / 8, dim3(32, 8)>>>(x, gamma1, beta1, h);
    // QKV: h @ wq^T + b_qkv -> qkv (bf16)
    gemm_bf16_kernel<0, bf16><<<dim3(12, MB), 256, GSMEM>>>(h, wq, b_qkv, nullptr, qkv, 1536, 512);
    // window attention -> attn (bf16)
    attn_kernel<<<8192, 256>>>(qkv, bias_table, attn);
    // proj + shortcut: attn @ wp^T + b_proj + x -> x1 (fp32)
    gemm_bf16_kernel<2, float><<<dim3(4, MB), 256, GSMEM>>>(attn, wp, b_proj, x, x1, 512, 512);
    // LN2: x1 -> h (bf16)
    ln_kernel<<<MROWS / 8, dim3(32, 8)>>>(x1, gamma2, beta2, h);
    // FC1 + GELU: h @ w1^T + b_fc1 -> mlp (bf16)
    gemm_bf16_kernel<1, bf16><<<dim3(16, MB), 256, GSMEM>>>(h, w1, b_fc1, nullptr, mlp, 2048, 512);
    // FC2 + residual: mlp @ w2^T + b_fc2 + x1 -> x2 (fp32, reuses qkv buffer)
    gemm_bf16_kernel<2, float><<<dim3(4, MB), 256, GSMEM>>>(mlp, w2, b_fc2, x1, x2, 512, 2048);
    // merge conv -> out
    conv_kernel<<<(8192 * 512) / 256, 256>>>(x2, w_conv, b_conv, out);
}

// round 8
// speedup vs baseline: 11.7258x; 1.1048x over previous
#include <cuda_runtime.h>
#include <cuda_bf16.h>
#include <math.h>
#include <stdint.h>

// ---------------------------------------------------------------------------
// TransformerBlock: B=8192, N=9, DIM=512, HEADS=8, HEAD_DIM=64
// Round 8: bf16 HMMA GEMMs, ldmatrix fragments, 4-stage cp.async ring with a
// SINGLE __syncthreads per k-tile (trailing barrier proven redundant at S=4).
// ---------------------------------------------------------------------------

#define MROWS (8192 * 9)   // 73728 token rows

typedef __nv_bfloat16  bf16;
typedef __nv_bfloat162 bf162;

// Scratch (allocation-free: static device globals)
__device__ __align__(16) bf16  g_h   [(size_t)MROWS * 512];   // LN out (bf16)
__device__ __align__(16) bf16  g_qkv [(size_t)MROWS * 1536];  // QKV (bf16); later fp32 x2
__device__ __align__(16) bf16  g_attn[(size_t)MROWS * 512];   // attn out (bf16)
__device__ __align__(16) float g_x1  [(size_t)MROWS * 512];   // residual after attn (fp32)
__device__ __align__(16) bf16  g_mlp [(size_t)MROWS * 2048];  // GELU(FC1) (bf16)
__device__ __align__(16) bf16  g_wb  [3145728];               // bf16 weights

__device__ __forceinline__ void cp16(void* dst, const void* src) {
    uint32_t s = (uint32_t)__cvta_generic_to_shared(dst);
    asm volatile("cp.async.cg.shared.global [%0], [%1], 16;\n" :: "r"(s), "l"(src));
}
__device__ __forceinline__ void cp_commit() { asm volatile("cp.async.commit_group;\n"); }
template <int N> __device__ __forceinline__ void cp_wait() {
    asm volatile("cp.async.wait_group %0;\n" :: "n"(N));
}

__device__ __forceinline__ void mma_bf16(float4& d, const uint32_t a[4], const uint32_t b[2]) {
    asm volatile(
        "mma.sync.aligned.m16n8k16.row.col.f32.bf16.bf16.f32 "
        "{%0,%1,%2,%3}, {%4,%5,%6,%7}, {%8,%9}, {%0,%1,%2,%3};\n"
        : "+f"(d.x), "+f"(d.y), "+f"(d.z), "+f"(d.w)
        : "r"(a[0]), "r"(a[1]), "r"(a[2]), "r"(a[3]), "r"(b[0]), "r"(b[1]));
}
__device__ __forceinline__ void ldsm4(uint32_t& r0, uint32_t& r1, uint32_t& r2,
                                      uint32_t& r3, uint32_t addr) {
    asm volatile("ldmatrix.sync.aligned.m8n8.x4.shared.b16 {%0,%1,%2,%3}, [%4];"
                 : "=r"(r0), "=r"(r1), "=r"(r2), "=r"(r3) : "r"(addr));
}

// ---------------------------------------------------------------------------
// Convert fp32 weights -> bf16 (vectorized)
// ---------------------------------------------------------------------------
__global__ __launch_bounds__(256) void convw_kernel(
    const float* __restrict__ in, bf16* __restrict__ out, int n4)
{
    int i = blockIdx.x * 256 + threadIdx.x;
    if (i < n4) {
        float4 v = reinterpret_cast<const float4*>(in)[i];
        bf162* o = reinterpret_cast<bf162*>(out) + i * 2;
        o[0] = __floats2bfloat162_rn(v.x, v.y);
        o[1] = __floats2bfloat162_rn(v.z, v.w);
    }
}

// ---------------------------------------------------------------------------
// LayerNorm over last dim (512). One warp per row. fp32 in -> bf16 out.
// ---------------------------------------------------------------------------
__global__ __launch_bounds__(256) void ln_kernel(
    const float* __restrict__ x, const float* __restrict__ gam,
    const float* __restrict__ bet, bf16* __restrict__ out)
{
    int row  = blockIdx.x * 8 + threadIdx.y;
    int lane = threadIdx.x;
    const float4* xr = reinterpret_cast<const float4*>(x) + (size_t)row * 128;
    float4 v[4];
    float s = 0.f, s2 = 0.f;
#pragma unroll
    for (int i = 0; i < 4; i++) {
        v[i] = xr[lane + 32 * i];
        s  += v[i].x + v[i].y + v[i].z + v[i].w;
        s2 += v[i].x * v[i].x + v[i].y * v[i].y + v[i].z * v[i].z + v[i].w * v[i].w;
    }
#pragma unroll
    for (int o = 16; o; o >>= 1) {
        s  += __shfl_xor_sync(0xffffffffu, s,  o);
        s2 += __shfl_xor_sync(0xffffffffu, s2, o);
    }
    float mu   = s * (1.f / 512.f);
    float var  = s2 * (1.f / 512.f) - mu * mu;
    float rstd = rsqrtf(var + 1e-5f);
    bf162* orow = reinterpret_cast<bf162*>(out) + (size_t)row * 256;
    const float4* g4 = reinterpret_cast<const float4*>(gam);
    const float4* b4 = reinterpret_cast<const float4*>(bet);
#pragma unroll
    for (int i = 0; i < 4; i++) {
        int c = lane + 32 * i;
        float4 g = g4[c], b = b4[c];
        float o0 = (v[i].x - mu) * rstd * g.x + b.x;
        float o1 = (v[i].y - mu) * rstd * g.y + b.y;
        float o2 = (v[i].z - mu) * rstd * g.z + b.z;
        float o3 = (v[i].w - mu) * rstd * g.w + b.w;
        orow[2 * c]     = __floats2bfloat162_rn(o0, o1);
        orow[2 * c + 1] = __floats2bfloat162_rn(o2, o3);
    }
}

// ---------------------------------------------------------------------------
// bf16 HMMA GEMM: C[M,N] = A[M,K] @ Bw[N,K]^T + bias[N] (+ epilogue)
//   EP=0: none (bf16 out);  EP=1: exact GELU (bf16 out);  EP=2: +Res (fp32 out)
// 128x128x32 CTA tile, 8 warps (4Mx2N), warp = 32x64 via m16n8k16.
// ldmatrix.x4 fragment loads; 4-stage cp.async, lookahead 2, ONE sync/tile.
// PITCH=40 bf16 (80B rows): conflict-free LDSM.
// ---------------------------------------------------------------------------
#define BK     32
#define PITCH  40                  // bf16 elements per smem row
#define TILE   (128 * PITCH)       // bf16 elements per stage per matrix
#define STAGES 4
#define GSMEM  (STAGES * 2 * TILE * 2)   // bytes = 81920

__device__ __forceinline__ void store2(bf16* C, size_t off, float a, float b) {
    *reinterpret_cast<bf162*>(C + off) = __floats2bfloat162_rn(a, b);
}
__device__ __forceinline__ void store2(float* C, size_t off, float a, float b) {
    *reinterpret_cast<float2*>(C + off) = make_float2(a, b);
}

template <int EP, typename OutT>
__global__ __launch_bounds__(256, 2) void gemm_bf16_kernel(
    const bf16* __restrict__ A, const bf16* __restrict__ Bw,
    const float* __restrict__ bias, const float* __restrict__ Res,
    OutT* __restrict__ C, int N, int K)
{
    extern __shared__ bf16 smem[];   // [A stages][B stages]
    uint32_t sbase = (uint32_t)__cvta_generic_to_shared(smem);

    int tid  = threadIdx.x;
    int bm   = blockIdx.y * 128, bn = blockIdx.x * 128;
    int warp = tid >> 5, lane = tid & 31;
    int warpM = warp >> 1, warpN = warp & 1;
    int lg = lane >> 2, lt = lane & 3;

    // ldmatrix lane->row/k mapping
    int aRow = warpM * 32 + ((lane >> 3) & 1) * 8 + (lane & 7);
    int aK   = (lane >> 4) * 8;
    int bRow = warpN * 64 + (lane >> 4) * 8 + (lane & 7);
    int bK   = ((lane >> 3) & 1) * 8;

    // loaders: 16B = 8 bf16 per cp; 128 rows x 32 cols per matrix per stage
    int lrow = tid >> 2;           // 0..63
    int lcol = (tid & 3) * 8;      // 0,8,16,24
    const bf16* Ag = A  + (size_t)(bm + lrow) * K + lcol;
    const bf16* Bg = Bw + (size_t)(bn + lrow) * K + lcol;

    float4 acc[2][8];
#pragma unroll
    for (int mt = 0; mt < 2; mt++)
#pragma unroll
        for (int nt = 0; nt < 8; nt++) acc[mt][nt] = make_float4(0.f, 0.f, 0.f, 0.f);

    auto loadTile = [&](int stage, int kt) {
        bf16* as = smem + stage * TILE;
        bf16* bs = smem + STAGES * TILE + stage * TILE;
#pragma unroll
        for (int p = 0; p < 2; p++) {
            int r = p * 64 + lrow;
            cp16(as + r * PITCH + lcol, Ag + (size_t)p * 64 * K + kt);
            cp16(bs + r * PITCH + lcol, Bg + (size_t)p * 64 * K + kt);
        }
    };

    loadTile(0, 0);  cp_commit();
    loadTile(1, BK); cp_commit();

    int stage = 0;
    for (int kt = 0; kt < K; kt += BK) {
        int pre = stage + 2; if (pre >= STAGES) pre -= STAGES;
        if (kt + 2 * BK < K) loadTile(pre, kt + 2 * BK);
        cp_commit();
        cp_wait<2>();
        __syncthreads();   // single barrier per tile (S=4, L=2 proof in header)

        uint32_t aBase = sbase + (stage * TILE) * 2;
        uint32_t bBase = sbase + (STAGES * TILE + stage * TILE) * 2;
#pragma unroll
        for (int ks = 0; ks < 2; ks++) {
            int k0 = ks * 16;
            uint32_t a[2][4], b[8][2];
#pragma unroll
            for (int mt = 0; mt < 2; mt++) {
                uint32_t addr = aBase + (uint32_t)(((aRow + mt * 16) * PITCH + k0 + aK) * 2);
                ldsm4(a[mt][0], a[mt][1], a[mt][2], a[mt][3], addr);
            }
#pragma unroll
            for (int np = 0; np < 4; np++) {
                uint32_t addr = bBase + (uint32_t)(((bRow + np * 16) * PITCH + k0 + bK) * 2);
                ldsm4(b[2 * np][0], b[2 * np][1], b[2 * np + 1][0], b[2 * np + 1][1], addr);
            }
#pragma unroll
            for (int mt = 0; mt < 2; mt++)
#pragma unroll
                for (int nt = 0; nt < 8; nt++)
                    mma_bf16(acc[mt][nt], a[mt], b[nt]);
        }
        stage++; if (stage >= STAGES) stage = 0;
    }

    // epilogue
#pragma unroll
    for (int mt = 0; mt < 2; mt++) {
        int row = bm + warpM * 32 + mt * 16 + lg;
#pragma unroll
        for (int nt = 0; nt < 8; nt++) {
            int col = bn + warpN * 64 + nt * 8 + lt * 2;
            float b0 = bias[col], b1 = bias[col + 1];
            float4 v = acc[mt][nt];
            float o00 = v.x + b0, o01 = v.y + b1;   // row
            float o10 = v.z + b0, o11 = v.w + b1;   // row+8
            if (EP == 1) {
                o00 = 0.5f * o00 * (1.f + erff(o00 * 0.70710678f));
                o01 = 0.5f * o01 * (1.f + erff(o01 * 0.70710678f));
                o10 = 0.5f * o10 * (1.f + erff(o10 * 0.70710678f));
                o11 = 0.5f * o11 * (1.f + erff(o11 * 0.70710678f));
            } else if (EP == 2) {
                const float2 r0 = *reinterpret_cast<const float2*>(Res + (size_t)row * N + col);
                const float2 r1 = *reinterpret_cast<const float2*>(Res + (size_t)(row + 8) * N + col);
                o00 += r0.x; o01 += r0.y; o10 += r1.x; o11 += r1.y;
            }
            store2(C, (size_t)row * N + col,       o00, o01);
            store2(C, (size_t)(row + 8) * N + col, o10, o11);
        }
    }
}

// ---------------------------------------------------------------------------
// Window attention (fp32 math). One CTA per window, 8 warps = 8 heads.
// ---------------------------------------------------------------------------
__global__ __launch_bounds__(256) void attn_kernel(
    const bf16* __restrict__ qkv, const float* __restrict__ bias_table,
    bf16* __restrict__ out)
{
    __shared__ float sq[9][520];
    __shared__ float sk[9][520];
    __shared__ float sp[8][81];
    int b   = blockIdx.x;
    int tid = threadIdx.x;
    size_t base = (size_t)b * 9 * 1536;

    for (int idx = tid; idx < 9 * 256; idx += 256) {
        int n = idx >> 8, c2 = idx & 255;
        float2 q = __bfloat1622float2(
            *reinterpret_cast<const bf162*>(qkv + base + (size_t)n * 1536 + c2 * 2));
        float2 k = __bfloat1622float2(
            *reinterpret_cast<const bf162*>(qkv + base + (size_t)n * 1536 + 512 + c2 * 2));
        sq[n][c2 * 2]     = q.x * 0.125f;
        sq[n][c2 * 2 + 1] = q.y * 0.125f;
        sk[n][c2 * 2]     = k.x;
        sk[n][c2 * 2 + 1] = k.y;
    }
    __syncthreads();

    int h = tid >> 5, lane = tid & 31;

#pragma unroll
    for (int r = 0; r < 3; r++) {
        int idx = r * 32 + lane;
        if (idx < 81) {
            int n = idx / 9, m = idx - n * 9;
            const float* qp = &sq[n][h * 64];
            const float* kp = &sk[m][h * 64];
            float s = 0.f;
#pragma unroll
            for (int d = 0; d < 64; d++) s = fmaf(qp[d], kp[d], s);
            int di = n / 3 - m / 3 + 2;
            int dj = n % 3 - m % 3 + 2;
            s += bias_table[(di * 5 + dj) * 8 + h];
            sp[h][idx] = s;
        }
    }
    __syncwarp();

    if (lane < 9) {
        float mx = -1e30f;
#pragma unroll
        for (int m = 0; m < 9; m++) mx = fmaxf(mx, sp[h][lane * 9 + m]);
        float e[9], sum = 0.f;
#pragma unroll
        for (int m = 0; m < 9; m++) { e[m] = __expf(sp[h][lane * 9 + m] - mx); sum += e[m]; }
        float inv = 1.f / sum;
#pragma unroll
        for (int m = 0; m < 9; m++) sp[h][lane * 9 + m] = e[m] * inv;
    }
    __syncwarp();

    float a0[9], a1[9];
#pragma unroll
    for (int n = 0; n < 9; n++) { a0[n] = 0.f; a1[n] = 0.f; }
#pragma unroll
    for (int m = 0; m < 9; m++) {
        size_t vb = base + (size_t)m * 1536 + 1024 + h * 64;
        float v0 = __bfloat162float(qkv[vb + lane]);
        float v1 = __bfloat162float(qkv[vb + 32 + lane]);
#pragma unroll
        for (int n = 0; n < 9; n++) {
            float p = sp[h][n * 9 + m];
            a0[n] = fmaf(p, v0, a0[n]);
            a1[n] = fmaf(p, v1, a1[n]);
        }
    }
#pragma unroll
    for (int n = 0; n < 9; n++) {
        size_t o = ((size_t)b * 9 + n) * 512 + h * 64;
        out[o + lane]      = __float2bfloat16_rn(a0[n]);
        out[o + 32 + lane] = __float2bfloat16_rn(a1[n]);
    }
}

// ---------------------------------------------------------------------------
// Depthwise 3x3 merge conv (fp32)
// ---------------------------------------------------------------------------
__global__ __launch_bounds__(256) void conv_kernel(
    const float* __restrict__ x, const float* __restrict__ w,
    const float* __restrict__ bc, float* __restrict__ out)
{
    int i = blockIdx.x * 256 + threadIdx.x;
    int c = i & 511;
    int b = i >> 9;
    float acc = bc[c];
    size_t base = (size_t)b * 9 * 512 + c;
#pragma unroll
    for (int n = 0; n < 9; n++)
        acc = fmaf(x[base + (size_t)n * 512], w[c * 9 + n], acc);
    out[i] = acc;
}

// ---------------------------------------------------------------------------
extern "C" void kernel_launch(void* const* d_in, const int* in_sizes, int n_in,
                              void* d_out, int out_size)
{
    const float* x          = (const float*)d_in[0];
    const float* gamma1     = (const float*)d_in[1];
    const float* beta1      = (const float*)d_in[2];
    const float* w_qkv      = (const float*)d_in[3];
    const float* b_qkv      = (const float*)d_in[4];
    const float* bias_table = (const float*)d_in[5];
    const float* w_proj     = (const float*)d_in[6];
    const float* b_proj     = (const float*)d_in[7];
    const float* gamma2     = (const float*)d_in[8];
    const float* beta2      = (const float*)d_in[9];
    const float* w_fc1      = (const float*)d_in[10];
    const float* b_fc1      = (const float*)d_in[11];
    const float* w_fc2      = (const float*)d_in[12];
    const float* b_fc2      = (const float*)d_in[13];
    const float* w_conv     = (const float*)d_in[14];
    const float* b_conv     = (const float*)d_in[15];
    float* out = (float*)d_out;

    bf16 *h, *qkv, *attn, *mlp, *wb;
    float *x1;
    cudaGetSymbolAddress((void**)&h,    g_h);
    cudaGetSymbolAddress((void**)&qkv,  g_qkv);
    cudaGetSymbolAddress((void**)&attn, g_attn);
    cudaGetSymbolAddress((void**)&x1,   g_x1);
    cudaGetSymbolAddress((void**)&mlp,  g_mlp);
    cudaGetSymbolAddress((void**)&wb,   g_wb);
    float* x2 = reinterpret_cast<float*>(qkv);   // reuse qkv buffer for x2 (fp32)

    cudaFuncSetAttribute(gemm_bf16_kernel<0, bf16>,
                         cudaFuncAttributeMaxDynamicSharedMemorySize, GSMEM);
    cudaFuncSetAttribute(gemm_bf16_kernel<1, bf16>,
                         cudaFuncAttributeMaxDynamicSharedMemorySize, GSMEM);
    cudaFuncSetAttribute(gemm_bf16_kernel<2, float>,
                         cudaFuncAttributeMaxDynamicSharedMemorySize, GSMEM);

    bf16* wq = wb;
    bf16* wp = wb + 786432;
    bf16* w1 = wb + 1048576;
    bf16* w2 = wb + 2097152;

    convw_kernel<<<768,  256>>>(w_qkv,  wq, 196608);
    convw_kernel<<<256,  256>>>(w_proj, wp, 65536);
    convw_kernel<<<1024, 256>>>(w_fc1,  w1, 262144);
    convw_kernel<<<1024, 256>>>(w_fc2,  w2, 262144);

    const int MB = MROWS / 128;   // 576 row tiles

    // LN1: x -> h (bf16)
    ln_kernel<<<MROWS / 8, dim3(32, 8)>>>(x, gamma1, beta1, h);
    // QKV: h @ wq^T + b_qkv -> qkv (bf16)
    gemm_bf16_kernel<0, bf16><<<dim3(12, MB), 256, GSMEM>>>(h, wq, b_qkv, nullptr, qkv, 1536, 512);
    // window attention -> attn (bf16)
    attn_kernel<<<8192, 256>>>(qkv, bias_table, attn);
    // proj + shortcut: attn @ wp^T + b_proj + x -> x1 (fp32)
    gemm_bf16_kernel<2, float><<<dim3(4, MB), 256, GSMEM>>>(attn, wp, b_proj, x, x1, 512, 512);
    // LN2: x1 -> h (bf16)
    ln_kernel<<<MROWS / 8, dim3(32, 8)>>>(x1, gamma2, beta2, h);
    // FC1 + GELU: h @ w1^T + b_fc1 -> mlp (bf16)
    gemm_bf16_kernel<1, bf16><<<dim3(16, MB), 256, GSMEM>>>(h, w1, b_fc1, nullptr, mlp, 2048, 512);
    // FC2 + residual: mlp @ w2^T + b_fc2 + x1 -> x2 (fp32, reuses qkv buffer)
    gemm_bf16_kernel<2, float><<<dim3(4, MB), 256, GSMEM>>>(mlp, w2, b_fc2, x1, x2, 512, 2048);
    // merge conv -> out
    conv_kernel<<<(8192 * 512) / 256, 256>>>(x2, w_conv, b_conv, out);
}

// round 9
// speedup vs baseline: 13.2886x; 1.1333x over previous
#include <cuda_runtime.h>
#include <cuda_bf16.h>
#include <math.h>
#include <stdint.h>

// ---------------------------------------------------------------------------
// TransformerBlock: B=8192, N=9, DIM=512, HEADS=8, HEAD_DIM=64
// Round 9: bf16 HMMA GEMMs, ldmatrix + XOR-swizzled smem (no padding),
// 6-stage cp.async ring, ONE __syncthreads per TWO k-tiles, 2 CTAs/SM.
// ---------------------------------------------------------------------------

#define MROWS (8192 * 9)   // 73728 token rows

typedef __nv_bfloat16  bf16;
typedef __nv_bfloat162 bf162;

// Scratch (allocation-free: static device globals)
__device__ __align__(16) bf16  g_h   [(size_t)MROWS * 512];   // LN out (bf16)
__device__ __align__(16) bf16  g_qkv [(size_t)MROWS * 1536];  // QKV (bf16); later fp32 x2
__device__ __align__(16) bf16  g_attn[(size_t)MROWS * 512];   // attn out (bf16)
__device__ __align__(16) float g_x1  [(size_t)MROWS * 512];   // residual after attn (fp32)
__device__ __align__(16) bf16  g_mlp [(size_t)MROWS * 2048];  // GELU(FC1) (bf16)
__device__ __align__(16) bf16  g_wb  [3145728];               // bf16 weights

__device__ __forceinline__ void cp16s(uint32_t s, const void* src) {
    asm volatile("cp.async.cg.shared.global [%0], [%1], 16;\n" :: "r"(s), "l"(src));
}
__device__ __forceinline__ void cp_commit() { asm volatile("cp.async.commit_group;\n"); }
template <int N> __device__ __forceinline__ void cp_wait() {
    asm volatile("cp.async.wait_group %0;\n" :: "n"(N));
}

__device__ __forceinline__ void mma_bf16(float4& d, const uint32_t a[4], const uint32_t b[2]) {
    asm volatile(
        "mma.sync.aligned.m16n8k16.row.col.f32.bf16.bf16.f32 "
        "{%0,%1,%2,%3}, {%4,%5,%6,%7}, {%8,%9}, {%0,%1,%2,%3};\n"
        : "+f"(d.x), "+f"(d.y), "+f"(d.z), "+f"(d.w)
        : "r"(a[0]), "r"(a[1]), "r"(a[2]), "r"(a[3]), "r"(b[0]), "r"(b[1]));
}
__device__ __forceinline__ void ldsm4(uint32_t& r0, uint32_t& r1, uint32_t& r2,
                                      uint32_t& r3, uint32_t addr) {
    asm volatile("ldmatrix.sync.aligned.m8n8.x4.shared.b16 {%0,%1,%2,%3}, [%4];"
                 : "=r"(r0), "=r"(r1), "=r"(r2), "=r"(r3) : "r"(addr));
}

// swizzled byte offset within one 128x32 bf16 stage-matrix (64B rows)
__device__ __forceinline__ uint32_t swz(int row, int kc) {
    return (uint32_t)(row * 64 + ((kc ^ ((row >> 1) & 3)) << 4));
}

// ---------------------------------------------------------------------------
// Convert fp32 weights -> bf16 (vectorized)
// ---------------------------------------------------------------------------
__global__ __launch_bounds__(256) void convw_kernel(
    const float* __restrict__ in, bf16* __restrict__ out, int n4)
{
    int i = blockIdx.x * 256 + threadIdx.x;
    if (i < n4) {
        float4 v = reinterpret_cast<const float4*>(in)[i];
        bf162* o = reinterpret_cast<bf162*>(out) + i * 2;
        o[0] = __floats2bfloat162_rn(v.x, v.y);
        o[1] = __floats2bfloat162_rn(v.z, v.w);
    }
}

// ---------------------------------------------------------------------------
// LayerNorm over last dim (512). One warp per row. fp32 in -> bf16 out.
// ---------------------------------------------------------------------------
__global__ __launch_bounds__(256) void ln_kernel(
    const float* __restrict__ x, const float* __restrict__ gam,
    const float* __restrict__ bet, bf16* __restrict__ out)
{
    int row  = blockIdx.x * 8 + threadIdx.y;
    int lane = threadIdx.x;
    const float4* xr = reinterpret_cast<const float4*>(x) + (size_t)row * 128;
    float4 v[4];
    float s = 0.f, s2 = 0.f;
#pragma unroll
    for (int i = 0; i < 4; i++) {
        v[i] = xr[lane + 32 * i];
        s  += v[i].x + v[i].y + v[i].z + v[i].w;
        s2 += v[i].x * v[i].x + v[i].y * v[i].y + v[i].z * v[i].z + v[i].w * v[i].w;
    }
#pragma unroll
    for (int o = 16; o; o >>= 1) {
        s  += __shfl_xor_sync(0xffffffffu, s,  o);
        s2 += __shfl_xor_sync(0xffffffffu, s2, o);
    }
    float mu   = s * (1.f / 512.f);
    float var  = s2 * (1.f / 512.f) - mu * mu;
    float rstd = rsqrtf(var + 1e-5f);
    bf162* orow = reinterpret_cast<bf162*>(out) + (size_t)row * 256;
    const float4* g4 = reinterpret_cast<const float4*>(gam);
    const float4* b4 = reinterpret_cast<const float4*>(bet);
#pragma unroll
    for (int i = 0; i < 4; i++) {
        int c = lane + 32 * i;
        float4 g = g4[c], b = b4[c];
        float o0 = (v[i].x - mu) * rstd * g.x + b.x;
        float o1 = (v[i].y - mu) * rstd * g.y + b.y;
        float o2 = (v[i].z - mu) * rstd * g.z + b.z;
        float o3 = (v[i].w - mu) * rstd * g.w + b.w;
        orow[2 * c]     = __floats2bfloat162_rn(o0, o1);
        orow[2 * c + 1] = __floats2bfloat162_rn(o2, o3);
    }
}

// ---------------------------------------------------------------------------
// bf16 HMMA GEMM: C[M,N] = A[M,K] @ Bw[N,K]^T + bias[N] (+ epilogue)
//   EP=0: none (bf16 out);  EP=1: exact GELU (bf16 out);  EP=2: +Res (fp32 out)
// 128x128x32 CTA tile, 8 warps (4Mx2N), warp = 32x64 via m16n8k16.
// ldmatrix.x4 on XOR-swizzled 64B rows; 6-stage cp.async ring; one sync
// per two k-tiles (stage written at pair p was consumed at pair p-1, which
// sync_p at loop top guarantees drained across all warps).
// ---------------------------------------------------------------------------
#define BK     32
#define TILEB  8192                  // bytes per 128x32 bf16 stage-matrix
#define STAGES 6
#define GSMEM  (STAGES * 2 * TILEB)  // 98304 bytes

__device__ __forceinline__ void store2(bf16* C, size_t off, float a, float b) {
    *reinterpret_cast<bf162*>(C + off) = __floats2bfloat162_rn(a, b);
}
__device__ __forceinline__ void store2(float* C, size_t off, float a, float b) {
    *reinterpret_cast<float2*>(C + off) = make_float2(a, b);
}

template <int EP, typename OutT>
__global__ __launch_bounds__(256, 2) void gemm_bf16_kernel(
    const bf16* __restrict__ A, const bf16* __restrict__ Bw,
    const float* __restrict__ bias, const float* __restrict__ Res,
    OutT* __restrict__ C, int N, int K)
{
    extern __shared__ char smem[];   // [A stages 0..5][B stages 0..5]
    uint32_t sbase = (uint32_t)__cvta_generic_to_shared(smem);

    int tid  = threadIdx.x;
    int bm   = blockIdx.y * 128, bn = blockIdx.x * 128;
    int warp = tid >> 5, lane = tid & 31;
    int warpM = warp >> 1, warpN = warp & 1;
    int lg = lane >> 2, lt = lane & 3;

    // ldmatrix lane->row/chunk mapping
    int aRow = warpM * 32 + ((lane >> 3) & 1) * 8 + (lane & 7);
    int aKc  = lane >> 4;            // 0/1 chunk within k-step
    int bRow = warpN * 64 + (lane >> 4) * 8 + (lane & 7);
    int bKc  = (lane >> 3) & 1;

    // loaders: 16B = 8 bf16 per cp; 64 rows x 4 chunks per pass, 2 passes
    int lrow = tid >> 2;           // 0..63
    int lchk = tid & 3;            // chunk 0..3 (8 bf16 each)
    const bf16* Ag = A  + (size_t)(bm + lrow) * K + lchk * 8;
    const bf16* Bg = Bw + (size_t)(bn + lrow) * K + lchk * 8;

    float4 acc[2][8];
#pragma unroll
    for (int mt = 0; mt < 2; mt++)
#pragma unroll
        for (int nt = 0; nt < 8; nt++) acc[mt][nt] = make_float4(0.f, 0.f, 0.f, 0.f);

    auto loadTile = [&](int stage, int kt) {
        uint32_t as = sbase + stage * TILEB;
        uint32_t bs = sbase + STAGES * TILEB + stage * TILEB;
#pragma unroll
        for (int p = 0; p < 2; p++) {
            int r = p * 64 + lrow;
            uint32_t off = swz(r, lchk);
            cp16s(as + off, Ag + (size_t)p * 64 * K + kt);
            cp16s(bs + off, Bg + (size_t)p * 64 * K + kt);
        }
        cp_commit();
    };

    auto compute = [&](int stage) {
        uint32_t aBase = sbase + stage * TILEB;
        uint32_t bBase = sbase + STAGES * TILEB + stage * TILEB;
#pragma unroll
        for (int ks = 0; ks < 2; ks++) {
            uint32_t a[2][4], b[8][2];
#pragma unroll
            for (int mt = 0; mt < 2; mt++) {
                int row = aRow + mt * 16;
                ldsm4(a[mt][0], a[mt][1], a[mt][2], a[mt][3],
                      aBase + swz(row, ks * 2 + aKc));
            }
#pragma unroll
            for (int np = 0; np < 4; np++) {
                int row = bRow + np * 16;
                ldsm4(b[2 * np][0], b[2 * np][1], b[2 * np + 1][0], b[2 * np + 1][1],
                      bBase + swz(row, ks * 2 + bKc));
            }
#pragma unroll
            for (int mt = 0; mt < 2; mt++)
#pragma unroll
                for (int nt = 0; nt < 8; nt++)
                    mma_bf16(acc[mt][nt], a[mt], b[nt]);
        }
    };

    int T = K >> 5;   // k-tiles (16 or 64; always even, >= 8)

    loadTile(0, 0);
    loadTile(1, BK);
    loadTile(2, 2 * BK);
    loadTile(3, 3 * BK);

    int s0 = 0;                 // stage of tile 2p
    int sl = 4;                 // stage of tile 2p+4
    for (int t0 = 0; t0 < T; t0 += 2) {
        __syncthreads();        // all warps done with pair p-1 -> stages reusable
        if (t0 + 4 < T) loadTile(sl, (t0 + 4) * BK); else cp_commit();
        int sl2 = sl + 1; if (sl2 >= STAGES) sl2 -= STAGES;
        if (t0 + 5 < T) loadTile(sl2, (t0 + 5) * BK); else cp_commit();
        cp_wait<4>();           // tiles t0, t0+1 resident (newest 4 may pend)

        compute(s0);
        int s1 = s0 + 1; if (s1 >= STAGES) s1 -= STAGES;
        compute(s1);

        s0 += 2; if (s0 >= STAGES) s0 -= STAGES;
        sl += 2; if (sl >= STAGES) sl -= STAGES;
    }

    // epilogue
#pragma unroll
    for (int mt = 0; mt < 2; mt++) {
        int row = bm + warpM * 32 + mt * 16 + lg;
#pragma unroll
        for (int nt = 0; nt < 8; nt++) {
            int col = bn + warpN * 64 + nt * 8 + lt * 2;
            float b0 = bias[col], b1 = bias[col + 1];
            float4 v = acc[mt][nt];
            float o00 = v.x + b0, o01 = v.y + b1;   // row
            float o10 = v.z + b0, o11 = v.w + b1;   // row+8
            if (EP == 1) {
                o00 = 0.5f * o00 * (1.f + erff(o00 * 0.70710678f));
                o01 = 0.5f * o01 * (1.f + erff(o01 * 0.70710678f));
                o10 = 0.5f * o10 * (1.f + erff(o10 * 0.70710678f));
                o11 = 0.5f * o11 * (1.f + erff(o11 * 0.70710678f));
            } else if (EP == 2) {
                const float2 r0 = *reinterpret_cast<const float2*>(Res + (size_t)row * N + col);
                const float2 r1 = *reinterpret_cast<const float2*>(Res + (size_t)(row + 8) * N + col);
                o00 += r0.x; o01 += r0.y; o10 += r1.x; o11 += r1.y;
            }
            store2(C, (size_t)row * N + col,       o00, o01);
            store2(C, (size_t)(row + 8) * N + col, o10, o11);
        }
    }
}

// ---------------------------------------------------------------------------
// Window attention (fp32 math). One CTA per window, 8 warps = 8 heads.
// ---------------------------------------------------------------------------
__global__ __launch_bounds__(256) void attn_kernel(
    const bf16* __restrict__ qkv, const float* __restrict__ bias_table,
    bf16* __restrict__ out)
{
    __shared__ float sq[9][520];
    __shared__ float sk[9][520];
    __shared__ float sp[8][81];
    int b   = blockIdx.x;
    int tid = threadIdx.x;
    size_t base = (size_t)b * 9 * 1536;

    for (int idx = tid; idx < 9 * 256; idx += 256) {
        int n = idx >> 8, c2 = idx & 255;
        float2 q = __bfloat1622float2(
            *reinterpret_cast<const bf162*>(qkv + base + (size_t)n * 1536 + c2 * 2));
        float2 k = __bfloat1622float2(
            *reinterpret_cast<const bf162*>(qkv + base + (size_t)n * 1536 + 512 + c2 * 2));
        sq[n][c2 * 2]     = q.x * 0.125f;
        sq[n][c2 * 2 + 1] = q.y * 0.125f;
        sk[n][c2 * 2]     = k.x;
        sk[n][c2 * 2 + 1] = k.y;
    }
    __syncthreads();

    int h = tid >> 5, lane = tid & 31;

#pragma unroll
    for (int r = 0; r < 3; r++) {
        int idx = r * 32 + lane;
        if (idx < 81) {
            int n = idx / 9, m = idx - n * 9;
            const float* qp = &sq[n][h * 64];
            const float* kp = &sk[m][h * 64];
            float s = 0.f;
#pragma unroll
            for (int d = 0; d < 64; d++) s = fmaf(qp[d], kp[d], s);
            int di = n / 3 - m / 3 + 2;
            int dj = n % 3 - m % 3 + 2;
            s += bias_table[(di * 5 + dj) * 8 + h];
            sp[h][idx] = s;
        }
    }
    __syncwarp();

    if (lane < 9) {
        float mx = -1e30f;
#pragma unroll
        for (int m = 0; m < 9; m++) mx = fmaxf(mx, sp[h][lane * 9 + m]);
        float e[9], sum = 0.f;
#pragma unroll
        for (int m = 0; m < 9; m++) { e[m] = __expf(sp[h][lane * 9 + m] - mx); sum += e[m]; }
        float inv = 1.f / sum;
#pragma unroll
        for (int m = 0; m < 9; m++) sp[h][lane * 9 + m] = e[m] * inv;
    }
    __syncwarp();

    float a0[9], a1[9];
#pragma unroll
    for (int n = 0; n < 9; n++) { a0[n] = 0.f; a1[n] = 0.f; }
#pragma unroll
    for (int m = 0; m < 9; m++) {
        size_t vb = base + (size_t)m * 1536 + 1024 + h * 64;
        float v0 = __bfloat162float(qkv[vb + lane]);
        float v1 = __bfloat162float(qkv[vb + 32 + lane]);
#pragma unroll
        for (int n = 0; n < 9; n++) {
            float p = sp[h][n * 9 + m];
            a0[n] = fmaf(p, v0, a0[n]);
            a1[n] = fmaf(p, v1, a1[n]);
        }
    }
#pragma unroll
    for (int n = 0; n < 9; n++) {
        size_t o = ((size_t)b * 9 + n) * 512 + h * 64;
        out[o + lane]      = __float2bfloat16_rn(a0[n]);
        out[o + 32 + lane] = __float2bfloat16_rn(a1[n]);
    }
}

// ---------------------------------------------------------------------------
// Depthwise 3x3 merge conv (fp32)
// ---------------------------------------------------------------------------
__global__ __launch_bounds__(256) void conv_kernel(
    const float* __restrict__ x, const float* __restrict__ w,
    const float* __restrict__ bc, float* __restrict__ out)
{
    int i = blockIdx.x * 256 + threadIdx.x;
    int c = i & 511;
    int b = i >> 9;
    float acc = bc[c];
    size_t base = (size_t)b * 9 * 512 + c;
#pragma unroll
    for (int n = 0; n < 9; n++)
        acc = fmaf(x[base + (size_t)n * 512], w[c * 9 + n], acc);
    out[i] = acc;
}

// ---------------------------------------------------------------------------
extern "C" void kernel_launch(void* const* d_in, const int* in_sizes, int n_in,
                              void* d_out, int out_size)
{
    const float* x          = (const float*)d_in[0];
    const float* gamma1     = (const float*)d_in[1];
    const float* beta1      = (const float*)d_in[2];
    const float* w_qkv      = (const float*)d_in[3];
    const float* b_qkv      = (const float*)d_in[4];
    const float* bias_table = (const float*)d_in[5];
    const float* w_proj     = (const float*)d_in[6];
    const float* b_proj     = (const float*)d_in[7];
    const float* gamma2     = (const float*)d_in[8];
    const float* beta2      = (const float*)d_in[9];
    const float* w_fc1      = (const float*)d_in[10];
    const float* b_fc1      = (const float*)d_in[11];
    const float* w_fc2      = (const float*)d_in[12];
    const float* b_fc2      = (const float*)d_in[13];
    const float* w_conv     = (const float*)d_in[14];
    const float* b_conv     = (const float*)d_in[15];
    float* out = (float*)d_out;

    bf16 *h, *qkv, *attn, *mlp, *wb;
    float *x1;
    cudaGetSymbolAddress((void**)&h,    g_h);
    cudaGetSymbolAddress((void**)&qkv,  g_qkv);
    cudaGetSymbolAddress((void**)&attn, g_attn);
    cudaGetSymbolAddress((void**)&x1,   g_x1);
    cudaGetSymbolAddress((void**)&mlp,  g_mlp);
    cudaGetSymbolAddress((void**)&wb,   g_wb);
    float* x2 = reinterpret_cast<float*>(qkv);   // reuse qkv buffer for x2 (fp32)

    cudaFuncSetAttribute(gemm_bf16_kernel<0, bf16>,
                         cudaFuncAttributeMaxDynamicSharedMemorySize, GSMEM);
    cudaFuncSetAttribute(gemm_bf16_kernel<1, bf16>,
                         cudaFuncAttributeMaxDynamicSharedMemorySize, GSMEM);
    cudaFuncSetAttribute(gemm_bf16_kernel<2, float>,
                         cudaFuncAttributeMaxDynamicSharedMemorySize, GSMEM);

    bf16* wq = wb;
    bf16* wp = wb + 786432;
    bf16* w1 = wb + 1048576;
    bf16* w2 = wb + 2097152;

    convw_kernel<<<768,  256>>>(w_qkv,  wq, 196608);
    convw_kernel<<<256,  256>>>(w_proj, wp, 65536);
    convw_kernel<<<1024, 256>>>(w_fc1,  w1, 262144);
    convw_kernel<<<1024, 256>>>(w_fc2,  w2, 262144);

    const int MB = MROWS / 128;   // 576 row tiles

    // LN1: x -> h (bf16)
    ln_kernel<<<MROWS / 8, dim3(32, 8)>>>(x, gamma1, beta1, h);
    // QKV: h @ wq^T + b_qkv -> qkv (bf16)
    gemm_bf16_kernel<0, bf16><<<dim3(12, MB), 256, GSMEM>>>(h, wq, b_qkv, nullptr, qkv, 1536, 512);
    // window attention -> attn (bf16)
    attn_kernel<<<8192, 256>>>(qkv, bias_table, attn);
    // proj + shortcut: attn @ wp^T + b_proj + x -> x1 (fp32)
    gemm_bf16_kernel<2, float><<<dim3(4, MB), 256, GSMEM>>>(attn, wp, b_proj, x, x1, 512, 512);
    // LN2: x1 -> h (bf16)
    ln_kernel<<<MROWS / 8, dim3(32, 8)>>>(x1, gamma2, beta2, h);
    // FC1 + GELU: h @ w1^T + b_fc1 -> mlp (bf16)
    gemm_bf16_kernel<1, bf16><<<dim3(16, MB), 256, GSMEM>>>(h, w1, b_fc1, nullptr, mlp, 2048, 512);
    // FC2 + residual: mlp @ w2^T + b_fc2 + x1 -> x2 (fp32, reuses qkv buffer)
    gemm_bf16_kernel<2, float><<<dim3(4, MB), 256, GSMEM>>>(mlp, w2, b_fc2, x1, x2, 512, 2048);
    // merge conv -> out
    conv_kernel<<<(8192 * 512) / 256, 256>>>(x2, w_conv, b_conv, out);
}

// round 11
// speedup vs baseline: 13.7077x; 1.0315x over previous
#include <cuda_runtime.h>
#include <cuda_bf16.h>
#include <math.h>
#include <stdint.h>

// ---------------------------------------------------------------------------
// TransformerBlock: B=8192, N=9, DIM=512, HEADS=8, HEAD_DIM=64
// Round 11: race-fixed pair loop (wait -> sync -> compute -> prefetch),
// 6-stage ring, 1 sync / 2 k-tiles, 2 CTAs/SM. attn float4 + merged convw.
// ---------------------------------------------------------------------------

#define MROWS (8192 * 9)   // 73728 token rows

typedef __nv_bfloat16  bf16;
typedef __nv_bfloat162 bf162;

// Scratch (allocation-free: static device globals)
__device__ __align__(16) bf16  g_h   [(size_t)MROWS * 512];   // LN out (bf16)
__device__ __align__(16) bf16  g_qkv [(size_t)MROWS * 1536];  // QKV (bf16); later fp32 x2
__device__ __align__(16) bf16  g_attn[(size_t)MROWS * 512];   // attn out (bf16)
__device__ __align__(16) float g_x1  [(size_t)MROWS * 512];   // residual after attn (fp32)
__device__ __align__(16) bf16  g_mlp [(size_t)MROWS * 2048];  // GELU(FC1) (bf16)
__device__ __align__(16) bf16  g_wb  [3145728];               // bf16 weights (contiguous)

__device__ __forceinline__ void cp16s(uint32_t s, const void* src) {
    asm volatile("cp.async.cg.shared.global [%0], [%1], 16;\n" :: "r"(s), "l"(src));
}
__device__ __forceinline__ void cp_commit() { asm volatile("cp.async.commit_group;\n"); }
template <int N> __device__ __forceinline__ void cp_wait() {
    asm volatile("cp.async.wait_group %0;\n" :: "n"(N));
}

__device__ __forceinline__ void mma_bf16(float4& d, const uint32_t a[4], const uint32_t b[2]) {
    asm volatile(
        "mma.sync.aligned.m16n8k16.row.col.f32.bf16.bf16.f32 "
        "{%0,%1,%2,%3}, {%4,%5,%6,%7}, {%8,%9}, {%0,%1,%2,%3};\n"
        : "+f"(d.x), "+f"(d.y), "+f"(d.z), "+f"(d.w)
        : "r"(a[0]), "r"(a[1]), "r"(a[2]), "r"(a[3]), "r"(b[0]), "r"(b[1]));
}
__device__ __forceinline__ void ldsm4(uint32_t& r0, uint32_t& r1, uint32_t& r2,
                                      uint32_t& r3, uint32_t addr) {
    asm volatile("ldmatrix.sync.aligned.m8n8.x4.shared.b16 {%0,%1,%2,%3}, [%4];"
                 : "=r"(r0), "=r"(r1), "=r"(r2), "=r"(r3) : "r"(addr));
}

// swizzled byte offset within one 128x32 bf16 stage-matrix (64B rows)
__device__ __forceinline__ uint32_t swz(int row, int kc) {
    return (uint32_t)(row * 64 + ((kc ^ ((row >> 1) & 3)) << 4));
}

// ---------------------------------------------------------------------------
// Convert all 4 fp32 weight matrices -> bf16 in one launch.
// ---------------------------------------------------------------------------
__global__ __launch_bounds__(256) void convw4_kernel(
    const float* __restrict__ wq, const float* __restrict__ wp,
    const float* __restrict__ w1, const float* __restrict__ w2,
    bf16* __restrict__ out)
{
    int i = blockIdx.x * 256 + threadIdx.x;   // 0 .. 786431 (float4 index)
    const float4* src;
    int local;
    if (i < 196608)      { src = (const float4*)wq; local = i; }
    else if (i < 262144) { src = (const float4*)wp; local = i - 196608; }
    else if (i < 524288) { src = (const float4*)w1; local = i - 262144; }
    else                 { src = (const float4*)w2; local = i - 524288; }
    float4 v = src[local];
    bf162* o = reinterpret_cast<bf162*>(out) + i * 2;
    o[0] = __floats2bfloat162_rn(v.x, v.y);
    o[1] = __floats2bfloat162_rn(v.z, v.w);
}

// ---------------------------------------------------------------------------
// LayerNorm over last dim (512). One warp per row. fp32 in -> bf16 out.
// ---------------------------------------------------------------------------
__global__ __launch_bounds__(256) void ln_kernel(
    const float* __restrict__ x, const float* __restrict__ gam,
    const float* __restrict__ bet, bf16* __restrict__ out)
{
    int row  = blockIdx.x * 8 + threadIdx.y;
    int lane = threadIdx.x;
    const float4* xr = reinterpret_cast<const float4*>(x) + (size_t)row * 128;
    float4 v[4];
    float s = 0.f, s2 = 0.f;
#pragma unroll
    for (int i = 0; i < 4; i++) {
        v[i] = xr[lane + 32 * i];
        s  += v[i].x + v[i].y + v[i].z + v[i].w;
        s2 += v[i].x * v[i].x + v[i].y * v[i].y + v[i].z * v[i].z + v[i].w * v[i].w;
    }
#pragma unroll
    for (int o = 16; o; o >>= 1) {
        s  += __shfl_xor_sync(0xffffffffu, s,  o);
        s2 += __shfl_xor_sync(0xffffffffu, s2, o);
    }
    float mu   = s * (1.f / 512.f);
    float var  = s2 * (1.f / 512.f) - mu * mu;
    float rstd = rsqrtf(var + 1e-5f);
    bf162* orow = reinterpret_cast<bf162*>(out) + (size_t)row * 256;
    const float4* g4 = reinterpret_cast<const float4*>(gam);
    const float4* b4 = reinterpret_cast<const float4*>(bet);
#pragma unroll
    for (int i = 0; i < 4; i++) {
        int c = lane + 32 * i;
        float4 g = g4[c], b = b4[c];
        float o0 = (v[i].x - mu) * rstd * g.x + b.x;
        float o1 = (v[i].y - mu) * rstd * g.y + b.y;
        float o2 = (v[i].z - mu) * rstd * g.z + b.z;
        float o3 = (v[i].w - mu) * rstd * g.w + b.w;
        orow[2 * c]     = __floats2bfloat162_rn(o0, o1);
        orow[2 * c + 1] = __floats2bfloat162_rn(o2, o3);
    }
}

// ---------------------------------------------------------------------------
// bf16 HMMA GEMM: C[M,N] = A[M,K] @ Bw[N,K]^T + bias[N] (+ epilogue)
//   EP=0: none (bf16 out);  EP=1: exact GELU (bf16 out);  EP=2: +Res (fp32 out)
// 128x128x32 CTA tile, 8 warps (4Mx2N), warp = 32x64 via m16n8k16.
// ldmatrix.x4 on XOR-swizzled 64B rows; 6-stage cp.async ring.
// SOUND pair loop: cp_wait<2> -> __syncthreads -> compute both tiles ->
// prefetch tiles t0+4,t0+5. Visibility: every thread waits before the sync,
// then reads. Overwrite: pair p's loads touch stages consumed at pair p-1,
// and pair p's sync follows pair p-1's compute in every warp's program order.
// ---------------------------------------------------------------------------
#define BK     32
#define TILEB  8192                  // bytes per 128x32 bf16 stage-matrix
#define STAGES 6
#define GSMEM  (STAGES * 2 * TILEB)  // 98304 bytes

__device__ __forceinline__ void store2(bf16* C, size_t off, float a, float b) {
    *reinterpret_cast<bf162*>(C + off) = __floats2bfloat162_rn(a, b);
}
__device__ __forceinline__ void store2(float* C, size_t off, float a, float b) {
    *reinterpret_cast<float2*>(C + off) = make_float2(a, b);
}

template <int EP, typename OutT>
__global__ __launch_bounds__(256, 2) void gemm_bf16_kernel(
    const bf16* __restrict__ A, const bf16* __restrict__ Bw,
    const float* __restrict__ bias, const float* __restrict__ Res,
    OutT* __restrict__ C, int N, int K)
{
    extern __shared__ char smem[];   // [A stages 0..5][B stages 0..5]
    uint32_t sbase = (uint32_t)__cvta_generic_to_shared(smem);

    int tid  = threadIdx.x;
    int bm   = blockIdx.y * 128, bn = blockIdx.x * 128;
    int warp = tid >> 5, lane = tid & 31;
    int warpM = warp >> 1, warpN = warp & 1;
    int lg = lane >> 2, lt = lane & 3;

    // ldmatrix lane->row/chunk mapping
    int aRow = warpM * 32 + ((lane >> 3) & 1) * 8 + (lane & 7);
    int aKc  = lane >> 4;            // 0/1 chunk within k-step
    int bRow = warpN * 64 + (lane >> 4) * 8 + (lane & 7);
    int bKc  = (lane >> 3) & 1;

    // loaders: 16B = 8 bf16 per cp; 64 rows x 4 chunks per pass, 2 passes
    int lrow = tid >> 2;           // 0..63
    int lchk = tid & 3;            // chunk 0..3 (8 bf16 each)
    const bf16* Ag = A  + (size_t)(bm + lrow) * K + lchk * 8;
    const bf16* Bg = Bw + (size_t)(bn + lrow) * K + lchk * 8;

    float4 acc[2][8];
#pragma unroll
    for (int mt = 0; mt < 2; mt++)
#pragma unroll
        for (int nt = 0; nt < 8; nt++) acc[mt][nt] = make_float4(0.f, 0.f, 0.f, 0.f);

    auto loadTile = [&](int stage, int kt) {
        uint32_t as = sbase + stage * TILEB;
        uint32_t bs = sbase + STAGES * TILEB + stage * TILEB;
#pragma unroll
        for (int p = 0; p < 2; p++) {
            int r = p * 64 + lrow;
            uint32_t off = swz(r, lchk);
            cp16s(as + off, Ag + (size_t)p * 64 * K + kt);
            cp16s(bs + off, Bg + (size_t)p * 64 * K + kt);
        }
        cp_commit();
    };

    auto compute = [&](int stage) {
        uint32_t aBase = sbase + stage * TILEB;
        uint32_t bBase = sbase + STAGES * TILEB + stage * TILEB;
#pragma unroll
        for (int ks = 0; ks < 2; ks++) {
            uint32_t a[2][4], b[8][2];
#pragma unroll
            for (int mt = 0; mt < 2; mt++) {
                int row = aRow + mt * 16;
                ldsm4(a[mt][0], a[mt][1], a[mt][2], a[mt][3],
                      aBase + swz(row, ks * 2 + aKc));
            }
#pragma unroll
            for (int np = 0; np < 4; np++) {
                int row = bRow + np * 16;
                ldsm4(b[2 * np][0], b[2 * np][1], b[2 * np + 1][0], b[2 * np + 1][1],
                      bBase + swz(row, ks * 2 + bKc));
            }
#pragma unroll
            for (int mt = 0; mt < 2; mt++)
#pragma unroll
                for (int nt = 0; nt < 8; nt++)
                    mma_bf16(acc[mt][nt], a[mt], b[nt]);
        }
    };

    int T = K >> 5;   // k-tiles (16 or 64; always even, >= 8)

    loadTile(0, 0);
    loadTile(1, BK);
    loadTile(2, 2 * BK);
    loadTile(3, 3 * BK);

    int s0 = 0;                 // stage of tile t0
    int sl = 4;                 // stage of tile t0+4
    for (int t0 = 0; t0 < T; t0 += 2) {
        cp_wait<2>();           // tiles <= t0+1 complete (this thread's groups)
        __syncthreads();        // visibility for all threads + overwrite guard

        compute(s0);
        int s1 = s0 + 1; if (s1 >= STAGES) s1 -= STAGES;
        compute(s1);

        if (t0 + 4 < T) loadTile(sl, (t0 + 4) * BK); else cp_commit();
        int sl2 = sl + 1; if (sl2 >= STAGES) sl2 -= STAGES;
        if (t0 + 5 < T) loadTile(sl2, (t0 + 5) * BK); else cp_commit();

        s0 += 2; if (s0 >= STAGES) s0 -= STAGES;
        sl += 2; if (sl >= STAGES) sl -= STAGES;
    }

    // epilogue
#pragma unroll
    for (int mt = 0; mt < 2; mt++) {
        int row = bm + warpM * 32 + mt * 16 + lg;
#pragma unroll
        for (int nt = 0; nt < 8; nt++) {
            int col = bn + warpN * 64 + nt * 8 + lt * 2;
            float b0 = bias[col], b1 = bias[col + 1];
            float4 v = acc[mt][nt];
            float o00 = v.x + b0, o01 = v.y + b1;   // row
            float o10 = v.z + b0, o11 = v.w + b1;   // row+8
            if (EP == 1) {
                o00 = 0.5f * o00 * (1.f + erff(o00 * 0.70710678f));
                o01 = 0.5f * o01 * (1.f + erff(o01 * 0.70710678f));
                o10 = 0.5f * o10 * (1.f + erff(o10 * 0.70710678f));
                o11 = 0.5f * o11 * (1.f + erff(o11 * 0.70710678f));
            } else if (EP == 2) {
                const float2 r0 = *reinterpret_cast<const float2*>(Res + (size_t)row * N + col);
                const float2 r1 = *reinterpret_cast<const float2*>(Res + (size_t)(row + 8) * N + col);
                o00 += r0.x; o01 += r0.y; o10 += r1.x; o11 += r1.y;
            }
            store2(C, (size_t)row * N + col,       o00, o01);
            store2(C, (size_t)(row + 8) * N + col, o10, o11);
        }
    }
}

// ---------------------------------------------------------------------------
// Window attention (fp32 math). One CTA per window, 8 warps = 8 heads.
// QK^T uses float4 LDS (same fmaf order as scalar -> identical numerics).
// ---------------------------------------------------------------------------
__global__ __launch_bounds__(256) void attn_kernel(
    const bf16* __restrict__ qkv, const float* __restrict__ bias_table,
    bf16* __restrict__ out)
{
    __shared__ float sq[9][520];
    __shared__ float sk[9][520];
    __shared__ float sp[8][81];
    int b   = blockIdx.x;
    int tid = threadIdx.x;
    size_t base = (size_t)b * 9 * 1536;

    for (int idx = tid; idx < 9 * 256; idx += 256) {
        int n = idx >> 8, c2 = idx & 255;
        float2 q = __bfloat1622float2(
            *reinterpret_cast<const bf162*>(qkv + base + (size_t)n * 1536 + c2 * 2));
        float2 k = __bfloat1622float2(
            *reinterpret_cast<const bf162*>(qkv + base + (size_t)n * 1536 + 512 + c2 * 2));
        sq[n][c2 * 2]     = q.x * 0.125f;
        sq[n][c2 * 2 + 1] = q.y * 0.125f;
        sk[n][c2 * 2]     = k.x;
        sk[n][c2 * 2 + 1] = k.y;
    }
    __syncthreads();

    int h = tid >> 5, lane = tid & 31;

#pragma unroll
    for (int r = 0; r < 3; r++) {
        int idx = r * 32 + lane;
        if (idx < 81) {
            int n = idx / 9, m = idx - n * 9;
            const float4* qp = reinterpret_cast<const float4*>(&sq[n][h * 64]);
            const float4* kp = reinterpret_cast<const float4*>(&sk[m][h * 64]);
            float s = 0.f;
#pragma unroll
            for (int d4 = 0; d4 < 16; d4++) {
                float4 qv = qp[d4], kv = kp[d4];
                s = fmaf(qv.x, kv.x, s);
                s = fmaf(qv.y, kv.y, s);
                s = fmaf(qv.z, kv.z, s);
                s = fmaf(qv.w, kv.w, s);
            }
            int di = n / 3 - m / 3 + 2;
            int dj = n % 3 - m % 3 + 2;
            s += bias_table[(di * 5 + dj) * 8 + h];
            sp[h][idx] = s;
        }
    }
    __syncwarp();

    if (lane < 9) {
        float mx = -1e30f;
#pragma unroll
        for (int m = 0; m < 9; m++) mx = fmaxf(mx, sp[h][lane * 9 + m]);
        float e[9], sum = 0.f;
#pragma unroll
        for (int m = 0; m < 9; m++) { e[m] = __expf(sp[h][lane * 9 + m] - mx); sum += e[m]; }
        float inv = 1.f / sum;
#pragma unroll
        for (int m = 0; m < 9; m++) sp[h][lane * 9 + m] = e[m] * inv;
    }
    __syncwarp();

    float a0[9], a1[9];
#pragma unroll
    for (int n = 0; n < 9; n++) { a0[n] = 0.f; a1[n] = 0.f; }
#pragma unroll
    for (int m = 0; m < 9; m++) {
        size_t vb = base + (size_t)m * 1536 + 1024 + h * 64;
        float v0 = __bfloat162float(qkv[vb + lane]);
        float v1 = __bfloat162float(qkv[vb + 32 + lane]);
#pragma unroll
        for (int n = 0; n < 9; n++) {
            float p = sp[h][n * 9 + m];
            a0[n] = fmaf(p, v0, a0[n]);
            a1[n] = fmaf(p, v1, a1[n]);
        }
    }
#pragma unroll
    for (int n = 0; n < 9; n++) {
        size_t o = ((size_t)b * 9 + n) * 512 + h * 64;
        out[o + lane]      = __float2bfloat16_rn(a0[n]);
        out[o + 32 + lane] = __float2bfloat16_rn(a1[n]);
    }
}

// ---------------------------------------------------------------------------
// Depthwise 3x3 merge conv (fp32)
// ---------------------------------------------------------------------------
__global__ __launch_bounds__(256) void conv_kernel(
    const float* __restrict__ x, const float* __restrict__ w,
    const float* __restrict__ bc, float* __restrict__ out)
{
    int i = blockIdx.x * 256 + threadIdx.x;
    int c = i & 511;
    int b = i >> 9;
    float acc = bc[c];
    size_t base = (size_t)b * 9 * 512 + c;
#pragma unroll
    for (int n = 0; n < 9; n++)
        acc = fmaf(x[base + (size_t)n * 512], w[c * 9 + n], acc);
    out[i] = acc;
}

// ---------------------------------------------------------------------------
extern "C" void kernel_launch(void* const* d_in, const int* in_sizes, int n_in,
                              void* d_out, int out_size)
{
    const float* x          = (const float*)d_in[0];
    const float* gamma1     = (const float*)d_in[1];
    const float* beta1      = (const float*)d_in[2];
    const float* w_qkv      = (const float*)d_in[3];
    const float* b_qkv      = (const float*)d_in[4];
    const float* bias_table = (const float*)d_in[5];
    const float* w_proj     = (const float*)d_in[6];
    const float* b_proj     = (const float*)d_in[7];
    const float* gamma2     = (const float*)d_in[8];
    const float* beta2      = (const float*)d_in[9];
    const float* w_fc1      = (const float*)d_in[10];
    const float* b_fc1      = (const float*)d_in[11];
    const float* w_fc2      = (const float*)d_in[12];
    const float* b_fc2      = (const float*)d_in[13];
    const float* w_conv     = (const float*)d_in[14];
    const float* b_conv     = (const float*)d_in[15];
    float* out = (float*)d_out;

    bf16 *h, *qkv, *attn, *mlp, *wb;
    float *x1;
    cudaGetSymbolAddress((void**)&h,    g_h);
    cudaGetSymbolAddress((void**)&qkv,  g_qkv);
    cudaGetSymbolAddress((void**)&attn, g_attn);
    cudaGetSymbolAddress((void**)&x1,   g_x1);
    cudaGetSymbolAddress((void**)&mlp,  g_mlp);
    cudaGetSymbolAddress((void**)&wb,   g_wb);
    float* x2 = reinterpret_cast<float*>(qkv);   // reuse qkv buffer for x2 (fp32)

    cudaFuncSetAttribute(gemm_bf16_kernel<0, bf16>,
                         cudaFuncAttributeMaxDynamicSharedMemorySize, GSMEM);
    cudaFuncSetAttribute(gemm_bf16_kernel<1, bf16>,
                         cudaFuncAttributeMaxDynamicSharedMemorySize, GSMEM);
    cudaFuncSetAttribute(gemm_bf16_kernel<2, float>,
                         cudaFuncAttributeMaxDynamicSharedMemorySize, GSMEM);

    bf16* wq = wb;
    bf16* wp = wb + 786432;
    bf16* w1 = wb + 1048576;
    bf16* w2 = wb + 2097152;

    // all weight conversions in one launch (regions contiguous in g_wb)
    convw4_kernel<<<3072, 256>>>(w_qkv, w_proj, w_fc1, w_fc2, wb);

    const int MB = MROWS / 128;   // 576 row tiles

    // LN1: x -> h (bf16)
    ln_kernel<<<MROWS / 8, dim3(32, 8)>>>(x, gamma1, beta1, h);
    // QKV: h @ wq^T + b_qkv -> qkv (bf16)
    gemm_bf16_kernel<0, bf16><<<dim3(12, MB), 256, GSMEM>>>(h, wq, b_qkv, nullptr, qkv, 1536, 512);
    // window attention -> attn (bf16)
    attn_kernel<<<8192, 256>>>(qkv, bias_table, attn);
    // proj + shortcut: attn @ wp^T + b_proj + x -> x1 (fp32)
    gemm_bf16_kernel<2, float><<<dim3(4, MB), 256, GSMEM>>>(attn, wp, b_proj, x, x1, 512, 512);
    // LN2: x1 -> h (bf16)
    ln_kernel<<<MROWS / 8, dim3(32, 8)>>>(x1, gamma2, beta2, h);
    // FC1 + GELU: h @ w1^T + b_fc1 -> mlp (bf16)
    gemm_bf16_kernel<1, bf16><<<dim3(16, MB), 256, GSMEM>>>(h, w1, b_fc1, nullptr, mlp, 2048, 512);
    // FC2 + residual: mlp @ w2^T + b_fc2 + x1 -> x2 (fp32, reuses qkv buffer)
    gemm_bf16_kernel<2, float><<<dim3(4, MB), 256, GSMEM>>>(mlp, w2, b_fc2, x1, x2, 512, 2048);
    // merge conv -> out
    conv_kernel<<<(8192 * 512) / 256, 256>>>(x2, w_conv, b_conv, out);
}

// round 12
// speedup vs baseline: 14.5903x; 1.0644x over previous
#include <cuda_runtime.h>
#include <cuda_bf16.h>
#include <math.h>
#include <stdint.h>

// ---------------------------------------------------------------------------
// TransformerBlock: B=8192, N=9, DIM=512, HEADS=8, HEAD_DIM=64
// Round 12: R11 GEMM unchanged; attention rebuilt with bf16 smem staging,
// conflict-free lane mapping, vectorized P@V. Bit-identical math.
// ---------------------------------------------------------------------------

#define MROWS (8192 * 9)   // 73728 token rows

typedef __nv_bfloat16  bf16;
typedef __nv_bfloat162 bf162;

// Scratch (allocation-free: static device globals)
__device__ __align__(16) bf16  g_h   [(size_t)MROWS * 512];   // LN out (bf16)
__device__ __align__(16) bf16  g_qkv [(size_t)MROWS * 1536];  // QKV (bf16); later fp32 x2
__device__ __align__(16) bf16  g_attn[(size_t)MROWS * 512];   // attn out (bf16)
__device__ __align__(16) float g_x1  [(size_t)MROWS * 512];   // residual after attn (fp32)
__device__ __align__(16) bf16  g_mlp [(size_t)MROWS * 2048];  // GELU(FC1) (bf16)
__device__ __align__(16) bf16  g_wb  [3145728];               // bf16 weights (contiguous)

__device__ __forceinline__ void cp16s(uint32_t s, const void* src) {
    asm volatile("cp.async.cg.shared.global [%0], [%1], 16;\n" :: "r"(s), "l"(src));
}
__device__ __forceinline__ void cp_commit() { asm volatile("cp.async.commit_group;\n"); }
template <int N> __device__ __forceinline__ void cp_wait() {
    asm volatile("cp.async.wait_group %0;\n" :: "n"(N));
}

__device__ __forceinline__ void mma_bf16(float4& d, const uint32_t a[4], const uint32_t b[2]) {
    asm volatile(
        "mma.sync.aligned.m16n8k16.row.col.f32.bf16.bf16.f32 "
        "{%0,%1,%2,%3}, {%4,%5,%6,%7}, {%8,%9}, {%0,%1,%2,%3};\n"
        : "+f"(d.x), "+f"(d.y), "+f"(d.z), "+f"(d.w)
        : "r"(a[0]), "r"(a[1]), "r"(a[2]), "r"(a[3]), "r"(b[0]), "r"(b[1]));
}
__device__ __forceinline__ void ldsm4(uint32_t& r0, uint32_t& r1, uint32_t& r2,
                                      uint32_t& r3, uint32_t addr) {
    asm volatile("ldmatrix.sync.aligned.m8n8.x4.shared.b16 {%0,%1,%2,%3}, [%4];"
                 : "=r"(r0), "=r"(r1), "=r"(r2), "=r"(r3) : "r"(addr));
}

// swizzled byte offset within one 128x32 bf16 stage-matrix (64B rows)
__device__ __forceinline__ uint32_t swz(int row, int kc) {
    return (uint32_t)(row * 64 + ((kc ^ ((row >> 1) & 3)) << 4));
}

// ---------------------------------------------------------------------------
// Convert all 4 fp32 weight matrices -> bf16 in one launch.
// ---------------------------------------------------------------------------
__global__ __launch_bounds__(256) void convw4_kernel(
    const float* __restrict__ wq, const float* __restrict__ wp,
    const float* __restrict__ w1, const float* __restrict__ w2,
    bf16* __restrict__ out)
{
    int i = blockIdx.x * 256 + threadIdx.x;   // 0 .. 786431 (float4 index)
    const float4* src;
    int local;
    if (i < 196608)      { src = (const float4*)wq; local = i; }
    else if (i < 262144) { src = (const float4*)wp; local = i - 196608; }
    else if (i < 524288) { src = (const float4*)w1; local = i - 262144; }
    else                 { src = (const float4*)w2; local = i - 524288; }
    float4 v = src[local];
    bf162* o = reinterpret_cast<bf162*>(out) + i * 2;
    o[0] = __floats2bfloat162_rn(v.x, v.y);
    o[1] = __floats2bfloat162_rn(v.z, v.w);
}

// ---------------------------------------------------------------------------
// LayerNorm over last dim (512). One warp per row. fp32 in -> bf16 out.
// ---------------------------------------------------------------------------
__global__ __launch_bounds__(256) void ln_kernel(
    const float* __restrict__ x, const float* __restrict__ gam,
    const float* __restrict__ bet, bf16* __restrict__ out)
{
    int row  = blockIdx.x * 8 + threadIdx.y;
    int lane = threadIdx.x;
    const float4* xr = reinterpret_cast<const float4*>(x) + (size_t)row * 128;
    float4 v[4];
    float s = 0.f, s2 = 0.f;
#pragma unroll
    for (int i = 0; i < 4; i++) {
        v[i] = xr[lane + 32 * i];
        s  += v[i].x + v[i].y + v[i].z + v[i].w;
        s2 += v[i].x * v[i].x + v[i].y * v[i].y + v[i].z * v[i].z + v[i].w * v[i].w;
    }
#pragma unroll
    for (int o = 16; o; o >>= 1) {
        s  += __shfl_xor_sync(0xffffffffu, s,  o);
        s2 += __shfl_xor_sync(0xffffffffu, s2, o);
    }
    float mu   = s * (1.f / 512.f);
    float var  = s2 * (1.f / 512.f) - mu * mu;
    float rstd = rsqrtf(var + 1e-5f);
    bf162* orow = reinterpret_cast<bf162*>(out) + (size_t)row * 256;
    const float4* g4 = reinterpret_cast<const float4*>(gam);
    const float4* b4 = reinterpret_cast<const float4*>(bet);
#pragma unroll
    for (int i = 0; i < 4; i++) {
        int c = lane + 32 * i;
        float4 g = g4[c], b = b4[c];
        float o0 = (v[i].x - mu) * rstd * g.x + b.x;
        float o1 = (v[i].y - mu) * rstd * g.y + b.y;
        float o2 = (v[i].z - mu) * rstd * g.z + b.z;
        float o3 = (v[i].w - mu) * rstd * g.w + b.w;
        orow[2 * c]     = __floats2bfloat162_rn(o0, o1);
        orow[2 * c + 1] = __floats2bfloat162_rn(o2, o3);
    }
}

// ---------------------------------------------------------------------------
// bf16 HMMA GEMM (unchanged from R11 — validated).
// ---------------------------------------------------------------------------
#define BK     32
#define TILEB  8192                  // bytes per 128x32 bf16 stage-matrix
#define STAGES 6
#define GSMEM  (STAGES * 2 * TILEB)  // 98304 bytes

__device__ __forceinline__ void store2(bf16* C, size_t off, float a, float b) {
    *reinterpret_cast<bf162*>(C + off) = __floats2bfloat162_rn(a, b);
}
__device__ __forceinline__ void store2(float* C, size_t off, float a, float b) {
    *reinterpret_cast<float2*>(C + off) = make_float2(a, b);
}

template <int EP, typename OutT>
__global__ __launch_bounds__(256, 2) void gemm_bf16_kernel(
    const bf16* __restrict__ A, const bf16* __restrict__ Bw,
    const float* __restrict__ bias, const float* __restrict__ Res,
    OutT* __restrict__ C, int N, int K)
{
    extern __shared__ char smem[];   // [A stages 0..5][B stages 0..5]
    uint32_t sbase = (uint32_t)__cvta_generic_to_shared(smem);

    int tid  = threadIdx.x;
    int bm   = blockIdx.y * 128, bn = blockIdx.x * 128;
    int warp = tid >> 5, lane = tid & 31;
    int warpM = warp >> 1, warpN = warp & 1;
    int lg = lane >> 2, lt = lane & 3;

    int aRow = warpM * 32 + ((lane >> 3) & 1) * 8 + (lane & 7);
    int aKc  = lane >> 4;
    int bRow = warpN * 64 + (lane >> 4) * 8 + (lane & 7);
    int bKc  = (lane >> 3) & 1;

    int lrow = tid >> 2;
    int lchk = tid & 3;
    const bf16* Ag = A  + (size_t)(bm + lrow) * K + lchk * 8;
    const bf16* Bg = Bw + (size_t)(bn + lrow) * K + lchk * 8;

    float4 acc[2][8];
#pragma unroll
    for (int mt = 0; mt < 2; mt++)
#pragma unroll
        for (int nt = 0; nt < 8; nt++) acc[mt][nt] = make_float4(0.f, 0.f, 0.f, 0.f);

    auto loadTile = [&](int stage, int kt) {
        uint32_t as = sbase + stage * TILEB;
        uint32_t bs = sbase + STAGES * TILEB + stage * TILEB;
#pragma unroll
        for (int p = 0; p < 2; p++) {
            int r = p * 64 + lrow;
            uint32_t off = swz(r, lchk);
            cp16s(as + off, Ag + (size_t)p * 64 * K + kt);
            cp16s(bs + off, Bg + (size_t)p * 64 * K + kt);
        }
        cp_commit();
    };

    auto compute = [&](int stage) {
        uint32_t aBase = sbase + stage * TILEB;
        uint32_t bBase = sbase + STAGES * TILEB + stage * TILEB;
#pragma unroll
        for (int ks = 0; ks < 2; ks++) {
            uint32_t a[2][4], b[8][2];
#pragma unroll
            for (int mt = 0; mt < 2; mt++) {
                int row = aRow + mt * 16;
                ldsm4(a[mt][0], a[mt][1], a[mt][2], a[mt][3],
                      aBase + swz(row, ks * 2 + aKc));
            }
#pragma unroll
            for (int np = 0; np < 4; np++) {
                int row = bRow + np * 16;
                ldsm4(b[2 * np][0], b[2 * np][1], b[2 * np + 1][0], b[2 * np + 1][1],
                      bBase + swz(row, ks * 2 + bKc));
            }
#pragma unroll
            for (int mt = 0; mt < 2; mt++)
#pragma unroll
                for (int nt = 0; nt < 8; nt++)
                    mma_bf16(acc[mt][nt], a[mt], b[nt]);
        }
    };

    int T = K >> 5;

    loadTile(0, 0);
    loadTile(1, BK);
    loadTile(2, 2 * BK);
    loadTile(3, 3 * BK);

    int s0 = 0;
    int sl = 4;
    for (int t0 = 0; t0 < T; t0 += 2) {
        cp_wait<2>();
        __syncthreads();

        compute(s0);
        int s1 = s0 + 1; if (s1 >= STAGES) s1 -= STAGES;
        compute(s1);

        if (t0 + 4 < T) loadTile(sl, (t0 + 4) * BK); else cp_commit();
        int sl2 = sl + 1; if (sl2 >= STAGES) sl2 -= STAGES;
        if (t0 + 5 < T) loadTile(sl2, (t0 + 5) * BK); else cp_commit();

        s0 += 2; if (s0 >= STAGES) s0 -= STAGES;
        sl += 2; if (sl >= STAGES) sl -= STAGES;
    }

    // epilogue
#pragma unroll
    for (int mt = 0; mt < 2; mt++) {
        int row = bm + warpM * 32 + mt * 16 + lg;
#pragma unroll
        for (int nt = 0; nt < 8; nt++) {
            int col = bn + warpN * 64 + nt * 8 + lt * 2;
            float b0 = bias[col], b1 = bias[col + 1];
            float4 v = acc[mt][nt];
            float o00 = v.x + b0, o01 = v.y + b1;
            float o10 = v.z + b0, o11 = v.w + b1;
            if (EP == 1) {
                o00 = 0.5f * o00 * (1.f + erff(o00 * 0.70710678f));
                o01 = 0.5f * o01 * (1.f + erff(o01 * 0.70710678f));
                o10 = 0.5f * o10 * (1.f + erff(o10 * 0.70710678f));
                o11 = 0.5f * o11 * (1.f + erff(o11 * 0.70710678f));
            } else if (EP == 2) {
                const float2 r0 = *reinterpret_cast<const float2*>(Res + (size_t)row * N + col);
                const float2 r1 = *reinterpret_cast<const float2*>(Res + (size_t)(row + 8) * N + col);
                o00 += r0.x; o01 += r0.y; o10 += r1.x; o11 += r1.y;
            }
            store2(C, (size_t)row * N + col,       o00, o01);
            store2(C, (size_t)(row + 8) * N + col, o10, o11);
        }
    }
}

// ---------------------------------------------------------------------------
// Window attention, rebuilt. One CTA per window, 8 warps = 8 heads.
// smem: bf16 q (pre-scaled x0.125, exact) and k, row stride 520 bf16
// (1040 B = 16 mod 128 -> distinct k-rows map to distinct 16B banks).
// Lanes 0..26: (n,g) = (lane/3, lane%3); lane computes scores (n, 3g+j).
// q loads broadcast (3 lanes/row); k loads 3 distinct rows, conflict-free.
// fp32 fma chains d-ascending per score / m-ascending per dim: bit-identical
// to the R11 kernel.
// ---------------------------------------------------------------------------
__global__ __launch_bounds__(256) void attn_kernel(
    const bf16* __restrict__ qkv, const float* __restrict__ bias_table,
    bf16* __restrict__ out)
{
    __shared__ __align__(16) bf16 sq[9][520];
    __shared__ __align__(16) bf16 sk[9][520];
    __shared__ float sp[8][81];
    int b   = blockIdx.x;
    int tid = threadIdx.x;
    size_t base = (size_t)b * 9 * 1536;

    // staging: 576 16B-chunks per matrix (9 rows x 64 chunks of 8 bf16)
    for (int idx = tid; idx < 576; idx += 256) {
        int n  = idx >> 6;
        int c8 = (idx & 63) * 8;
        uint4 qv = *reinterpret_cast<const uint4*>(qkv + base + (size_t)n * 1536 + c8);
        bf162* qp = reinterpret_cast<bf162*>(&qv);
        uint4 qs;
        bf162* qo = reinterpret_cast<bf162*>(&qs);
#pragma unroll
        for (int j = 0; j < 4; j++) {
            float2 f = __bfloat1622float2(qp[j]);
            qo[j] = __floats2bfloat162_rn(f.x * 0.125f, f.y * 0.125f);  // exact
        }
        *reinterpret_cast<uint4*>(&sq[n][c8]) = qs;
        *reinterpret_cast<uint4*>(&sk[n][c8]) =
            *reinterpret_cast<const uint4*>(qkv + base + (size_t)n * 1536 + 512 + c8);
    }
    __syncthreads();

    int h = tid >> 5, lane = tid & 31;

    // ---- QK^T + relative position bias ----
    if (lane < 27) {
        int n = lane / 3, g = lane % 3;
        const bf16* qrow = &sq[n][h * 64];
        const bf16* kr0  = &sk[3 * g + 0][h * 64];
        const bf16* kr1  = &sk[3 * g + 1][h * 64];
        const bf16* kr2  = &sk[3 * g + 2][h * 64];
        float acc0 = 0.f, acc1 = 0.f, acc2 = 0.f;
#pragma unroll
        for (int c = 0; c < 8; c++) {
            uint4 qv = *reinterpret_cast<const uint4*>(qrow + c * 8);
            const bf162* q2 = reinterpret_cast<const bf162*>(&qv);
            float2 qf0 = __bfloat1622float2(q2[0]);
            float2 qf1 = __bfloat1622float2(q2[1]);
            float2 qf2 = __bfloat1622float2(q2[2]);
            float2 qf3 = __bfloat1622float2(q2[3]);

            uint4 kv0 = *reinterpret_cast<const uint4*>(kr0 + c * 8);
            uint4 kv1 = *reinterpret_cast<const uint4*>(kr1 + c * 8);
            uint4 kv2 = *reinterpret_cast<const uint4*>(kr2 + c * 8);

            const bf162* k2;
            k2 = reinterpret_cast<const bf162*>(&kv0);
            {
                float2 f0 = __bfloat1622float2(k2[0]);
                float2 f1 = __bfloat1622float2(k2[1]);
                float2 f2 = __bfloat1622float2(k2[2]);
                float2 f3 = __bfloat1622float2(k2[3]);
                acc0 = fmaf(qf0.x, f0.x, acc0); acc0 = fmaf(qf0.y, f0.y, acc0);
                acc0 = fmaf(qf1.x, f1.x, acc0); acc0 = fmaf(qf1.y, f1.y, acc0);
                acc0 = fmaf(qf2.x, f2.x, acc0); acc0 = fmaf(qf2.y, f2.y, acc0);
                acc0 = fmaf(qf3.x, f3.x, acc0); acc0 = fmaf(qf3.y, f3.y, acc0);
            }
            k2 = reinterpret_cast<const bf162*>(&kv1);
            {
                float2 f0 = __bfloat1622float2(k2[0]);
                float2 f1 = __bfloat1622float2(k2[1]);
                float2 f2 = __bfloat1622float2(k2[2]);
                float2 f3 = __bfloat1622float2(k2[3]);
                acc1 = fmaf(qf0.x, f0.x, acc1); acc1 = fmaf(qf0.y, f0.y, acc1);
                acc1 = fmaf(qf1.x, f1.x, acc1); acc1 = fmaf(qf1.y, f1.y, acc1);
                acc1 = fmaf(qf2.x, f2.x, acc1); acc1 = fmaf(qf2.y, f2.y, acc1);
                acc1 = fmaf(qf3.x, f3.x, acc1); acc1 = fmaf(qf3.y, f3.y, acc1);
            }
            k2 = reinterpret_cast<const bf162*>(&kv2);
            {
                float2 f0 = __bfloat1622float2(k2[0]);
                float2 f1 = __bfloat1622float2(k2[1]);
                float2 f2 = __bfloat1622float2(k2[2]);
                float2 f3 = __bfloat1622float2(k2[3]);
                acc2 = fmaf(qf0.x, f0.x, acc2); acc2 = fmaf(qf0.y, f0.y, acc2);
                acc2 = fmaf(qf1.x, f1.x, acc2); acc2 = fmaf(qf1.y, f1.y, acc2);
                acc2 = fmaf(qf2.x, f2.x, acc2); acc2 = fmaf(qf2.y, f2.y, acc2);
                acc2 = fmaf(qf3.x, f3.x, acc2); acc2 = fmaf(qf3.y, f3.y, acc2);
            }
        }
#pragma unroll
        for (int j = 0; j < 3; j++) {
            int m = 3 * g + j;
            float s = (j == 0) ? acc0 : (j == 1) ? acc1 : acc2;
            int di = n / 3 - m / 3 + 2;
            int dj = n % 3 - m % 3 + 2;
            s += bias_table[(di * 5 + dj) * 8 + h];
            sp[h][n * 9 + m] = s;
        }
    }
    __syncwarp();

    // ---- softmax: lanes 0..8 each own one query row ----
    if (lane < 9) {
        float mx = -1e30f;
#pragma unroll
        for (int m = 0; m < 9; m++) mx = fmaxf(mx, sp[h][lane * 9 + m]);
        float e[9], sum = 0.f;
#pragma unroll
        for (int m = 0; m < 9; m++) { e[m] = __expf(sp[h][lane * 9 + m] - mx); sum += e[m]; }
        float inv = 1.f / sum;
#pragma unroll
        for (int m = 0; m < 9; m++) sp[h][lane * 9 + m] = e[m] * inv;
    }
    __syncwarp();

    // ---- P@V: lane owns dims 2*lane, 2*lane+1 ----
    float a0[9], a1[9];
#pragma unroll
    for (int n = 0; n < 9; n++) { a0[n] = 0.f; a1[n] = 0.f; }
#pragma unroll
    for (int m = 0; m < 9; m++) {
        size_t vb = base + (size_t)m * 1536 + 1024 + h * 64;
        float2 vf = __bfloat1622float2(
            *reinterpret_cast<const bf162*>(qkv + vb + 2 * lane));
#pragma unroll
        for (int n = 0; n < 9; n++) {
            float p = sp[h][n * 9 + m];
            a0[n] = fmaf(p, vf.x, a0[n]);
            a1[n] = fmaf(p, vf.y, a1[n]);
        }
    }
#pragma unroll
    for (int n = 0; n < 9; n++) {
        size_t o = ((size_t)b * 9 + n) * 512 + h * 64;
        *reinterpret_cast<bf162*>(out + o + 2 * lane) =
            __floats2bfloat162_rn(a0[n], a1[n]);
    }
}

// ---------------------------------------------------------------------------
// Depthwise 3x3 merge conv (fp32)
// ---------------------------------------------------------------------------
__global__ __launch_bounds__(256) void conv_kernel(
    const float* __restrict__ x, const float* __restrict__ w,
    const float* __restrict__ bc, float* __restrict__ out)
{
    int i = blockIdx.x * 256 + threadIdx.x;
    int c = i & 511;
    int b = i >> 9;
    float acc = bc[c];
    size_t base = (size_t)b * 9 * 512 + c;
#pragma unroll
    for (int n = 0; n < 9; n++)
        acc = fmaf(x[base + (size_t)n * 512], w[c * 9 + n], acc);
    out[i] = acc;
}

// ---------------------------------------------------------------------------
extern "C" void kernel_launch(void* const* d_in, const int* in_sizes, int n_in,
                              void* d_out, int out_size)
{
    const float* x          = (const float*)d_in[0];
    const float* gamma1     = (const float*)d_in[1];
    const float* beta1      = (const float*)d_in[2];
    const float* w_qkv      = (const float*)d_in[3];
    const float* b_qkv      = (const float*)d_in[4];
    const float* bias_table = (const float*)d_in[5];
    const float* w_proj     = (const float*)d_in[6];
    const float* b_proj     = (const float*)d_in[7];
    const float* gamma2     = (const float*)d_in[8];
    const float* beta2      = (const float*)d_in[9];
    const float* w_fc1      = (const float*)d_in[10];
    const float* b_fc1      = (const float*)d_in[11];
    const float* w_fc2      = (const float*)d_in[12];
    const float* b_fc2      = (const float*)d_in[13];
    const float* w_conv     = (const float*)d_in[14];
    const float* b_conv     = (const float*)d_in[15];
    float* out = (float*)d_out;

    bf16 *h, *qkv, *attn, *mlp, *wb;
    float *x1;
    cudaGetSymbolAddress((void**)&h,    g_h);
    cudaGetSymbolAddress((void**)&qkv,  g_qkv);
    cudaGetSymbolAddress((void**)&attn, g_attn);
    cudaGetSymbolAddress((void**)&x1,   g_x1);
    cudaGetSymbolAddress((void**)&mlp,  g_mlp);
    cudaGetSymbolAddress((void**)&wb,   g_wb);
    float* x2 = reinterpret_cast<float*>(qkv);   // reuse qkv buffer for x2 (fp32)

    cudaFuncSetAttribute(gemm_bf16_kernel<0, bf16>,
                         cudaFuncAttributeMaxDynamicSharedMemorySize, GSMEM);
    cudaFuncSetAttribute(gemm_bf16_kernel<1, bf16>,
                         cudaFuncAttributeMaxDynamicSharedMemorySize, GSMEM);
    cudaFuncSetAttribute(gemm_bf16_kernel<2, float>,
                         cudaFuncAttributeMaxDynamicSharedMemorySize, GSMEM);

    bf16* wq = wb;
    bf16* wp = wb + 786432;
    bf16* w1 = wb + 1048576;
    bf16* w2 = wb + 2097152;

    // all weight conversions in one launch (regions contiguous in g_wb)
    convw4_kernel<<<3072, 256>>>(w_qkv, w_proj, w_fc1, w_fc2, wb);

    const int MB = MROWS / 128;   // 576 row tiles

    // LN1: x -> h (bf16)
    ln_kernel<<<MROWS / 8, dim3(32, 8)>>>(x, gamma1, beta1, h);
    // QKV: h @ wq^T + b_qkv -> qkv (bf16)
    gemm_bf16_kernel<0, bf16><<<dim3(12, MB), 256, GSMEM>>>(h, wq, b_qkv, nullptr, qkv, 1536, 512);
    // window attention -> attn (bf16)
    attn_kernel<<<8192, 256>>>(qkv, bias_table, attn);
    // proj + shortcut: attn @ wp^T + b_proj + x -> x1 (fp32)
    gemm_bf16_kernel<2, float><<<dim3(4, MB), 256, GSMEM>>>(attn, wp, b_proj, x, x1, 512, 512);
    // LN2: x1 -> h (bf16)
    ln_kernel<<<MROWS / 8, dim3(32, 8)>>>(x1, gamma2, beta2, h);
    // FC1 + GELU: h @ w1^T + b_fc1 -> mlp (bf16)
    gemm_bf16_kernel<1, bf16><<<dim3(16, MB), 256, GSMEM>>>(h, w1, b_fc1, nullptr, mlp, 2048, 512);
    // FC2 + residual: mlp @ w2^T + b_fc2 + x1 -> x2 (fp32, reuses qkv buffer)
    gemm_bf16_kernel<2, float><<<dim3(4, MB), 256, GSMEM>>>(mlp, w2, b_fc2, x1, x2, 512, 2048);
    // merge conv -> out
    conv_kernel<<<(8192 * 512) / 256, 256>>>(x2, w_conv, b_conv, out);
}

// round 13
// speedup vs baseline: 14.6339x; 1.0030x over previous
#include <cuda_runtime.h>
#include <cuda_bf16.h>
#include <math.h>
#include <stdint.h>

// ---------------------------------------------------------------------------
// TransformerBlock: B=8192, N=9, DIM=512, HEADS=8, HEAD_DIM=64
// Round 13: SCALE folded into w_qkv/b_qkv q-slice (exact, power of 2);
// attention stages q/k/v via pure cp.async; V read from smem.
// GEMM pipeline unchanged from R11/12 (validated).
// ---------------------------------------------------------------------------

#define MROWS (8192 * 9)   // 73728 token rows

typedef __nv_bfloat16  bf16;
typedef __nv_bfloat162 bf162;

// Scratch (allocation-free: static device globals)
__device__ __align__(16) bf16  g_h   [(size_t)MROWS * 512];   // LN out (bf16)
__device__ __align__(16) bf16  g_qkv [(size_t)MROWS * 1536];  // QKV (bf16); later fp32 x2
__device__ __align__(16) bf16  g_attn[(size_t)MROWS * 512];   // attn out (bf16)
__device__ __align__(16) float g_x1  [(size_t)MROWS * 512];   // residual after attn (fp32)
__device__ __align__(16) bf16  g_mlp [(size_t)MROWS * 2048];  // GELU(FC1) (bf16)
__device__ __align__(16) bf16  g_wb  [3145728];               // bf16 weights (contiguous)
__device__ __align__(16) float g_bq  [1536];                  // scaled b_qkv (q part x0.125)

__device__ __forceinline__ void cp16s(uint32_t s, const void* src) {
    asm volatile("cp.async.cg.shared.global [%0], [%1], 16;\n" :: "r"(s), "l"(src));
}
__device__ __forceinline__ void cp_commit() { asm volatile("cp.async.commit_group;\n"); }
template <int N> __device__ __forceinline__ void cp_wait() {
    asm volatile("cp.async.wait_group %0;\n" :: "n"(N));
}

__device__ __forceinline__ void mma_bf16(float4& d, const uint32_t a[4], const uint32_t b[2]) {
    asm volatile(
        "mma.sync.aligned.m16n8k16.row.col.f32.bf16.bf16.f32 "
        "{%0,%1,%2,%3}, {%4,%5,%6,%7}, {%8,%9}, {%0,%1,%2,%3};\n"
        : "+f"(d.x), "+f"(d.y), "+f"(d.z), "+f"(d.w)
        : "r"(a[0]), "r"(a[1]), "r"(a[2]), "r"(a[3]), "r"(b[0]), "r"(b[1]));
}
__device__ __forceinline__ void ldsm4(uint32_t& r0, uint32_t& r1, uint32_t& r2,
                                      uint32_t& r3, uint32_t addr) {
    asm volatile("ldmatrix.sync.aligned.m8n8.x4.shared.b16 {%0,%1,%2,%3}, [%4];"
                 : "=r"(r0), "=r"(r1), "=r"(r2), "=r"(r3) : "r"(addr));
}

// swizzled byte offset within one 128x32 bf16 stage-matrix (64B rows)
__device__ __forceinline__ uint32_t swz(int row, int kc) {
    return (uint32_t)(row * 64 + ((kc ^ ((row >> 1) & 3)) << 4));
}

// ---------------------------------------------------------------------------
// Convert all 4 fp32 weight matrices -> bf16 in one launch.
// The q slice of w_qkv (first 65536 float4s = rows 0..511) is scaled by
// 0.125 (power of 2 -> every downstream fp32/bf16 value scales EXACTLY).
// Also writes scaled b_qkv to g_bq (first 512 entries x0.125).
// ---------------------------------------------------------------------------
__global__ __launch_bounds__(256) void convw4_kernel(
    const float* __restrict__ wq, const float* __restrict__ wp,
    const float* __restrict__ w1, const float* __restrict__ w2,
    const float* __restrict__ bq, bf16* __restrict__ out,
    float* __restrict__ bq_out)
{
    int i = blockIdx.x * 256 + threadIdx.x;   // 0 .. 786431 (float4 index)
    const float4* src;
    int local;
    float sc = 1.0f;
    if (i < 196608)      { src = (const float4*)wq; local = i;
                           if (i < 65536) sc = 0.125f; }
    else if (i < 262144) { src = (const float4*)wp; local = i - 196608; }
    else if (i < 524288) { src = (const float4*)w1; local = i - 262144; }
    else                 { src = (const float4*)w2; local = i - 524288; }
    float4 v = src[local];
    bf162* o = reinterpret_cast<bf162*>(out) + i * 2;
    o[0] = __floats2bfloat162_rn(v.x * sc, v.y * sc);
    o[1] = __floats2bfloat162_rn(v.z * sc, v.w * sc);

    if (i < 384) {   // b_qkv: 1536 floats = 384 float4
        float4 b = reinterpret_cast<const float4*>(bq)[i];
        float bs = (i < 128) ? 0.125f : 1.0f;
        reinterpret_cast<float4*>(bq_out)[i] =
            make_float4(b.x * bs, b.y * bs, b.z * bs, b.w * bs);
    }
}

// ---------------------------------------------------------------------------
// LayerNorm over last dim (512). One warp per row. fp32 in -> bf16 out.
// ---------------------------------------------------------------------------
__global__ __launch_bounds__(256) void ln_kernel(
    const float* __restrict__ x, const float* __restrict__ gam,
    const float* __restrict__ bet, bf16* __restrict__ out)
{
    int row  = blockIdx.x * 8 + threadIdx.y;
    int lane = threadIdx.x;
    const float4* xr = reinterpret_cast<const float4*>(x) + (size_t)row * 128;
    float4 v[4];
    float s = 0.f, s2 = 0.f;
#pragma unroll
    for (int i = 0; i < 4; i++) {
        v[i] = xr[lane + 32 * i];
        s  += v[i].x + v[i].y + v[i].z + v[i].w;
        s2 += v[i].x * v[i].x + v[i].y * v[i].y + v[i].z * v[i].z + v[i].w * v[i].w;
    }
#pragma unroll
    for (int o = 16; o; o >>= 1) {
        s  += __shfl_xor_sync(0xffffffffu, s,  o);
        s2 += __shfl_xor_sync(0xffffffffu, s2, o);
    }
    float mu   = s * (1.f / 512.f);
    float var  = s2 * (1.f / 512.f) - mu * mu;
    float rstd = rsqrtf(var + 1e-5f);
    bf162* orow = reinterpret_cast<bf162*>(out) + (size_t)row * 256;
    const float4* g4 = reinterpret_cast<const float4*>(gam);
    const float4* b4 = reinterpret_cast<const float4*>(bet);
#pragma unroll
    for (int i = 0; i < 4; i++) {
        int c = lane + 32 * i;
        float4 g = g4[c], b = b4[c];
        float o0 = (v[i].x - mu) * rstd * g.x + b.x;
        float o1 = (v[i].y - mu) * rstd * g.y + b.y;
        float o2 = (v[i].z - mu) * rstd * g.z + b.z;
        float o3 = (v[i].w - mu) * rstd * g.w + b.w;
        orow[2 * c]     = __floats2bfloat162_rn(o0, o1);
        orow[2 * c + 1] = __floats2bfloat162_rn(o2, o3);
    }
}

// ---------------------------------------------------------------------------
// bf16 HMMA GEMM (unchanged from R11/12 — validated).
// ---------------------------------------------------------------------------
#define BK     32
#define TILEB  8192                  // bytes per 128x32 bf16 stage-matrix
#define STAGES 6
#define GSMEM  (STAGES * 2 * TILEB)  // 98304 bytes

__device__ __forceinline__ void store2(bf16* C, size_t off, float a, float b) {
    *reinterpret_cast<bf162*>(C + off) = __floats2bfloat162_rn(a, b);
}
__device__ __forceinline__ void store2(float* C, size_t off, float a, float b) {
    *reinterpret_cast<float2*>(C + off) = make_float2(a, b);
}

template <int EP, typename OutT>
__global__ __launch_bounds__(256, 2) void gemm_bf16_kernel(
    const bf16* __restrict__ A, const bf16* __restrict__ Bw,
    const float* __restrict__ bias, const float* __restrict__ Res,
    OutT* __restrict__ C, int N, int K)
{
    extern __shared__ char smem[];   // [A stages 0..5][B stages 0..5]
    uint32_t sbase = (uint32_t)__cvta_generic_to_shared(smem);

    int tid  = threadIdx.x;
    int bm   = blockIdx.y * 128, bn = blockIdx.x * 128;
    int warp = tid >> 5, lane = tid & 31;
    int warpM = warp >> 1, warpN = warp & 1;
    int lg = lane >> 2, lt = lane & 3;

    int aRow = warpM * 32 + ((lane >> 3) & 1) * 8 + (lane & 7);
    int aKc  = lane >> 4;
    int bRow = warpN * 64 + (lane >> 4) * 8 + (lane & 7);
    int bKc  = (lane >> 3) & 1;

    int lrow = tid >> 2;
    int lchk = tid & 3;
    const bf16* Ag = A  + (size_t)(bm + lrow) * K + lchk * 8;
    const bf16* Bg = Bw + (size_t)(bn + lrow) * K + lchk * 8;

    float4 acc[2][8];
#pragma unroll
    for (int mt = 0; mt < 2; mt++)
#pragma unroll
        for (int nt = 0; nt < 8; nt++) acc[mt][nt] = make_float4(0.f, 0.f, 0.f, 0.f);

    auto loadTile = [&](int stage, int kt) {
        uint32_t as = sbase + stage * TILEB;
        uint32_t bs = sbase + STAGES * TILEB + stage * TILEB;
#pragma unroll
        for (int p = 0; p < 2; p++) {
            int r = p * 64 + lrow;
            uint32_t off = swz(r, lchk);
            cp16s(as + off, Ag + (size_t)p * 64 * K + kt);
            cp16s(bs + off, Bg + (size_t)p * 64 * K + kt);
        }
        cp_commit();
    };

    auto compute = [&](int stage) {
        uint32_t aBase = sbase + stage * TILEB;
        uint32_t bBase = sbase + STAGES * TILEB + stage * TILEB;
#pragma unroll
        for (int ks = 0; ks < 2; ks++) {
            uint32_t a[2][4], b[8][2];
#pragma unroll
            for (int mt = 0; mt < 2; mt++) {
                int row = aRow + mt * 16;
                ldsm4(a[mt][0], a[mt][1], a[mt][2], a[mt][3],
                      aBase + swz(row, ks * 2 + aKc));
            }
#pragma unroll
            for (int np = 0; np < 4; np++) {
                int row = bRow + np * 16;
                ldsm4(b[2 * np][0], b[2 * np][1], b[2 * np + 1][0], b[2 * np + 1][1],
                      bBase + swz(row, ks * 2 + bKc));
            }
#pragma unroll
            for (int mt = 0; mt < 2; mt++)
#pragma unroll
                for (int nt = 0; nt < 8; nt++)
                    mma_bf16(acc[mt][nt], a[mt], b[nt]);
        }
    };

    int T = K >> 5;

    loadTile(0, 0);
    loadTile(1, BK);
    loadTile(2, 2 * BK);
    loadTile(3, 3 * BK);

    int s0 = 0;
    int sl = 4;
    for (int t0 = 0; t0 < T; t0 += 2) {
        cp_wait<2>();
        __syncthreads();

        compute(s0);
        int s1 = s0 + 1; if (s1 >= STAGES) s1 -= STAGES;
        compute(s1);

        if (t0 + 4 < T) loadTile(sl, (t0 + 4) * BK); else cp_commit();
        int sl2 = sl + 1; if (sl2 >= STAGES) sl2 -= STAGES;
        if (t0 + 5 < T) loadTile(sl2, (t0 + 5) * BK); else cp_commit();

        s0 += 2; if (s0 >= STAGES) s0 -= STAGES;
        sl += 2; if (sl >= STAGES) sl -= STAGES;
    }

    // epilogue
#pragma unroll
    for (int mt = 0; mt < 2; mt++) {
        int row = bm + warpM * 32 + mt * 16 + lg;
#pragma unroll
        for (int nt = 0; nt < 8; nt++) {
            int col = bn + warpN * 64 + nt * 8 + lt * 2;
            float b0 = bias[col], b1 = bias[col + 1];
            float4 v = acc[mt][nt];
            float o00 = v.x + b0, o01 = v.y + b1;
            float o10 = v.z + b0, o11 = v.w + b1;
            if (EP == 1) {
                o00 = 0.5f * o00 * (1.f + erff(o00 * 0.70710678f));
                o01 = 0.5f * o01 * (1.f + erff(o01 * 0.70710678f));
                o10 = 0.5f * o10 * (1.f + erff(o10 * 0.70710678f));
                o11 = 0.5f * o11 * (1.f + erff(o11 * 0.70710678f));
            } else if (EP == 2) {
                const float2 r0 = *reinterpret_cast<const float2*>(Res + (size_t)row * N + col);
                const float2 r1 = *reinterpret_cast<const float2*>(Res + (size_t)(row + 8) * N + col);
                o00 += r0.x; o01 += r0.y; o10 += r1.x; o11 += r1.y;
            }
            store2(C, (size_t)row * N + col,       o00, o01);
            store2(C, (size_t)(row + 8) * N + col, o10, o11);
        }
    }
}

// ---------------------------------------------------------------------------
// Window attention. One CTA per window, 8 warps = 8 heads.
// q arrives PRE-SCALED (scale folded into w_qkv/b_qkv, exact).
// q/k/v staged via pure cp.async (no register round-trips).
// Row stride 520 bf16 (1040B = 16 mod 128): distinct rows hit distinct
// 16B windows -> conflict-free QK^T k-loads; P@V reads 4B/lane, also free.
// fp32 fma chains identical order to R12 -> bit-identical output.
// ---------------------------------------------------------------------------
__global__ __launch_bounds__(256) void attn_kernel(
    const bf16* __restrict__ qkv, const float* __restrict__ bias_table,
    bf16* __restrict__ out)
{
    __shared__ __align__(16) bf16 sq[9][520];
    __shared__ __align__(16) bf16 sk[9][520];
    __shared__ __align__(16) bf16 sv[9][520];
    __shared__ float sp[8][81];
    int b   = blockIdx.x;
    int tid = threadIdx.x;
    size_t base = (size_t)b * 9 * 1536;
    uint32_t sqb = (uint32_t)__cvta_generic_to_shared(&sq[0][0]);
    uint32_t skb = (uint32_t)__cvta_generic_to_shared(&sk[0][0]);
    uint32_t svb = (uint32_t)__cvta_generic_to_shared(&sv[0][0]);

    // staging: 9 rows x 192 chunks of 16B (q|k|v contiguous per token row)
    for (int idx = tid; idx < 1728; idx += 256) {
        int n = idx / 192, c = idx - n * 192;      // c in [0,192)
        int mat = c >> 6;                           // 0=q 1=k 2=v
        uint32_t dst = (mat == 0 ? sqb : mat == 1 ? skb : svb)
                     + (uint32_t)(n * 1040 + (c & 63) * 16);
        cp16s(dst, qkv + base + (size_t)n * 1536 + c * 8);
    }
    cp_commit();
    cp_wait<0>();
    __syncthreads();

    int h = tid >> 5, lane = tid & 31;

    // ---- QK^T + relative position bias ----
    if (lane < 27) {
        int n = lane / 3, g = lane % 3;
        const bf16* qrow = &sq[n][h * 64];
        const bf16* kr0  = &sk[3 * g + 0][h * 64];
        const bf16* kr1  = &sk[3 * g + 1][h * 64];
        const bf16* kr2  = &sk[3 * g + 2][h * 64];
        float acc0 = 0.f, acc1 = 0.f, acc2 = 0.f;
#pragma unroll
        for (int c = 0; c < 8; c++) {
            uint4 qv = *reinterpret_cast<const uint4*>(qrow + c * 8);
            const bf162* q2 = reinterpret_cast<const bf162*>(&qv);
            float2 qf0 = __bfloat1622float2(q2[0]);
            float2 qf1 = __bfloat1622float2(q2[1]);
            float2 qf2 = __bfloat1622float2(q2[2]);
            float2 qf3 = __bfloat1622float2(q2[3]);

            uint4 kv0 = *reinterpret_cast<const uint4*>(kr0 + c * 8);
            uint4 kv1 = *reinterpret_cast<const uint4*>(kr1 + c * 8);
            uint4 kv2 = *reinterpret_cast<const uint4*>(kr2 + c * 8);

            const bf162* k2;
            k2 = reinterpret_cast<const bf162*>(&kv0);
            {
                float2 f0 = __bfloat1622float2(k2[0]);
                float2 f1 = __bfloat1622float2(k2[1]);
                float2 f2 = __bfloat1622float2(k2[2]);
                float2 f3 = __bfloat1622float2(k2[3]);
                acc0 = fmaf(qf0.x, f0.x, acc0); acc0 = fmaf(qf0.y, f0.y, acc0);
                acc0 = fmaf(qf1.x, f1.x, acc0); acc0 = fmaf(qf1.y, f1.y, acc0);
                acc0 = fmaf(qf2.x, f2.x, acc0); acc0 = fmaf(qf2.y, f2.y, acc0);
                acc0 = fmaf(qf3.x, f3.x, acc0); acc0 = fmaf(qf3.y, f3.y, acc0);
            }
            k2 = reinterpret_cast<const bf162*>(&kv1);
            {
                float2 f0 = __bfloat1622float2(k2[0]);
                float2 f1 = __bfloat1622float2(k2[1]);
                float2 f2 = __bfloat1622float2(k2[2]);
                float2 f3 = __bfloat1622float2(k2[3]);
                acc1 = fmaf(qf0.x, f0.x, acc1); acc1 = fmaf(qf0.y, f0.y, acc1);
                acc1 = fmaf(qf1.x, f1.x, acc1); acc1 = fmaf(qf1.y, f1.y, acc1);
                acc1 = fmaf(qf2.x, f2.x, acc1); acc1 = fmaf(qf2.y, f2.y, acc1);
                acc1 = fmaf(qf3.x, f3.x, acc1); acc1 = fmaf(qf3.y, f3.y, acc1);
            }
            k2 = reinterpret_cast<const bf162*>(&kv2);
            {
                float2 f0 = __bfloat1622float2(k2[0]);
                float2 f1 = __bfloat1622float2(k2[1]);
                float2 f2 = __bfloat1622float2(k2[2]);
                float2 f3 = __bfloat1622float2(k2[3]);
                acc2 = fmaf(qf0.x, f0.x, acc2); acc2 = fmaf(qf0.y, f0.y, acc2);
                acc2 = fmaf(qf1.x, f1.x, acc2); acc2 = fmaf(qf1.y, f1.y, acc2);
                acc2 = fmaf(qf2.x, f2.x, acc2); acc2 = fmaf(qf2.y, f2.y, acc2);
                acc2 = fmaf(qf3.x, f3.x, acc2); acc2 = fmaf(qf3.y, f3.y, acc2);
            }
        }
#pragma unroll
        for (int j = 0; j < 3; j++) {
            int m = 3 * g + j;
            float s = (j == 0) ? acc0 : (j == 1) ? acc1 : acc2;
            int di = n / 3 - m / 3 + 2;
            int dj = n % 3 - m % 3 + 2;
            s += bias_table[(di * 5 + dj) * 8 + h];
            sp[h][n * 9 + m] = s;
        }
    }
    __syncwarp();

    // ---- softmax: lanes 0..8 each own one query row ----
    if (lane < 9) {
        float mx = -1e30f;
#pragma unroll
        for (int m = 0; m < 9; m++) mx = fmaxf(mx, sp[h][lane * 9 + m]);
        float e[9], sum = 0.f;
#pragma unroll
        for (int m = 0; m < 9; m++) { e[m] = __expf(sp[h][lane * 9 + m] - mx); sum += e[m]; }
        float inv = 1.f / sum;
#pragma unroll
        for (int m = 0; m < 9; m++) sp[h][lane * 9 + m] = e[m] * inv;
    }
    __syncwarp();

    // ---- P@V from smem: lane owns dims 2*lane, 2*lane+1 ----
    float a0[9], a1[9];
#pragma unroll
    for (int n = 0; n < 9; n++) { a0[n] = 0.f; a1[n] = 0.f; }
#pragma unroll
    for (int m = 0; m < 9; m++) {
        float2 vf = __bfloat1622float2(
            *reinterpret_cast<const bf162*>(&sv[m][h * 64 + 2 * lane]));
#pragma unroll
        for (int n = 0; n < 9; n++) {
            float p = sp[h][n * 9 + m];
            a0[n] = fmaf(p, vf.x, a0[n]);
            a1[n] = fmaf(p, vf.y, a1[n]);
        }
    }
#pragma unroll
    for (int n = 0; n < 9; n++) {
        size_t o = ((size_t)b * 9 + n) * 512 + h * 64;
        *reinterpret_cast<bf162*>(out + o + 2 * lane) =
            __floats2bfloat162_rn(a0[n], a1[n]);
    }
}

// ---------------------------------------------------------------------------
// Depthwise 3x3 merge conv (fp32)
// ---------------------------------------------------------------------------
__global__ __launch_bounds__(256) void conv_kernel(
    const float* __restrict__ x, const float* __restrict__ w,
    const float* __restrict__ bc, float* __restrict__ out)
{
    int i = blockIdx.x * 256 + threadIdx.x;
    int c = i & 511;
    int b = i >> 9;
    float acc = bc[c];
    size_t base = (size_t)b * 9 * 512 + c;
#pragma unroll
    for (int n = 0; n < 9; n++)
        acc = fmaf(x[base + (size_t)n * 512], w[c * 9 + n], acc);
    out[i] = acc;
}

// ---------------------------------------------------------------------------
extern "C" void kernel_launch(void* const* d_in, const int* in_sizes, int n_in,
                              void* d_out, int out_size)
{
    const float* x          = (const float*)d_in[0];
    const float* gamma1     = (const float*)d_in[1];
    const float* beta1      = (const float*)d_in[2];
    const float* w_qkv      = (const float*)d_in[3];
    const float* b_qkv      = (const float*)d_in[4];
    const float* bias_table = (const float*)d_in[5];
    const float* w_proj     = (const float*)d_in[6];
    const float* b_proj     = (const float*)d_in[7];
    const float* gamma2     = (const float*)d_in[8];
    const float* beta2      = (const float*)d_in[9];
    const float* w_fc1      = (const float*)d_in[10];
    const float* b_fc1      = (const float*)d_in[11];
    const float* w_fc2      = (const float*)d_in[12];
    const float* b_fc2      = (const float*)d_in[13];
    const float* w_conv     = (const float*)d_in[14];
    const float* b_conv     = (const float*)d_in[15];
    float* out = (float*)d_out;

    bf16 *h, *qkv, *attn, *mlp, *wb;
    float *x1, *bqs;
    cudaGetSymbolAddress((void**)&h,    g_h);
    cudaGetSymbolAddress((void**)&qkv,  g_qkv);
    cudaGetSymbolAddress((void**)&attn, g_attn);
    cudaGetSymbolAddress((void**)&x1,   g_x1);
    cudaGetSymbolAddress((void**)&mlp,  g_mlp);
    cudaGetSymbolAddress((void**)&wb,   g_wb);
    cudaGetSymbolAddress((void**)&bqs,  g_bq);
    float* x2 = reinterpret_cast<float*>(qkv);   // reuse qkv buffer for x2 (fp32)

    cudaFuncSetAttribute(gemm_bf16_kernel<0, bf16>,
                         cudaFuncAttributeMaxDynamicSharedMemorySize, GSMEM);
    cudaFuncSetAttribute(gemm_bf16_kernel<1, bf16>,
                         cudaFuncAttributeMaxDynamicSharedMemorySize, GSMEM);
    cudaFuncSetAttribute(gemm_bf16_kernel<2, float>,
                         cudaFuncAttributeMaxDynamicSharedMemorySize, GSMEM);

    bf16* wq = wb;
    bf16* wp = wb + 786432;
    bf16* w1 = wb + 1048576;
    bf16* w2 = wb + 2097152;

    // all weight conversions + q-scale folding in one launch
    convw4_kernel<<<3072, 256>>>(w_qkv, w_proj, w_fc1, w_fc2, b_qkv, wb, bqs);

    const int MB = MROWS / 128;   // 576 row tiles

    // LN1: x -> h (bf16)
    ln_kernel<<<MROWS / 8, dim3(32, 8)>>>(x, gamma1, beta1, h);
    // QKV (q pre-scaled): h @ wq^T + bqs -> qkv (bf16)
    gemm_bf16_kernel<0, bf16><<<dim3(12, MB), 256, GSMEM>>>(h, wq, bqs, nullptr, qkv, 1536, 512);
    // window attention -> attn (bf16)
    attn_kernel<<<8192, 256>>>(qkv, bias_table, attn);
    // proj + shortcut: attn @ wp^T + b_proj + x -> x1 (fp32)
    gemm_bf16_kernel<2, float><<<dim3(4, MB), 256, GSMEM>>>(attn, wp, b_proj, x, x1, 512, 512);
    // LN2: x1 -> h (bf16)
    ln_kernel<<<MROWS / 8, dim3(32, 8)>>>(x1, gamma2, beta2, h);
    // FC1 + GELU: h @ w1^T + b_fc1 -> mlp (bf16)
    gemm_bf16_kernel<1, bf16><<<dim3(16, MB), 256, GSMEM>>>(h, w1, b_fc1, nullptr, mlp, 2048, 512);
    // FC2 + residual: mlp @ w2^T + b_fc2 + x1 -> x2 (fp32, reuses qkv buffer)
    gemm_bf16_kernel<2, float><<<dim3(4, MB), 256, GSMEM>>>(mlp, w2, b_fc2, x1, x2, 512, 2048);
    // merge conv -> out
    conv_kernel<<<(8192 * 512) / 256, 256>>>(x2, w_conv, b_conv, out);
}

// round 16
// speedup vs baseline: 14.8534x; 1.0150x over previous
#include <cuda_runtime.h>
#include <cuda_bf16.h>
#include <math.h>
#include <stdint.h>

// ---------------------------------------------------------------------------
// TransformerBlock: B=8192, N=9, DIM=512, HEADS=8, HEAD_DIM=64
// Round 14: attention QK^T moved to HMMA (bf16 in, fp32 accum; no new
// quantization). Softmax + P@V stay fp32. GEMM pipeline unchanged.
// ---------------------------------------------------------------------------

#define MROWS (8192 * 9)   // 73728 token rows

typedef __nv_bfloat16  bf16;
typedef __nv_bfloat162 bf162;

// Scratch (allocation-free: static device globals)
__device__ __align__(16) bf16  g_h   [(size_t)MROWS * 512];   // LN out (bf16)
__device__ __align__(16) bf16  g_qkv [(size_t)MROWS * 1536];  // QKV (bf16); later fp32 x2
__device__ __align__(16) bf16  g_attn[(size_t)MROWS * 512];   // attn out (bf16)
__device__ __align__(16) float g_x1  [(size_t)MROWS * 512];   // residual after attn (fp32)
__device__ __align__(16) bf16  g_mlp [(size_t)MROWS * 2048];  // GELU(FC1) (bf16)
__device__ __align__(16) bf16  g_wb  [3145728];               // bf16 weights (contiguous)
__device__ __align__(16) float g_bq  [1536];                  // scaled b_qkv (q part x0.125)

__device__ __forceinline__ void cp16s(uint32_t s, const void* src) {
    asm volatile("cp.async.cg.shared.global [%0], [%1], 16;\n" :: "r"(s), "l"(src));
}
__device__ __forceinline__ void cp_commit() { asm volatile("cp.async.commit_group;\n"); }
template <int N> __device__ __forceinline__ void cp_wait() {
    asm volatile("cp.async.wait_group %0;\n" :: "n"(N));
}

__device__ __forceinline__ void mma_bf16(float4& d, const uint32_t a[4], const uint32_t b[2]) {
    asm volatile(
        "mma.sync.aligned.m16n8k16.row.col.f32.bf16.bf16.f32 "
        "{%0,%1,%2,%3}, {%4,%5,%6,%7}, {%8,%9}, {%0,%1,%2,%3};\n"
        : "+f"(d.x), "+f"(d.y), "+f"(d.z), "+f"(d.w)
        : "r"(a[0]), "r"(a[1]), "r"(a[2]), "r"(a[3]), "r"(b[0]), "r"(b[1]));
}
__device__ __forceinline__ void ldsm4(uint32_t& r0, uint32_t& r1, uint32_t& r2,
                                      uint32_t& r3, uint32_t addr) {
    asm volatile("ldmatrix.sync.aligned.m8n8.x4.shared.b16 {%0,%1,%2,%3}, [%4];"
                 : "=r"(r0), "=r"(r1), "=r"(r2), "=r"(r3) : "r"(addr));
}

// swizzled byte offset within one 128x32 bf16 stage-matrix (64B rows)
__device__ __forceinline__ uint32_t swz(int row, int kc) {
    return (uint32_t)(row * 64 + ((kc ^ ((row >> 1) & 3)) << 4));
}

// ---------------------------------------------------------------------------
// Convert all 4 fp32 weight matrices -> bf16 in one launch; q slice of
// w_qkv/b_qkv scaled by 0.125 (power of 2 -> exact).
// ---------------------------------------------------------------------------
__global__ __launch_bounds__(256) void convw4_kernel(
    const float* __restrict__ wq, const float* __restrict__ wp,
    const float* __restrict__ w1, const float* __restrict__ w2,
    const float* __restrict__ bq, bf16* __restrict__ out,
    float* __restrict__ bq_out)
{
    int i = blockIdx.x * 256 + threadIdx.x;   // 0 .. 786431 (float4 index)
    const float4* src;
    int local;
    float sc = 1.0f;
    if (i < 196608)      { src = (const float4*)wq; local = i;
                           if (i < 65536) sc = 0.125f; }
    else if (i < 262144) { src = (const float4*)wp; local = i - 196608; }
    else if (i < 524288) { src = (const float4*)w1; local = i - 262144; }
    else                 { src = (const float4*)w2; local = i - 524288; }
    float4 v = src[local];
    bf162* o = reinterpret_cast<bf162*>(out) + i * 2;
    o[0] = __floats2bfloat162_rn(v.x * sc, v.y * sc);
    o[1] = __floats2bfloat162_rn(v.z * sc, v.w * sc);

    if (i < 384) {   // b_qkv: 1536 floats = 384 float4
        float4 b = reinterpret_cast<const float4*>(bq)[i];
        float bs = (i < 128) ? 0.125f : 1.0f;
        reinterpret_cast<float4*>(bq_out)[i] =
            make_float4(b.x * bs, b.y * bs, b.z * bs, b.w * bs);
    }
}

// ---------------------------------------------------------------------------
// LayerNorm over last dim (512). One warp per row. fp32 in -> bf16 out.
// ---------------------------------------------------------------------------
__global__ __launch_bounds__(256) void ln_kernel(
    const float* __restrict__ x, const float* __restrict__ gam,
    const float* __restrict__ bet, bf16* __restrict__ out)
{
    int row  = blockIdx.x * 8 + threadIdx.y;
    int lane = threadIdx.x;
    const float4* xr = reinterpret_cast<const float4*>(x) + (size_t)row * 128;
    float4 v[4];
    float s = 0.f, s2 = 0.f;
#pragma unroll
    for (int i = 0; i < 4; i++) {
        v[i] = xr[lane + 32 * i];
        s  += v[i].x + v[i].y + v[i].z + v[i].w;
        s2 += v[i].x * v[i].x + v[i].y * v[i].y + v[i].z * v[i].z + v[i].w * v[i].w;
    }
#pragma unroll
    for (int o = 16; o; o >>= 1) {
        s  += __shfl_xor_sync(0xffffffffu, s,  o);
        s2 += __shfl_xor_sync(0xffffffffu, s2, o);
    }
    float mu   = s * (1.f / 512.f);
    float var  = s2 * (1.f / 512.f) - mu * mu;
    float rstd = rsqrtf(var + 1e-5f);
    bf162* orow = reinterpret_cast<bf162*>(out) + (size_t)row * 256;
    const float4* g4 = reinterpret_cast<const float4*>(gam);
    const float4* b4 = reinterpret_cast<const float4*>(bet);
#pragma unroll
    for (int i = 0; i < 4; i++) {
        int c = lane + 32 * i;
        float4 g = g4[c], b = b4[c];
        float o0 = (v[i].x - mu) * rstd * g.x + b.x;
        float o1 = (v[i].y - mu) * rstd * g.y + b.y;
        float o2 = (v[i].z - mu) * rstd * g.z + b.z;
        float o3 = (v[i].w - mu) * rstd * g.w + b.w;
        orow[2 * c]     = __floats2bfloat162_rn(o0, o1);
        orow[2 * c + 1] = __floats2bfloat162_rn(o2, o3);
    }
}

// ---------------------------------------------------------------------------
// bf16 HMMA GEMM (unchanged from R11-13 — validated).
// ---------------------------------------------------------------------------
#define BK     32
#define TILEB  8192                  // bytes per 128x32 bf16 stage-matrix
#define STAGES 6
#define GSMEM  (STAGES * 2 * TILEB)  // 98304 bytes

__device__ __forceinline__ void store2(bf16* C, size_t off, float a, float b) {
    *reinterpret_cast<bf162*>(C + off) = __floats2bfloat162_rn(a, b);
}
__device__ __forceinline__ void store2(float* C, size_t off, float a, float b) {
    *reinterpret_cast<float2*>(C + off) = make_float2(a, b);
}

template <int EP, typename OutT>
__global__ __launch_bounds__(256, 2) void gemm_bf16_kernel(
    const bf16* __restrict__ A, const bf16* __restrict__ Bw,
    const float* __restrict__ bias, const float* __restrict__ Res,
    OutT* __restrict__ C, int N, int K)
{
    extern __shared__ char smem[];   // [A stages 0..5][B stages 0..5]
    uint32_t sbase = (uint32_t)__cvta_generic_to_shared(smem);

    int tid  = threadIdx.x;
    int bm   = blockIdx.y * 128, bn = blockIdx.x * 128;
    int warp = tid >> 5, lane = tid & 31;
    int warpM = warp >> 1, warpN = warp & 1;
    int lg = lane >> 2, lt = lane & 3;

    int aRow = warpM * 32 + ((lane >> 3) & 1) * 8 + (lane & 7);
    int aKc  = lane >> 4;
    int bRow = warpN * 64 + (lane >> 4) * 8 + (lane & 7);
    int bKc  = (lane >> 3) & 1;

    int lrow = tid >> 2;
    int lchk = tid & 3;
    const bf16* Ag = A  + (size_t)(bm + lrow) * K + lchk * 8;
    const bf16* Bg = Bw + (size_t)(bn + lrow) * K + lchk * 8;

    float4 acc[2][8];
#pragma unroll
    for (int mt = 0; mt < 2; mt++)
#pragma unroll
        for (int nt = 0; nt < 8; nt++) acc[mt][nt] = make_float4(0.f, 0.f, 0.f, 0.f);

    auto loadTile = [&](int stage, int kt) {
        uint32_t as = sbase + stage * TILEB;
        uint32_t bs = sbase + STAGES * TILEB + stage * TILEB;
#pragma unroll
        for (int p = 0; p < 2; p++) {
            int r = p * 64 + lrow;
            uint32_t off = swz(r, lchk);
            cp16s(as + off, Ag + (size_t)p * 64 * K + kt);
            cp16s(bs + off, Bg + (size_t)p * 64 * K + kt);
        }
        cp_commit();
    };

    auto compute = [&](int stage) {
        uint32_t aBase = sbase + stage * TILEB;
        uint32_t bBase = sbase + STAGES * TILEB + stage * TILEB;
#pragma unroll
        for (int ks = 0; ks < 2; ks++) {
            uint32_t a[2][4], b[8][2];
#pragma unroll
            for (int mt = 0; mt < 2; mt++) {
                int row = aRow + mt * 16;
                ldsm4(a[mt][0], a[mt][1], a[mt][2], a[mt][3],
                      aBase + swz(row, ks * 2 + aKc));
            }
#pragma unroll
            for (int np = 0; np < 4; np++) {
                int row = bRow + np * 16;
                ldsm4(b[2 * np][0], b[2 * np][1], b[2 * np + 1][0], b[2 * np + 1][1],
                      bBase + swz(row, ks * 2 + bKc));
            }
#pragma unroll
            for (int mt = 0; mt < 2; mt++)
#pragma unroll
                for (int nt = 0; nt < 8; nt++)
                    mma_bf16(acc[mt][nt], a[mt], b[nt]);
        }
    };

    int T = K >> 5;

    loadTile(0, 0);
    loadTile(1, BK);
    loadTile(2, 2 * BK);
    loadTile(3, 3 * BK);

    int s0 = 0;
    int sl = 4;
    for (int t0 = 0; t0 < T; t0 += 2) {
        cp_wait<2>();
        __syncthreads();

        compute(s0);
        int s1 = s0 + 1; if (s1 >= STAGES) s1 -= STAGES;
        compute(s1);

        if (t0 + 4 < T) loadTile(sl, (t0 + 4) * BK); else cp_commit();
        int sl2 = sl + 1; if (sl2 >= STAGES) sl2 -= STAGES;
        if (t0 + 5 < T) loadTile(sl2, (t0 + 5) * BK); else cp_commit();

        s0 += 2; if (s0 >= STAGES) s0 -= STAGES;
        sl += 2; if (sl >= STAGES) sl -= STAGES;
    }

    // epilogue
#pragma unroll
    for (int mt = 0; mt < 2; mt++) {
        int row = bm + warpM * 32 + mt * 16 + lg;
#pragma unroll
        for (int nt = 0; nt < 8; nt++) {
            int col = bn + warpN * 64 + nt * 8 + lt * 2;
            float b0 = bias[col], b1 = bias[col + 1];
            float4 v = acc[mt][nt];
            float o00 = v.x + b0, o01 = v.y + b1;
            float o10 = v.z + b0, o11 = v.w + b1;
            if (EP == 1) {
                o00 = 0.5f * o00 * (1.f + erff(o00 * 0.70710678f));
                o01 = 0.5f * o01 * (1.f + erff(o01 * 0.70710678f));
                o10 = 0.5f * o10 * (1.f + erff(o10 * 0.70710678f));
                o11 = 0.5f * o11 * (1.f + erff(o11 * 0.70710678f));
            } else if (EP == 2) {
                const float2 r0 = *reinterpret_cast<const float2*>(Res + (size_t)row * N + col);
                const float2 r1 = *reinterpret_cast<const float2*>(Res + (size_t)(row + 8) * N + col);
                o00 += r0.x; o01 += r0.y; o10 += r1.x; o11 += r1.y;
            }
            store2(C, (size_t)row * N + col,       o00, o01);
            store2(C, (size_t)(row + 8) * N + col, o10, o11);
        }
    }
}

// ---------------------------------------------------------------------------
// Window attention. One CTA per window, 8 warps = 8 heads.
// q PRE-SCALED (folded into weights). q/k/v staged via cp.async.
// QK^T via HMMA m16n8k16: rows/cols 9..15 of the fragment are garbage and
// discarded by predicate (addresses stay inside this CTA's smem).
// Softmax + P@V remain fp32 CUDA-core (no new quantization).
// ---------------------------------------------------------------------------
__global__ __launch_bounds__(256) void attn_kernel(
    const bf16* __restrict__ qkv, const float* __restrict__ bias_table,
    bf16* __restrict__ out)
{
    __shared__ __align__(16) bf16 sq[16][520];   // rows 9..15 scratch (legal reads)
    __shared__ __align__(16) bf16 sk[16][520];
    __shared__ __align__(16) bf16 sv[9][520];
    __shared__ float sp[8][81];
    int b   = blockIdx.x;
    int tid = threadIdx.x;
    size_t base = (size_t)b * 9 * 1536;
    uint32_t sqb = (uint32_t)__cvta_generic_to_shared(&sq[0][0]);
    uint32_t skb = (uint32_t)__cvta_generic_to_shared(&sk[0][0]);
    uint32_t svb = (uint32_t)__cvta_generic_to_shared(&sv[0][0]);

    // staging: 9 rows x 192 chunks of 16B (q|k|v per token row)
    for (int idx = tid; idx < 1728; idx += 256) {
        int n = idx / 192, c = idx - n * 192;      // c in [0,192)
        int mat = c >> 6;                           // 0=q 1=k 2=v
        uint32_t dst = (mat == 0 ? sqb : mat == 1 ? skb : svb)
                     + (uint32_t)(n * 1040 + (c & 63) * 16);
        cp16s(dst, qkv + base + (size_t)n * 1536 + c * 8);
    }
    cp_commit();
    cp_wait<0>();
    __syncthreads();

    int h = tid >> 5, lane = tid & 31;

    // ---- QK^T via HMMA ----
    // A-frag: rows 0..15 of sq, B-frag: rows 0..15 of sk (cols of S).
    int aRow = ((lane >> 3) & 1) * 8 + (lane & 7);   // 0..15
    int aK   = (lane >> 4) * 8;                       // 0 / 8
    int bRow = (lane >> 4) * 8 + (lane & 7);          // 0..15
    int bK   = ((lane >> 3) & 1) * 8;                 // 0 / 8

    float4 s0 = make_float4(0.f, 0.f, 0.f, 0.f);     // S cols 0..7
    float4 s1 = make_float4(0.f, 0.f, 0.f, 0.f);     // S cols 8..15
#pragma unroll
    for (int c = 0; c < 4; c++) {                     // k chunks of 16 dims
        uint32_t a[4], bb[4];
        uint32_t aAddr = sqb + (uint32_t)(aRow * 1040 + (h * 64 + c * 16 + aK) * 2);
        uint32_t bAddr = skb + (uint32_t)(bRow * 1040 + (h * 64 + c * 16 + bK) * 2);
        ldsm4(a[0], a[1], a[2], a[3], aAddr);
        ldsm4(bb[0], bb[1], bb[2], bb[3], bAddr);
        uint32_t b0[2] = { bb[0], bb[1] };            // cols 0..7
        uint32_t b1[2] = { bb[2], bb[3] };            // cols 8..15
        mma_bf16(s0, a, b0);
        mma_bf16(s1, a, b1);
    }

    // scatter valid scores (n<9, m<9) into sp[h][n*9+m]
    {
        int row = lane >> 2;          // 0..7
        int col = (lane & 3) * 2;     // 0,2,4,6
        sp[h][row * 9 + col]     = s0.x;
        sp[h][row * 9 + col + 1] = s0.y;
        if (row == 0) {               // fragment rows 8..15 -> only row 8 valid
            sp[h][8 * 9 + col]     = s0.z;
            sp[h][8 * 9 + col + 1] = s0.w;
        }
        if ((lane & 3) == 0) {        // tile1: only col 8 valid
            sp[h][row * 9 + 8] = s1.x;
            if (row == 0) sp[h][8 * 9 + 8] = s1.z;
        }
    }
    __syncwarp();

    // ---- softmax (bias added here; same add-order as before) ----
    if (lane < 9) {
        int n = lane;
        int ndiv = n / 3, nmod = n - 3 * ndiv;
        float sc[9];
#pragma unroll
        for (int m = 0; m < 9; m++) {
            int mdiv = m / 3, mmod = m - 3 * mdiv;
            int di = ndiv - mdiv + 2;
            int dj = nmod - mmod + 2;
            sc[m] = sp[h][n * 9 + m] + bias_table[(di * 5 + dj) * 8 + h];
        }
        float mx = -1e30f;
#pragma unroll
        for (int m = 0; m < 9; m++) mx = fmaxf(mx, sc[m]);
        float e[9], sum = 0.f;
#pragma unroll
        for (int m = 0; m < 9; m++) { e[m] = __expf(sc[m] - mx); sum += e[m]; }
        float inv = 1.f / sum;
#pragma unroll
        for (int m = 0; m < 9; m++) sp[h][n * 9 + m] = e[m] * inv;
    }
    __syncwarp();

    // ---- P@V from smem: lane owns dims 2*lane, 2*lane+1 ----
    float a0[9], a1[9];
#pragma unroll
    for (int n = 0; n < 9; n++) { a0[n] = 0.f; a1[n] = 0.f; }
#pragma unroll
    for (int m = 0; m < 9; m++) {
        float2 vf = __bfloat1622float2(
            *reinterpret_cast<const bf162*>(&sv[m][h * 64 + 2 * lane]));
#pragma unroll
        for (int n = 0; n < 9; n++) {
            float p = sp[h][n * 9 + m];
            a0[n] = fmaf(p, vf.x, a0[n]);
            a1[n] = fmaf(p, vf.y, a1[n]);
        }
    }
#pragma unroll
    for (int n = 0; n < 9; n++) {
        size_t o = ((size_t)b * 9 + n) * 512 + h * 64;
        *reinterpret_cast<bf162*>(out + o + 2 * lane) =
            __floats2bfloat162_rn(a0[n], a1[n]);
    }
}

// ---------------------------------------------------------------------------
// Depthwise 3x3 merge conv (fp32)
// ---------------------------------------------------------------------------
__global__ __launch_bounds__(256) void conv_kernel(
    const float* __restrict__ x, const float* __restrict__ w,
    const float* __restrict__ bc, float* __restrict__ out)
{
    int i = blockIdx.x * 256 + threadIdx.x;
    int c = i & 511;
    int b = i >> 9;
    float acc = bc[c];
    size_t base = (size_t)b * 9 * 512 + c;
#pragma unroll
    for (int n = 0; n < 9; n++)
        acc = fmaf(x[base + (size_t)n * 512], w[c * 9 + n], acc);
    out[i] = acc;
}

// ---------------------------------------------------------------------------
extern "C" void kernel_launch(void* const* d_in, const int* in_sizes, int n_in,
                              void* d_out, int out_size)
{
    const float* x          = (const float*)d_in[0];
    const float* gamma1     = (const float*)d_in[1];
    const float* beta1      = (const float*)d_in[2];
    const float* w_qkv      = (const float*)d_in[3];
    const float* b_qkv      = (const float*)d_in[4];
    const float* bias_table = (const float*)d_in[5];
    const float* w_proj     = (const float*)d_in[6];
    const float* b_proj     = (const float*)d_in[7];
    const float* gamma2     = (const float*)d_in[8];
    const float* beta2      = (const float*)d_in[9];
    const float* w_fc1      = (const float*)d_in[10];
    const float* b_fc1      = (const float*)d_in[11];
    const float* w_fc2      = (const float*)d_in[12];
    const float* b_fc2      = (const float*)d_in[13];
    const float* w_conv     = (const float*)d_in[14];
    const float* b_conv     = (const float*)d_in[15];
    float* out = (float*)d_out;

    bf16 *h, *qkv, *attn, *mlp, *wb;
    float *x1, *bqs;
    cudaGetSymbolAddress((void**)&h,    g_h);
    cudaGetSymbolAddress((void**)&qkv,  g_qkv);
    cudaGetSymbolAddress((void**)&attn, g_attn);
    cudaGetSymbolAddress((void**)&x1,   g_x1);
    cudaGetSymbolAddress((void**)&mlp,  g_mlp);
    cudaGetSymbolAddress((void**)&wb,   g_wb);
    cudaGetSymbolAddress((void**)&bqs,  g_bq);
    float* x2 = reinterpret_cast<float*>(qkv);   // reuse qkv buffer for x2 (fp32)

    cudaFuncSetAttribute(gemm_bf16_kernel<0, bf16>,
                         cudaFuncAttributeMaxDynamicSharedMemorySize, GSMEM);
    cudaFuncSetAttribute(gemm_bf16_kernel<1, bf16>,
                         cudaFuncAttributeMaxDynamicSharedMemorySize, GSMEM);
    cudaFuncSetAttribute(gemm_bf16_kernel<2, float>,
                         cudaFuncAttributeMaxDynamicSharedMemorySize, GSMEM);

    bf16* wq = wb;
    bf16* wp = wb + 786432;
    bf16* w1 = wb + 1048576;
    bf16* w2 = wb + 2097152;

    // all weight conversions + q-scale folding in one launch
    convw4_kernel<<<3072, 256>>>(w_qkv, w_proj, w_fc1, w_fc2, b_qkv, wb, bqs);

    const int MB = MROWS / 128;   // 576 row tiles

    // LN1: x -> h (bf16)
    ln_kernel<<<MROWS / 8, dim3(32, 8)>>>(x, gamma1, beta1, h);
    // QKV (q pre-scaled): h @ wq^T + bqs -> qkv (bf16)
    gemm_bf16_kernel<0, bf16><<<dim3(12, MB), 256, GSMEM>>>(h, wq, bqs, nullptr, qkv, 1536, 512);
    // window attention -> attn (bf16)
    attn_kernel<<<8192, 256>>>(qkv, bias_table, attn);
    // proj + shortcut: attn @ wp^T + b_proj + x -> x1 (fp32)
    gemm_bf16_kernel<2, float><<<dim3(4, MB), 256, GSMEM>>>(attn, wp, b_proj, x, x1, 512, 512);
    // LN2: x1 -> h (bf16)
    ln_kernel<<<MROWS / 8, dim3(32, 8)>>>(x1, gamma2, beta2, h);
    // FC1 + GELU: h @ w1^T + b_fc1 -> mlp (bf16)
    gemm_bf16_kernel<1, bf16><<<dim3(16, MB), 256, GSMEM>>>(h, w1, b_fc1, nullptr, mlp, 2048, 512);
    // FC2 + residual: mlp @ w2^T + b_fc2 + x1 -> x2 (fp32, reuses qkv buffer)
    gemm_bf16_kernel<2, float><<<dim3(4, MB), 256, GSMEM>>>(mlp, w2, b_fc2, x1, x2, 512, 2048);
    // merge conv -> out
    conv_kernel<<<(8192 * 512) / 256, 256>>>(x2, w_conv, b_conv, out);
}